// round 7
// baseline (speedup 1.0000x reference)
#include <cuda_runtime.h>
#include <math_constants.h>
#include <cuda_fp16.h>
#include <cstdint>

// Problem constants
#define BB 1024   // batch
#define CC 32     // classes
#define KK 16     // prototypes per class
#define DD 256    // embedding dim
#define TWO_D 512

// Scratch (static device arrays — no allocation allowed)
__device__ float g_proto_term[CC * KK * DD];          // 512 KB
__device__ float g_dotep[(size_t)BB * CC * KK];       // 2 MB: emb·proto
__device__ float g_G[CC * KK * KK];                   // 32 KB: Gram
__device__ float g_e2[BB];                            // |emb|^2
__device__ float g_inval[CC * KK];                    // 0 = valid, -inf = invalid

__device__ __forceinline__ uint32_t f2tf(float f) {
    uint32_t r;
    asm("cvt.rna.tf32.f32 %0, %1;" : "=r"(r) : "f"(f));
    return r;
}
__device__ __forceinline__ __half2 tanh_h2(__half2 x) {
    uint32_t xi = *reinterpret_cast<uint32_t*>(&x);
    uint32_t r;
    asm("tanh.approx.f16x2 %0, %1;" : "=r"(r) : "r"(xi));
    return *reinterpret_cast<__half2*>(&r);
}
__device__ __forceinline__ void cp16(void* smem, const void* g) {
    uint32_t sa = (uint32_t)__cvta_generic_to_shared(smem);
    asm volatile("cp.async.cg.shared.global [%0], [%1], 16;" :: "r"(sa), "l"(g));
}
#define CP_COMMIT() asm volatile("cp.async.commit_group;")
#define CP_WAIT(N)  asm volatile("cp.async.wait_group %0;" :: "n"(N))

__device__ __forceinline__ void mma_tf32(float c_[4], const uint32_t a[4], const uint32_t b[2]) {
    asm volatile(
        "mma.sync.aligned.m16n8k8.row.col.f32.tf32.tf32.f32 "
        "{%0,%1,%2,%3}, {%4,%5,%6,%7}, {%8,%9}, {%0,%1,%2,%3};"
        : "+f"(c_[0]), "+f"(c_[1]), "+f"(c_[2]), "+f"(c_[3])
        : "r"(a[0]), "r"(a[1]), "r"(a[2]), "r"(a[3]), "r"(b[0]), "r"(b[1]));
}

// ===========================================================================
// Kernel A (prologue, fused): blockIdx dispatch, 256 threads everywhere
//   [0,128)   : proto_term  (c = blk>>2, d-slice = (blk&3)*64), MLP-8 prefetch
//   [128,160) : Gram        (c = blk-128)
//   [160,192) : e2          (32 rows per block, warp-per-row x4)
//   192       : decode prototype_valid mask
//   [193,257) : dotep tf32 GEMM (64x128 tiles: bm0=(b>>2)*64, bn0=(b&3)*128)
// ===========================================================================
__global__ __launch_bounds__(256) void prologue_kernel(
    const float* __restrict__ emb,      // [B,D]
    const float* __restrict__ protos,   // [C,K,D]
    const float* __restrict__ W1,       // [C,2D,D]
    const float* __restrict__ b1,       // [C,D]
    const void*  __restrict__ valid)
{
    __shared__ __align__(16) float sh[8192];   // 32 KB, reused per role
    const int blk = blockIdx.x;
    const int tid = threadIdx.x;

    if (blk < 128) {
        // ----- proto_term[c][k][d0+dl] = b1 + sum_e protos[c][k][e]*W1[c][D+e][d0+dl]
        const int c  = blk >> 2;
        const int d0 = (blk & 3) * 64;
        const int dl = tid & 63;        // d within slice
        const int eg = tid >> 6;        // e-group 0..3 (64 e's each)

        float* p_s  = sh;               // [16][256]
        float* sred = sh + KK * DD;     // [4][16][64]

        const float* pg = protos + (size_t)c * KK * DD;
        #pragma unroll
        for (int i = 0; i < 16; ++i) p_s[tid + i * 256] = pg[tid + i * 256];
        __syncthreads();

        float acc[KK];
        #pragma unroll
        for (int k = 0; k < KK; ++k) acc[k] = 0.f;

        // W1 bottom rows D+eg*64 .. +63, column d0+dl; 8-deep prefetch (MLP=8)
        const float* Wb = W1 + ((size_t)c * TWO_D + DD + eg * 64) * DD + d0 + dl;
        for (int e0 = 0; e0 < 64; e0 += 8) {
            float w[8];
            #pragma unroll
            for (int u = 0; u < 8; ++u) w[u] = Wb[(size_t)(e0 + u) * DD];
            #pragma unroll
            for (int u = 0; u < 8; ++u) {
                const float* pe = p_s + eg * 64 + e0 + u;
                #pragma unroll
                for (int k = 0; k < KK; ++k)
                    acc[k] = fmaf(pe[k * DD], w[u], acc[k]);
            }
        }

        #pragma unroll
        for (int k = 0; k < KK; ++k)
            sred[(eg * KK + k) * 64 + dl] = acc[k];
        __syncthreads();

        #pragma unroll
        for (int r = 0; r < 4; ++r) {
            int idx = tid + r * 256;        // k*64 + dl
            int k = idx >> 6, d = idx & 63;
            float s = sred[(0 * KK + k) * 64 + d] + sred[(1 * KK + k) * 64 + d]
                    + sred[(2 * KK + k) * 64 + d] + sred[(3 * KK + k) * 64 + d];
            g_proto_term[((c * KK) + k) * DD + d0 + d] = s + b1[c * DD + d0 + d];
        }

    } else if (blk < 160) {
        // ----- Gram G[c][k][k2]
        const int c = blk - 128;
        float* p_s = sh;   // [16][257]
        for (int i = tid; i < KK * DD; i += 256) {
            int k = i / DD, d = i % DD;
            p_s[k * (DD + 1) + d] = protos[(size_t)c * KK * DD + i];
        }
        __syncthreads();
        const int k = tid >> 4, k2 = tid & 15;
        float s = 0.f;
        #pragma unroll 4
        for (int d = 0; d < DD; ++d)
            s = fmaf(p_s[k * (DD + 1) + d], p_s[k2 * (DD + 1) + d], s);
        g_G[c * 256 + tid] = s;

    } else if (blk < 192) {
        // ----- e2: warp-per-row, 4 rows per warp
        const int warp = tid >> 5, lane = tid & 31;
        const int base = (blk - 160) * 32 + warp * 4;
        #pragma unroll
        for (int t = 0; t < 4; ++t) {
            const int b = base + t;
            const float4* p = (const float4*)(emb + (size_t)b * DD);
            float4 v0 = p[lane], v1 = p[lane + 32];
            float s = v0.x*v0.x + v0.y*v0.y + v0.z*v0.z + v0.w*v0.w
                    + v1.x*v1.x + v1.y*v1.y + v1.z*v1.z + v1.w*v1.w;
            #pragma unroll
            for (int off = 16; off > 0; off >>= 1)
                s += __shfl_xor_sync(0xFFFFFFFFu, s, off);
            if (lane == 0) g_e2[b] = s;
        }

    } else if (blk == 192) {
        // ----- decode prototype_valid (dtype-sniffing)
        __shared__ int s_hasF, s_hasHi, s_mode;
        if (tid == 0) { s_hasF = 0; s_hasHi = 0; }
        __syncthreads();
        if (tid < 128) {   // first 512 bytes — in-bounds for uint8/int32/float32
            unsigned v = ((const unsigned*)valid)[tid];
            if (v == 0x3F800000u)                        atomicOr(&s_hasF, 1);
            else if (v != 0u && (v & 0xFFFFFF00u) != 0u) atomicOr(&s_hasHi, 1);
        }
        __syncthreads();
        if (tid == 0) s_mode = s_hasF ? 0 : (s_hasHi ? 2 : 1);
        __syncthreads();
        const int mode = s_mode;
        for (int i = tid; i < CC * KK; i += 256) {
            bool v;
            if (mode == 0)      v = ((const float*)valid)[i] != 0.0f;
            else if (mode == 1) v = ((const int*)valid)[i] != 0;
            else                v = ((const unsigned char*)valid)[i] != 0;
            g_inval[i] = v ? 0.0f : -CUDART_INF_F;
        }

    } else {
        // ----- dotep[b][ck] = emb[b,:]·proto[ck,:]  (tf32 mma)
        // 64x128 tile, BK=16 double-buffered, 8 warps (2m x 4n), warp 32x32.
        const int b    = blk - 193;              // 0..63
        const int bm0  = (b >> 2) * 64;          // over 1024 batch
        const int bn0  = (b & 3) * 128;          // over 512 protos

        // As [2][64][20] at sh[0], Ps [2][128][20] at sh[2560]
        #define DAS(s, m, k) sh[(s) * 1280 + (m) * 20 + (k)]
        #define DPS(s, n, k) sh[2560 + (s) * 2560 + (n) * 20 + (k)]

        const int warp = tid >> 5, lane = tid & 31;
        const int wm = (warp >> 2) * 32;
        const int wn = (warp & 3) * 32;
        const int g  = lane >> 2, tg = lane & 3;

        float acc[2][4][4];
        #pragma unroll
        for (int i = 0; i < 2; ++i)
            #pragma unroll
            for (int j = 0; j < 4; ++j)
                #pragma unroll
                for (int t = 0; t < 4; ++t) acc[i][j][t] = 0.f;

        #define DE_LOAD(s, kbase)                                                         \
            {                                                                              \
                { int m = tid >> 2, k4 = (tid & 3) << 2;                                   \
                  cp16(&DAS(s, m, k4), emb + (size_t)(bm0 + m) * DD + (kbase) + k4); }     \
                _Pragma("unroll")                                                          \
                for (int i_ = 0; i_ < 2; ++i_) {                                           \
                    int slot = tid + i_ * 256;                                             \
                    int n = slot >> 2, k4 = (slot & 3) << 2;                               \
                    cp16(&DPS(s, n, k4), protos + (size_t)(bn0 + n) * DD + (kbase) + k4);  \
                }                                                                          \
                CP_COMMIT();                                                               \
            }

        DE_LOAD(0, 0);
        int s = 0;
        const int NT = DD / 16;
        for (int kt = 0; kt < NT; ++kt) {
            if (kt + 1 < NT) { DE_LOAD(s ^ 1, (kt + 1) * 16); CP_WAIT(1); }
            else             { CP_WAIT(0); }
            __syncthreads();

            #pragma unroll
            for (int ks = 0; ks < 2; ++ks) {
                const int kb = ks * 8;
                uint32_t afr[2][4], bfr[4][2];
                #pragma unroll
                for (int i = 0; i < 2; ++i) {
                    int m0 = wm + i * 16;
                    afr[i][0] = f2tf(DAS(s, m0 + g,     kb + tg));
                    afr[i][1] = f2tf(DAS(s, m0 + g + 8, kb + tg));
                    afr[i][2] = f2tf(DAS(s, m0 + g,     kb + tg + 4));
                    afr[i][3] = f2tf(DAS(s, m0 + g + 8, kb + tg + 4));
                }
                #pragma unroll
                for (int j = 0; j < 4; ++j) {
                    int n0 = wn + j * 8;
                    bfr[j][0] = f2tf(DPS(s, n0 + g, kb + tg));
                    bfr[j][1] = f2tf(DPS(s, n0 + g, kb + tg + 4));
                }
                #pragma unroll
                for (int i = 0; i < 2; ++i)
                    #pragma unroll
                    for (int j = 0; j < 4; ++j)
                        mma_tf32(acc[i][j], afr[i], bfr[j]);
            }
            __syncthreads();
            s ^= 1;
        }

        #pragma unroll
        for (int i = 0; i < 2; ++i) {
            int r0 = bm0 + wm + i * 16 + g;
            #pragma unroll
            for (int j = 0; j < 4; ++j) {
                int col = bn0 + wn + j * 8 + 2 * tg;
                *(float2*)(g_dotep + (size_t)r0 * (CC * KK) + col)       = make_float2(acc[i][j][0], acc[i][j][1]);
                *(float2*)(g_dotep + (size_t)(r0 + 8) * (CC * KK) + col) = make_float2(acc[i][j][2], acc[i][j][3]);
            }
        }
        #undef DE_LOAD
        #undef DAS
        #undef DPS
    }
}

// ===========================================================================
// Kernel B (main, fused): per (64-batch-tile, class):
//   1. qW tile [64 x 256] = emb_tile @ W1top  (tf32 mma, acc in registers)
//   2. epilogue: scores[b][k] = sum_d w2[d]*tanh(qW+pt[k][d])
//      tanh via tanh.approx.f16x2 (2 per MUFU op) + HFMA2 short accumulation
//   3. softmax over K, dist via Gram trick, write out
// grid (16, 32), 256 threads (8 warps, n-sliced: warp tile 64x32), 2 CTAs/SM.
// ===========================================================================
__global__ __launch_bounds__(256, 2) void fused_main(
    const float* __restrict__ emb, const float* __restrict__ W1,
    const float* __restrict__ w2, const float* __restrict__ b2,
    const float* __restrict__ temperature, float* __restrict__ out)
{
    extern __shared__ float sh[];
    // phase-1 layout: As [2][64][20] = 2560 fl ; Bs [2][16][260] = 8320 fl
    float* Asb = sh;
    float* Bsb = sh + 2560;
    // phase-2 layout (aliases phase-1 region)
    float* sh_pt    = sh;                  // [16][256] = 4096
    float* sh_score = sh + 4096;           // [64][17]  = 1088
    float* sh_w2    = sh + 4096 + 1088;    // 256
    float* sh_G     = sh_w2 + 256;         // [16][17] = 272
    float* sh_inval = sh_G + 272;          // 16

    const int c  = blockIdx.y;
    const int b0 = blockIdx.x * 64;
    const float* A  = emb;
    const float* Bm = W1 + (size_t)c * TWO_D * DD;   // top half [256 k][256 n]

    const int tid  = threadIdx.x;
    const int warp = tid >> 5, lane = tid & 31;
    const int wn = warp * 32;            // warp n-slice (all 64 rows)
    const int g  = lane >> 2, tg = lane & 3;

    float acc[4][4][4];                  // [m16 tile][n8 tile][frag]
    #pragma unroll
    for (int i = 0; i < 4; ++i)
        #pragma unroll
        for (int j = 0; j < 4; ++j)
            #pragma unroll
            for (int t = 0; t < 4; ++t) acc[i][j][t] = 0.f;

    #define AS(s, m, k) Asb[(s) * 1280 + (m) * 20 + (k)]
    #define BS(s, k, n) Bsb[(s) * 4160 + (k) * 260 + (n)]
    #define FM_LOAD(s, kbase)                                                    \
        {                                                                         \
            { int m = tid >> 2, k4 = (tid & 3) << 2;                              \
              cp16(&AS(s, m, k4), A + (size_t)(b0 + m) * DD + (kbase) + k4); }    \
            _Pragma("unroll")                                                     \
            for (int i_ = 0; i_ < 4; ++i_) {                                      \
                int slot = tid + i_ * 256;                                        \
                int k = slot >> 6, n4 = (slot & 63) << 2;                         \
                cp16(&BS(s, k, n4), Bm + (size_t)((kbase) + k) * DD + n4);        \
            }                                                                     \
            CP_COMMIT();                                                          \
        }

    // ---------------- Phase 1: tf32 GEMM ----------------
    FM_LOAD(0, 0);
    int s = 0;
    const int NT = DD / 16;   // 16
    for (int kt = 0; kt < NT; ++kt) {
        if (kt + 1 < NT) { FM_LOAD(s ^ 1, (kt + 1) * 16); CP_WAIT(1); }
        else             { CP_WAIT(0); }
        __syncthreads();

        #pragma unroll
        for (int ks = 0; ks < 2; ++ks) {
            const int kb = ks * 8;
            uint32_t afr[4][4], bfr[4][2];
            #pragma unroll
            for (int i = 0; i < 4; ++i) {
                int m0 = i * 16;
                afr[i][0] = f2tf(AS(s, m0 + g,     kb + tg));
                afr[i][1] = f2tf(AS(s, m0 + g + 8, kb + tg));
                afr[i][2] = f2tf(AS(s, m0 + g,     kb + tg + 4));
                afr[i][3] = f2tf(AS(s, m0 + g + 8, kb + tg + 4));
            }
            #pragma unroll
            for (int j = 0; j < 4; ++j) {
                int n0 = wn + j * 8;
                bfr[j][0] = f2tf(BS(s, kb + tg,     n0 + g));
                bfr[j][1] = f2tf(BS(s, kb + tg + 4, n0 + g));
            }
            #pragma unroll
            for (int i = 0; i < 4; ++i)
                #pragma unroll
                for (int j = 0; j < 4; ++j)
                    mma_tf32(acc[i][j], afr[i], bfr[j]);
        }
        __syncthreads();
        s ^= 1;
    }
    // last iteration ended with __syncthreads() — safe to repurpose smem.

    // ---------------- Phase 2 tables ----------------
    {
        const float* ptg = g_proto_term + (size_t)c * KK * DD;
        #pragma unroll
        for (int i = 0; i < 16; ++i) sh_pt[tid + i * 256] = ptg[tid + i * 256];
        for (int i = tid; i < 64 * 17; i += 256) sh_score[i] = 0.f;
        if (tid < DD) sh_w2[tid] = w2[c * DD + tid];
        if (tid < KK * KK) sh_G[(tid >> 4) * 17 + (tid & 15)] = g_G[c * 256 + tid];
        if (tid < KK) sh_inval[tid] = g_inval[c * KK + tid];
    }
    __syncthreads();

    // per-thread w2 pairs for held columns, packed half2
    __half2 w2h[4];
    #pragma unroll
    for (int j = 0; j < 4; ++j) {
        float2 w = *(float2*)&sh_w2[wn + j * 8 + 2 * tg];
        w2h[j] = __floats2half2_rn(w.x, w.y);
    }

    // ---------------- Phase 3: tanh scores (f16x2 MUFU path) ----------------
    #pragma unroll 1
    for (int k = 0; k < KK; ++k) {
        float2 ptv[4];
        #pragma unroll
        for (int j = 0; j < 4; ++j)
            ptv[j] = *(float2*)&sh_pt[k * DD + wn + j * 8 + 2 * tg];

        float part[8];
        #pragma unroll
        for (int i = 0; i < 4; ++i) {
            __half2 h0 = __floats2half2_rn(0.f, 0.f);
            __half2 h1 = h0;
            #pragma unroll
            for (int j = 0; j < 4; ++j) {
                __half2 x0 = __floats2half2_rn(acc[i][j][0] + ptv[j].x,
                                               acc[i][j][1] + ptv[j].y);
                __half2 x1 = __floats2half2_rn(acc[i][j][2] + ptv[j].x,
                                               acc[i][j][3] + ptv[j].y);
                h0 = __hfma2(tanh_h2(x0), w2h[j], h0);
                h1 = __hfma2(tanh_h2(x1), w2h[j], h1);
            }
            float2 f0 = __half22float2(h0);
            float2 f1 = __half22float2(h1);
            part[2 * i]     = f0.x + f0.y;
            part[2 * i + 1] = f1.x + f1.y;
        }
        // reduce over tg (lane bits 0..1)
        #pragma unroll
        for (int r = 0; r < 8; ++r) {
            part[r] += __shfl_xor_sync(0xFFFFFFFFu, part[r], 1);
            part[r] += __shfl_xor_sync(0xFFFFFFFFu, part[r], 2);
        }
        if (tg == 0) {
            #pragma unroll
            for (int r = 0; r < 8; ++r) {
                int row = (r >> 1) * 16 + g + ((r & 1) << 3);
                atomicAdd(&sh_score[row * 17 + k], part[r]);
            }
        }
    }
    __syncthreads();

    // ---------------- Phase 4: softmax + Gram distance ----------------
    if (tid < 64) {
        const int b = b0 + tid;
        const float b2v  = b2[c];
        const float temp = temperature[0];

        float s16[KK];
        #pragma unroll
        for (int k = 0; k < KK; ++k)
            s16[k] = sh_score[tid * 17 + k] + b2v + sh_inval[k];

        float m = s16[0];
        #pragma unroll
        for (int k = 1; k < KK; ++k) m = fmaxf(m, s16[k]);
        float sum = 0.f;
        #pragma unroll
        for (int k = 0; k < KK; ++k) {
            float e = __expf(s16[k] - m);
            s16[k] = e;
            sum += e;
        }
        float inv = 1.f / sum;
        #pragma unroll
        for (int k = 0; k < KK; ++k) s16[k] *= inv;

        // dist^2 = e2 - 2*attn·dotep + attn^T G attn
        float depv[KK];
        const float4* dep = (const float4*)(g_dotep + (size_t)b * (CC * KK) + c * KK);
        #pragma unroll
        for (int q = 0; q < 4; ++q) {
            float4 v = dep[q];
            depv[4 * q + 0] = v.x; depv[4 * q + 1] = v.y;
            depv[4 * q + 2] = v.z; depv[4 * q + 3] = v.w;
        }
        float dist2 = g_e2[b];
        #pragma unroll
        for (int k = 0; k < KK; ++k)
            dist2 = fmaf(-2.0f * s16[k], depv[k], dist2);
        #pragma unroll
        for (int k = 0; k < KK; ++k) {
            float t = 0.f;
            #pragma unroll
            for (int k2 = 0; k2 < KK; ++k2)
                t = fmaf(sh_G[k * 17 + k2], s16[k2], t);
            dist2 = fmaf(s16[k], t, dist2);
        }
        out[(size_t)b * CC + c] = -sqrtf(fmaxf(dist2, 0.f)) * temp;
    }
    #undef AS
    #undef BS
    #undef FM_LOAD
}

// ---------------------------------------------------------------------------
extern "C" void kernel_launch(void* const* d_in, const int* in_sizes, int n_in,
                              void* d_out, int out_size)
{
    const float* emb    = (const float*)d_in[0];   // [B,D]
    const float* protos = (const float*)d_in[1];   // [C,K,D]
    const float* W1     = (const float*)d_in[2];   // [C,2D,D]
    const float* b1     = (const float*)d_in[3];   // [C,D]
    const float* w2     = (const float*)d_in[4];   // [C,D]
    const float* b2     = (const float*)d_in[5];   // [C]
    const float* temp   = (const float*)d_in[6];   // [1]
    const void*  valid  = (const void*)d_in[7];    // [C,K] bool (storage dtype unknown)
    float* out = (float*)d_out;                    // [B,C]

    const int dyn = (2 * 64 * 20 + 2 * 16 * 260) * 4;   // 43520 bytes
    cudaFuncSetAttribute(fused_main, cudaFuncAttributeMaxDynamicSharedMemorySize, dyn);

    prologue_kernel<<<257, 256>>>(emb, protos, W1, b1, valid);
    fused_main<<<dim3(16, CC), 256, dyn>>>(emb, W1, w2, b2, temp, out);
}

// round 8
// speedup vs baseline: 1.1789x; 1.1789x over previous
#include <cuda_runtime.h>
#include <math_constants.h>
#include <cuda_fp16.h>
#include <cstdint>

// Problem constants
#define BB 1024   // batch
#define CC 32     // classes
#define KK 16     // prototypes per class
#define DD 256    // embedding dim
#define TWO_D 512

// Scratch (static device arrays — no allocation allowed)
__device__ float g_proto_term[CC * KK * DD];          // 512 KB
__device__ float g_dotep[(size_t)BB * CC * KK];       // 2 MB: emb·proto
__device__ float g_G[CC * KK * KK];                   // 32 KB: Gram
__device__ float g_e2[BB];                            // |emb|^2
__device__ float g_inval[CC * KK];                    // 0 = valid, -inf = invalid

__device__ __forceinline__ uint32_t f2tf(float f) {
    uint32_t r;
    asm("cvt.rna.tf32.f32 %0, %1;" : "=r"(r) : "f"(f));
    return r;
}
__device__ __forceinline__ __half2 tanh_h2(__half2 x) {
    uint32_t xi = *reinterpret_cast<uint32_t*>(&x);
    uint32_t r;
    asm("tanh.approx.f16x2 %0, %1;" : "=r"(r) : "r"(xi));
    return *reinterpret_cast<__half2*>(&r);
}
__device__ __forceinline__ void cp16(void* smem, const void* g) {
    uint32_t sa = (uint32_t)__cvta_generic_to_shared(smem);
    asm volatile("cp.async.cg.shared.global [%0], [%1], 16;" :: "r"(sa), "l"(g));
}
#define CP_COMMIT() asm volatile("cp.async.commit_group;")
#define CP_WAIT(N)  asm volatile("cp.async.wait_group %0;" :: "n"(N))

__device__ __forceinline__ void mma_tf32(float c_[4], const uint32_t a[4], const uint32_t b[2]) {
    asm volatile(
        "mma.sync.aligned.m16n8k8.row.col.f32.tf32.tf32.f32 "
        "{%0,%1,%2,%3}, {%4,%5,%6,%7}, {%8,%9}, {%0,%1,%2,%3};"
        : "+f"(c_[0]), "+f"(c_[1]), "+f"(c_[2]), "+f"(c_[3])
        : "r"(a[0]), "r"(a[1]), "r"(a[2]), "r"(a[3]), "r"(b[0]), "r"(b[1]));
}

// ===========================================================================
// Kernel A (prologue, fused): blockIdx dispatch, 256 threads everywhere
//   [0,128)   : proto_term  (c = blk>>2, d-slice = (blk&3)*64), MLP-8 prefetch
//   [128,160) : Gram        (c = blk-128)
//   [160,192) : e2          (32 rows per block, warp-per-row x4)
//   192       : decode prototype_valid mask
//   [193,257) : dotep tf32 GEMM (64x128 tiles: bm0=(b>>2)*64, bn0=(b&3)*128)
// ===========================================================================
__global__ __launch_bounds__(256) void prologue_kernel(
    const float* __restrict__ emb,      // [B,D]
    const float* __restrict__ protos,   // [C,K,D]
    const float* __restrict__ W1,       // [C,2D,D]
    const float* __restrict__ b1,       // [C,D]
    const void*  __restrict__ valid)
{
    __shared__ __align__(16) float sh[8192];   // 32 KB, reused per role
    const int blk = blockIdx.x;
    const int tid = threadIdx.x;

    if (blk < 128) {
        // ----- proto_term[c][k][d0+dl] = b1 + sum_e protos[c][k][e]*W1[c][D+e][d0+dl]
        const int c  = blk >> 2;
        const int d0 = (blk & 3) * 64;
        const int dl = tid & 63;        // d within slice
        const int eg = tid >> 6;        // e-group 0..3 (64 e's each)

        float* p_s  = sh;               // [16][256]
        float* sred = sh + KK * DD;     // [4][16][64]

        const float* pg = protos + (size_t)c * KK * DD;
        #pragma unroll
        for (int i = 0; i < 16; ++i) p_s[tid + i * 256] = pg[tid + i * 256];
        __syncthreads();

        float acc[KK];
        #pragma unroll
        for (int k = 0; k < KK; ++k) acc[k] = 0.f;

        // W1 bottom rows D+eg*64 .. +63, column d0+dl; 8-deep prefetch (MLP=8)
        const float* Wb = W1 + ((size_t)c * TWO_D + DD + eg * 64) * DD + d0 + dl;
        for (int e0 = 0; e0 < 64; e0 += 8) {
            float w[8];
            #pragma unroll
            for (int u = 0; u < 8; ++u) w[u] = Wb[(size_t)(e0 + u) * DD];
            #pragma unroll
            for (int u = 0; u < 8; ++u) {
                const float* pe = p_s + eg * 64 + e0 + u;
                #pragma unroll
                for (int k = 0; k < KK; ++k)
                    acc[k] = fmaf(pe[k * DD], w[u], acc[k]);
            }
        }

        #pragma unroll
        for (int k = 0; k < KK; ++k)
            sred[(eg * KK + k) * 64 + dl] = acc[k];
        __syncthreads();

        #pragma unroll
        for (int r = 0; r < 4; ++r) {
            int idx = tid + r * 256;        // k*64 + dl
            int k = idx >> 6, d = idx & 63;
            float s = sred[(0 * KK + k) * 64 + d] + sred[(1 * KK + k) * 64 + d]
                    + sred[(2 * KK + k) * 64 + d] + sred[(3 * KK + k) * 64 + d];
            g_proto_term[((c * KK) + k) * DD + d0 + d] = s + b1[c * DD + d0 + d];
        }

    } else if (blk < 160) {
        // ----- Gram G[c][k][k2]
        const int c = blk - 128;
        float* p_s = sh;   // [16][257]
        for (int i = tid; i < KK * DD; i += 256) {
            int k = i / DD, d = i % DD;
            p_s[k * (DD + 1) + d] = protos[(size_t)c * KK * DD + i];
        }
        __syncthreads();
        const int k = tid >> 4, k2 = tid & 15;
        float s = 0.f;
        #pragma unroll 4
        for (int d = 0; d < DD; ++d)
            s = fmaf(p_s[k * (DD + 1) + d], p_s[k2 * (DD + 1) + d], s);
        g_G[c * 256 + tid] = s;

    } else if (blk < 192) {
        // ----- e2: warp-per-row, 4 rows per warp
        const int warp = tid >> 5, lane = tid & 31;
        const int base = (blk - 160) * 32 + warp * 4;
        #pragma unroll
        for (int t = 0; t < 4; ++t) {
            const int b = base + t;
            const float4* p = (const float4*)(emb + (size_t)b * DD);
            float4 v0 = p[lane], v1 = p[lane + 32];
            float s = v0.x*v0.x + v0.y*v0.y + v0.z*v0.z + v0.w*v0.w
                    + v1.x*v1.x + v1.y*v1.y + v1.z*v1.z + v1.w*v1.w;
            #pragma unroll
            for (int off = 16; off > 0; off >>= 1)
                s += __shfl_xor_sync(0xFFFFFFFFu, s, off);
            if (lane == 0) g_e2[b] = s;
        }

    } else if (blk == 192) {
        // ----- decode prototype_valid (dtype-sniffing)
        __shared__ int s_hasF, s_hasHi, s_mode;
        if (tid == 0) { s_hasF = 0; s_hasHi = 0; }
        __syncthreads();
        if (tid < 128) {   // first 512 bytes — in-bounds for uint8/int32/float32
            unsigned v = ((const unsigned*)valid)[tid];
            if (v == 0x3F800000u)                        atomicOr(&s_hasF, 1);
            else if (v != 0u && (v & 0xFFFFFF00u) != 0u) atomicOr(&s_hasHi, 1);
        }
        __syncthreads();
        if (tid == 0) s_mode = s_hasF ? 0 : (s_hasHi ? 2 : 1);
        __syncthreads();
        const int mode = s_mode;
        for (int i = tid; i < CC * KK; i += 256) {
            bool v;
            if (mode == 0)      v = ((const float*)valid)[i] != 0.0f;
            else if (mode == 1) v = ((const int*)valid)[i] != 0;
            else                v = ((const unsigned char*)valid)[i] != 0;
            g_inval[i] = v ? 0.0f : -CUDART_INF_F;
        }

    } else {
        // ----- dotep[b][ck] = emb[b,:]·proto[ck,:]  (tf32 mma)
        // 64x128 tile, BK=16 double-buffered, 8 warps (2m x 4n), warp 32x32.
        const int b    = blk - 193;              // 0..63
        const int bm0  = (b >> 2) * 64;          // over 1024 batch
        const int bn0  = (b & 3) * 128;          // over 512 protos

        // As [2][64][20] at sh[0], Ps [2][128][20] at sh[2560]
        #define DAS(s, m, k) sh[(s) * 1280 + (m) * 20 + (k)]
        #define DPS(s, n, k) sh[2560 + (s) * 2560 + (n) * 20 + (k)]

        const int warp = tid >> 5, lane = tid & 31;
        const int wm = (warp >> 2) * 32;
        const int wn = (warp & 3) * 32;
        const int g  = lane >> 2, tg = lane & 3;

        float acc[2][4][4];
        #pragma unroll
        for (int i = 0; i < 2; ++i)
            #pragma unroll
            for (int j = 0; j < 4; ++j)
                #pragma unroll
                for (int t = 0; t < 4; ++t) acc[i][j][t] = 0.f;

        #define DE_LOAD(s, kbase)                                                         \
            {                                                                              \
                { int m = tid >> 2, k4 = (tid & 3) << 2;                                   \
                  cp16(&DAS(s, m, k4), emb + (size_t)(bm0 + m) * DD + (kbase) + k4); }     \
                _Pragma("unroll")                                                          \
                for (int i_ = 0; i_ < 2; ++i_) {                                           \
                    int slot = tid + i_ * 256;                                             \
                    int n = slot >> 2, k4 = (slot & 3) << 2;                               \
                    cp16(&DPS(s, n, k4), protos + (size_t)(bn0 + n) * DD + (kbase) + k4);  \
                }                                                                          \
                CP_COMMIT();                                                               \
            }

        DE_LOAD(0, 0);
        int s = 0;
        const int NT = DD / 16;
        for (int kt = 0; kt < NT; ++kt) {
            if (kt + 1 < NT) { DE_LOAD(s ^ 1, (kt + 1) * 16); CP_WAIT(1); }
            else             { CP_WAIT(0); }
            __syncthreads();

            #pragma unroll
            for (int ks = 0; ks < 2; ++ks) {
                const int kb = ks * 8;
                uint32_t afr[2][4], bfr[4][2];
                #pragma unroll
                for (int i = 0; i < 2; ++i) {
                    int m0 = wm + i * 16;
                    afr[i][0] = f2tf(DAS(s, m0 + g,     kb + tg));
                    afr[i][1] = f2tf(DAS(s, m0 + g + 8, kb + tg));
                    afr[i][2] = f2tf(DAS(s, m0 + g,     kb + tg + 4));
                    afr[i][3] = f2tf(DAS(s, m0 + g + 8, kb + tg + 4));
                }
                #pragma unroll
                for (int j = 0; j < 4; ++j) {
                    int n0 = wn + j * 8;
                    bfr[j][0] = f2tf(DPS(s, n0 + g, kb + tg));
                    bfr[j][1] = f2tf(DPS(s, n0 + g, kb + tg + 4));
                }
                #pragma unroll
                for (int i = 0; i < 2; ++i)
                    #pragma unroll
                    for (int j = 0; j < 4; ++j)
                        mma_tf32(acc[i][j], afr[i], bfr[j]);
            }
            __syncthreads();
            s ^= 1;
        }

        #pragma unroll
        for (int i = 0; i < 2; ++i) {
            int r0 = bm0 + wm + i * 16 + g;
            #pragma unroll
            for (int j = 0; j < 4; ++j) {
                int col = bn0 + wn + j * 8 + 2 * tg;
                *(float2*)(g_dotep + (size_t)r0 * (CC * KK) + col)       = make_float2(acc[i][j][0], acc[i][j][1]);
                *(float2*)(g_dotep + (size_t)(r0 + 8) * (CC * KK) + col) = make_float2(acc[i][j][2], acc[i][j][3]);
            }
        }
        #undef DE_LOAD
        #undef DAS
        #undef DPS
    }
}

// ===========================================================================
// Kernel B (main, fused): per (64-batch-tile, class):
//   1. qW tile [64 x 256] = emb_tile @ W1top  (tf32 mma, acc in registers)
//   2. epilogue: half2 end-to-end — acc packed to half2 once, pt in smem as
//      half2, inner loop = HADD2 + tanh.approx.f16x2 + HFMA2 (1.5 instr/elem),
//      per-warp score slabs (plain STS, no atomics)
//   3. softmax over K, dist via Gram trick, write out
// grid (16, 32), 256 threads (8 warps, n-sliced: warp tile 64x32), 2 CTAs/SM.
// ===========================================================================
__global__ __launch_bounds__(256, 2) void fused_main(
    const float* __restrict__ emb, const float* __restrict__ W1,
    const float* __restrict__ w2, const float* __restrict__ b2,
    const float* __restrict__ temperature, float* __restrict__ out)
{
    extern __shared__ float sh[];
    // phase-1 layout: As [2][64][20] = 2560 fl ; Bs [2][16][260] = 8320 fl
    float* Asb = sh;
    float* Bsb = sh + 2560;
    // phase-2 layout (aliases phase-1 region)
    uint32_t* sh_pt_h2 = (uint32_t*)sh;        // [16][128] half2 = 2048 words
    float* sh_scorew = sh + 2048;              // [8 warps][64 rows][20] = 10240
    float* sh_w2    = sh + 2048 + 10240;       // 256
    float* sh_G     = sh_w2 + 256;             // [16][17] = 272
    float* sh_inval = sh_G + 272;              // 16

    const int c  = blockIdx.y;
    const int b0 = blockIdx.x * 64;
    const float* A  = emb;
    const float* Bm = W1 + (size_t)c * TWO_D * DD;   // top half [256 k][256 n]

    const int tid  = threadIdx.x;
    const int warp = tid >> 5, lane = tid & 31;
    const int wn = warp * 32;            // warp n-slice (all 64 rows)
    const int g  = lane >> 2, tg = lane & 3;

    float acc[4][4][4];                  // [m16 tile][n8 tile][frag]
    #pragma unroll
    for (int i = 0; i < 4; ++i)
        #pragma unroll
        for (int j = 0; j < 4; ++j)
            #pragma unroll
            for (int t = 0; t < 4; ++t) acc[i][j][t] = 0.f;

    #define AS(s, m, k) Asb[(s) * 1280 + (m) * 20 + (k)]
    #define BS(s, k, n) Bsb[(s) * 4160 + (k) * 260 + (n)]
    #define FM_LOAD(s, kbase)                                                    \
        {                                                                         \
            { int m = tid >> 2, k4 = (tid & 3) << 2;                              \
              cp16(&AS(s, m, k4), A + (size_t)(b0 + m) * DD + (kbase) + k4); }    \
            _Pragma("unroll")                                                     \
            for (int i_ = 0; i_ < 4; ++i_) {                                      \
                int slot = tid + i_ * 256;                                        \
                int k = slot >> 6, n4 = (slot & 63) << 2;                         \
                cp16(&BS(s, k, n4), Bm + (size_t)((kbase) + k) * DD + n4);        \
            }                                                                     \
            CP_COMMIT();                                                          \
        }

    // ---------------- Phase 1: tf32 GEMM ----------------
    FM_LOAD(0, 0);
    int s = 0;
    const int NT = DD / 16;   // 16
    for (int kt = 0; kt < NT; ++kt) {
        if (kt + 1 < NT) { FM_LOAD(s ^ 1, (kt + 1) * 16); CP_WAIT(1); }
        else             { CP_WAIT(0); }
        __syncthreads();

        #pragma unroll
        for (int ks = 0; ks < 2; ++ks) {
            const int kb = ks * 8;
            uint32_t afr[4][4], bfr[4][2];
            #pragma unroll
            for (int i = 0; i < 4; ++i) {
                int m0 = i * 16;
                afr[i][0] = f2tf(AS(s, m0 + g,     kb + tg));
                afr[i][1] = f2tf(AS(s, m0 + g + 8, kb + tg));
                afr[i][2] = f2tf(AS(s, m0 + g,     kb + tg + 4));
                afr[i][3] = f2tf(AS(s, m0 + g + 8, kb + tg + 4));
            }
            #pragma unroll
            for (int j = 0; j < 4; ++j) {
                int n0 = wn + j * 8;
                bfr[j][0] = f2tf(BS(s, kb + tg,     n0 + g));
                bfr[j][1] = f2tf(BS(s, kb + tg + 4, n0 + g));
            }
            #pragma unroll
            for (int i = 0; i < 4; ++i)
                #pragma unroll
                for (int j = 0; j < 4; ++j)
                    mma_tf32(acc[i][j], afr[i], bfr[j]);
        }
        __syncthreads();
        s ^= 1;
    }
    // last iteration ended with __syncthreads() — safe to repurpose smem.

    // ---------------- Phase 2 tables ----------------
    {
        // pt as half2: [k][128 d-pairs]
        const float2* ptg2 = (const float2*)(g_proto_term + (size_t)c * KK * DD);
        #pragma unroll
        for (int i = 0; i < 8; ++i) {
            int idx = tid + i * 256;            // 0..2047
            float2 v = ptg2[idx];
            __half2 h = __floats2half2_rn(v.x, v.y);
            sh_pt_h2[idx] = *(uint32_t*)&h;
        }
        if (tid < DD) sh_w2[tid] = w2[c * DD + tid];
        if (tid < KK * KK) sh_G[(tid >> 4) * 17 + (tid & 15)] = g_G[c * 256 + tid];
        if (tid < KK) sh_inval[tid] = g_inval[c * KK + tid];
    }
    __syncthreads();

    // pack acc fragments to half2 once (row g in [0], row g+8 in [1])
    __half2 acch[4][4][2];
    #pragma unroll
    for (int i = 0; i < 4; ++i)
        #pragma unroll
        for (int j = 0; j < 4; ++j) {
            acch[i][j][0] = __floats2half2_rn(acc[i][j][0], acc[i][j][1]);
            acch[i][j][1] = __floats2half2_rn(acc[i][j][2], acc[i][j][3]);
        }

    // per-thread w2 pairs for held columns, packed half2
    __half2 w2h[4];
    #pragma unroll
    for (int j = 0; j < 4; ++j) {
        float2 w = *(float2*)&sh_w2[wn + j * 8 + 2 * tg];
        w2h[j] = __floats2half2_rn(w.x, w.y);
    }

    float* my_slab = sh_scorew + warp * 1280;   // [64][20]
    const int ptbase = (wn >> 1) + tg;          // d-pair index base

    // ---------------- Phase 3: tanh scores (half2 end-to-end) ----------------
    #pragma unroll 1
    for (int k = 0; k < KK; ++k) {
        __half2 pth[4];
        #pragma unroll
        for (int j = 0; j < 4; ++j) {
            uint32_t w = sh_pt_h2[k * 128 + ptbase + j * 4];
            pth[j] = *reinterpret_cast<__half2*>(&w);
        }

        float part[8];
        #pragma unroll
        for (int i = 0; i < 4; ++i) {
            __half2 a0 = __floats2half2_rn(0.f, 0.f);
            __half2 a1 = a0;
            #pragma unroll
            for (int j = 0; j < 4; ++j) {
                a0 = __hfma2(tanh_h2(__hadd2(acch[i][j][0], pth[j])), w2h[j], a0);
                a1 = __hfma2(tanh_h2(__hadd2(acch[i][j][1], pth[j])), w2h[j], a1);
            }
            float2 f0 = __half22float2(a0);
            float2 f1 = __half22float2(a1);
            part[2 * i]     = f0.x + f0.y;
            part[2 * i + 1] = f1.x + f1.y;
        }
        // reduce over tg (lane bits 0..1)
        #pragma unroll
        for (int r = 0; r < 8; ++r) {
            part[r] += __shfl_xor_sync(0xFFFFFFFFu, part[r], 1);
            part[r] += __shfl_xor_sync(0xFFFFFFFFu, part[r], 2);
        }
        if (tg == 0) {
            #pragma unroll
            for (int r = 0; r < 8; ++r) {
                int row = (r >> 1) * 16 + g + ((r & 1) << 3);
                my_slab[row * 20 + k] = part[r];   // plain STS, no RMW
            }
        }
    }
    __syncthreads();

    // ---------------- Phase 4: gather slabs + softmax + Gram distance -------
    if (tid < 64) {
        const int b = b0 + tid;
        const float b2v  = b2[c];
        const float temp = temperature[0];

        float s16[KK];
        #pragma unroll
        for (int k = 0; k < KK; ++k) s16[k] = b2v + sh_inval[k];
        #pragma unroll
        for (int w = 0; w < 8; ++w) {
            const float* p = sh_scorew + w * 1280 + tid * 20;
            float4 v0 = *(const float4*)(p + 0);
            float4 v1 = *(const float4*)(p + 4);
            float4 v2 = *(const float4*)(p + 8);
            float4 v3 = *(const float4*)(p + 12);
            s16[0] += v0.x;  s16[1] += v0.y;  s16[2] += v0.z;  s16[3] += v0.w;
            s16[4] += v1.x;  s16[5] += v1.y;  s16[6] += v1.z;  s16[7] += v1.w;
            s16[8] += v2.x;  s16[9] += v2.y;  s16[10] += v2.z; s16[11] += v2.w;
            s16[12] += v3.x; s16[13] += v3.y; s16[14] += v3.z; s16[15] += v3.w;
        }

        float m = s16[0];
        #pragma unroll
        for (int k = 1; k < KK; ++k) m = fmaxf(m, s16[k]);
        float sum = 0.f;
        #pragma unroll
        for (int k = 0; k < KK; ++k) {
            float e = __expf(s16[k] - m);
            s16[k] = e;
            sum += e;
        }
        float inv = 1.f / sum;
        #pragma unroll
        for (int k = 0; k < KK; ++k) s16[k] *= inv;

        // dist^2 = e2 - 2*attn·dotep + attn^T G attn
        float depv[KK];
        const float4* dep = (const float4*)(g_dotep + (size_t)b * (CC * KK) + c * KK);
        #pragma unroll
        for (int q = 0; q < 4; ++q) {
            float4 v = dep[q];
            depv[4 * q + 0] = v.x; depv[4 * q + 1] = v.y;
            depv[4 * q + 2] = v.z; depv[4 * q + 3] = v.w;
        }
        float dist2 = g_e2[b];
        #pragma unroll
        for (int k = 0; k < KK; ++k)
            dist2 = fmaf(-2.0f * s16[k], depv[k], dist2);
        #pragma unroll
        for (int k = 0; k < KK; ++k) {
            float t = 0.f;
            #pragma unroll
            for (int k2 = 0; k2 < KK; ++k2)
                t = fmaf(sh_G[k * 17 + k2], s16[k2], t);
            dist2 = fmaf(s16[k], t, dist2);
        }
        out[(size_t)b * CC + c] = -sqrtf(fmaxf(dist2, 0.f)) * temp;
    }
    #undef AS
    #undef BS
    #undef FM_LOAD
}

// ---------------------------------------------------------------------------
extern "C" void kernel_launch(void* const* d_in, const int* in_sizes, int n_in,
                              void* d_out, int out_size)
{
    const float* emb    = (const float*)d_in[0];   // [B,D]
    const float* protos = (const float*)d_in[1];   // [C,K,D]
    const float* W1     = (const float*)d_in[2];   // [C,2D,D]
    const float* b1     = (const float*)d_in[3];   // [C,D]
    const float* w2     = (const float*)d_in[4];   // [C,D]
    const float* b2     = (const float*)d_in[5];   // [C]
    const float* temp   = (const float*)d_in[6];   // [1]
    const void*  valid  = (const void*)d_in[7];    // [C,K] bool (storage dtype unknown)
    float* out = (float*)d_out;                    // [B,C]

    // dyn smem = max(GEMM phase 43520 B, epilogue 12832 floats = 51328 B)
    const int dyn = 12832 * 4;
    cudaFuncSetAttribute(fused_main, cudaFuncAttributeMaxDynamicSharedMemorySize, dyn);

    prologue_kernel<<<257, 256>>>(emb, protos, W1, b1, valid);
    fused_main<<<dim3(16, CC), 256, dyn>>>(emb, W1, w2, b2, temp, out);
}

// round 9
// speedup vs baseline: 1.2254x; 1.0395x over previous
#include <cuda_runtime.h>
#include <math_constants.h>
#include <cuda_fp16.h>
#include <cstdint>

// Problem constants
#define BB 1024   // batch
#define CC 32     // classes
#define KK 16     // prototypes per class
#define DD 256    // embedding dim
#define TWO_D 512

// Scratch (static device arrays — no allocation allowed)
__device__ float g_proto_term[CC * KK * DD];          // 512 KB
__device__ float g_dotep[(size_t)BB * CC * KK];       // 2 MB: emb·proto
__device__ float g_G[CC * KK * KK];                   // 32 KB: Gram
__device__ float g_e2[BB];                            // |emb|^2
__device__ float g_inval[CC * KK];                    // 0 = valid, -inf = invalid

__device__ __forceinline__ uint32_t f2tf(float f) {
    uint32_t r;
    asm("cvt.rna.tf32.f32 %0, %1;" : "=r"(r) : "f"(f));
    return r;
}
__device__ __forceinline__ __half2 tanh_h2(__half2 x) {
    uint32_t xi = *reinterpret_cast<uint32_t*>(&x);
    uint32_t r;
    asm("tanh.approx.f16x2 %0, %1;" : "=r"(r) : "r"(xi));
    return *reinterpret_cast<__half2*>(&r);
}
__device__ __forceinline__ uint32_t h2u(__half2 h) {
    return *reinterpret_cast<uint32_t*>(&h);
}
__device__ __forceinline__ void cp16(void* smem, const void* g) {
    uint32_t sa = (uint32_t)__cvta_generic_to_shared(smem);
    asm volatile("cp.async.cg.shared.global [%0], [%1], 16;" :: "r"(sa), "l"(g));
}
#define CP_COMMIT() asm volatile("cp.async.commit_group;")
#define CP_WAIT(N)  asm volatile("cp.async.wait_group %0;" :: "n"(N))

__device__ __forceinline__ void mma_tf32(float c_[4], const uint32_t a[4], const uint32_t b[2]) {
    asm volatile(
        "mma.sync.aligned.m16n8k8.row.col.f32.tf32.tf32.f32 "
        "{%0,%1,%2,%3}, {%4,%5,%6,%7}, {%8,%9}, {%0,%1,%2,%3};"
        : "+f"(c_[0]), "+f"(c_[1]), "+f"(c_[2]), "+f"(c_[3])
        : "r"(a[0]), "r"(a[1]), "r"(a[2]), "r"(a[3]), "r"(b[0]), "r"(b[1]));
}
// fp16 inputs, fp32 accumulate
__device__ __forceinline__ void mma_f16(float c_[4],
    uint32_t a0, uint32_t a1, uint32_t a2, uint32_t a3,
    uint32_t b0, uint32_t b1) {
    asm volatile(
        "mma.sync.aligned.m16n8k16.row.col.f32.f16.f16.f32 "
        "{%0,%1,%2,%3}, {%4,%5,%6,%7}, {%8,%9}, {%0,%1,%2,%3};"
        : "+f"(c_[0]), "+f"(c_[1]), "+f"(c_[2]), "+f"(c_[3])
        : "r"(a0), "r"(a1), "r"(a2), "r"(a3), "r"(b0), "r"(b1));
}

// ===========================================================================
// Kernel A (prologue, fused): blockIdx dispatch, 256 threads everywhere
//   [0,128)   : proto_term  (c = blk>>2, d-slice = (blk&3)*64), MLP-8 prefetch
//   [128,160) : Gram        (c = blk-128)
//   [160,192) : e2          (32 rows per block, warp-per-row x4)
//   192       : decode prototype_valid mask
//   [193,257) : dotep tf32 GEMM (64x128 tiles: bm0=(b>>2)*64, bn0=(b&3)*128)
// ===========================================================================
__global__ __launch_bounds__(256) void prologue_kernel(
    const float* __restrict__ emb,      // [B,D]
    const float* __restrict__ protos,   // [C,K,D]
    const float* __restrict__ W1,       // [C,2D,D]
    const float* __restrict__ b1,       // [C,D]
    const void*  __restrict__ valid)
{
    __shared__ __align__(16) float sh[8192];   // 32 KB, reused per role
    const int blk = blockIdx.x;
    const int tid = threadIdx.x;

    if (blk < 128) {
        // ----- proto_term[c][k][d0+dl] = b1 + sum_e protos[c][k][e]*W1[c][D+e][d0+dl]
        const int c  = blk >> 2;
        const int d0 = (blk & 3) * 64;
        const int dl = tid & 63;        // d within slice
        const int eg = tid >> 6;        // e-group 0..3 (64 e's each)

        float* p_s  = sh;               // [16][256]
        float* sred = sh + KK * DD;     // [4][16][64]

        const float* pg = protos + (size_t)c * KK * DD;
        #pragma unroll
        for (int i = 0; i < 16; ++i) p_s[tid + i * 256] = pg[tid + i * 256];
        __syncthreads();

        float acc[KK];
        #pragma unroll
        for (int k = 0; k < KK; ++k) acc[k] = 0.f;

        // W1 bottom rows D+eg*64 .. +63, column d0+dl; 8-deep prefetch (MLP=8)
        const float* Wb = W1 + ((size_t)c * TWO_D + DD + eg * 64) * DD + d0 + dl;
        for (int e0 = 0; e0 < 64; e0 += 8) {
            float w[8];
            #pragma unroll
            for (int u = 0; u < 8; ++u) w[u] = Wb[(size_t)(e0 + u) * DD];
            #pragma unroll
            for (int u = 0; u < 8; ++u) {
                const float* pe = p_s + eg * 64 + e0 + u;
                #pragma unroll
                for (int k = 0; k < KK; ++k)
                    acc[k] = fmaf(pe[k * DD], w[u], acc[k]);
            }
        }

        #pragma unroll
        for (int k = 0; k < KK; ++k)
            sred[(eg * KK + k) * 64 + dl] = acc[k];
        __syncthreads();

        #pragma unroll
        for (int r = 0; r < 4; ++r) {
            int idx = tid + r * 256;        // k*64 + dl
            int k = idx >> 6, d = idx & 63;
            float s = sred[(0 * KK + k) * 64 + d] + sred[(1 * KK + k) * 64 + d]
                    + sred[(2 * KK + k) * 64 + d] + sred[(3 * KK + k) * 64 + d];
            g_proto_term[((c * KK) + k) * DD + d0 + d] = s + b1[c * DD + d0 + d];
        }

    } else if (blk < 160) {
        // ----- Gram G[c][k][k2]
        const int c = blk - 128;
        float* p_s = sh;   // [16][257]
        for (int i = tid; i < KK * DD; i += 256) {
            int k = i / DD, d = i % DD;
            p_s[k * (DD + 1) + d] = protos[(size_t)c * KK * DD + i];
        }
        __syncthreads();
        const int k = tid >> 4, k2 = tid & 15;
        float s = 0.f;
        #pragma unroll 4
        for (int d = 0; d < DD; ++d)
            s = fmaf(p_s[k * (DD + 1) + d], p_s[k2 * (DD + 1) + d], s);
        g_G[c * 256 + tid] = s;

    } else if (blk < 192) {
        // ----- e2: warp-per-row, 4 rows per warp
        const int warp = tid >> 5, lane = tid & 31;
        const int base = (blk - 160) * 32 + warp * 4;
        #pragma unroll
        for (int t = 0; t < 4; ++t) {
            const int b = base + t;
            const float4* p = (const float4*)(emb + (size_t)b * DD);
            float4 v0 = p[lane], v1 = p[lane + 32];
            float s = v0.x*v0.x + v0.y*v0.y + v0.z*v0.z + v0.w*v0.w
                    + v1.x*v1.x + v1.y*v1.y + v1.z*v1.z + v1.w*v1.w;
            #pragma unroll
            for (int off = 16; off > 0; off >>= 1)
                s += __shfl_xor_sync(0xFFFFFFFFu, s, off);
            if (lane == 0) g_e2[b] = s;
        }

    } else if (blk == 192) {
        // ----- decode prototype_valid (dtype-sniffing)
        __shared__ int s_hasF, s_hasHi, s_mode;
        if (tid == 0) { s_hasF = 0; s_hasHi = 0; }
        __syncthreads();
        if (tid < 128) {   // first 512 bytes — in-bounds for uint8/int32/float32
            unsigned v = ((const unsigned*)valid)[tid];
            if (v == 0x3F800000u)                        atomicOr(&s_hasF, 1);
            else if (v != 0u && (v & 0xFFFFFF00u) != 0u) atomicOr(&s_hasHi, 1);
        }
        __syncthreads();
        if (tid == 0) s_mode = s_hasF ? 0 : (s_hasHi ? 2 : 1);
        __syncthreads();
        const int mode = s_mode;
        for (int i = tid; i < CC * KK; i += 256) {
            bool v;
            if (mode == 0)      v = ((const float*)valid)[i] != 0.0f;
            else if (mode == 1) v = ((const int*)valid)[i] != 0;
            else                v = ((const unsigned char*)valid)[i] != 0;
            g_inval[i] = v ? 0.0f : -CUDART_INF_F;
        }

    } else {
        // ----- dotep[b][ck] = emb[b,:]·proto[ck,:]  (tf32 mma)
        // 64x128 tile, BK=16 double-buffered, 8 warps (2m x 4n), warp 32x32.
        const int b    = blk - 193;              // 0..63
        const int bm0  = (b >> 2) * 64;          // over 1024 batch
        const int bn0  = (b & 3) * 128;          // over 512 protos

        // As [2][64][20] at sh[0], Ps [2][128][20] at sh[2560]
        #define DAS(s, m, k) sh[(s) * 1280 + (m) * 20 + (k)]
        #define DPS(s, n, k) sh[2560 + (s) * 2560 + (n) * 20 + (k)]

        const int warp = tid >> 5, lane = tid & 31;
        const int wm = (warp >> 2) * 32;
        const int wn = (warp & 3) * 32;
        const int g  = lane >> 2, tg = lane & 3;

        float acc[2][4][4];
        #pragma unroll
        for (int i = 0; i < 2; ++i)
            #pragma unroll
            for (int j = 0; j < 4; ++j)
                #pragma unroll
                for (int t = 0; t < 4; ++t) acc[i][j][t] = 0.f;

        #define DE_LOAD(s, kbase)                                                         \
            {                                                                              \
                { int m = tid >> 2, k4 = (tid & 3) << 2;                                   \
                  cp16(&DAS(s, m, k4), emb + (size_t)(bm0 + m) * DD + (kbase) + k4); }     \
                _Pragma("unroll")                                                          \
                for (int i_ = 0; i_ < 2; ++i_) {                                           \
                    int slot = tid + i_ * 256;                                             \
                    int n = slot >> 2, k4 = (slot & 3) << 2;                               \
                    cp16(&DPS(s, n, k4), protos + (size_t)(bn0 + n) * DD + (kbase) + k4);  \
                }                                                                          \
                CP_COMMIT();                                                               \
            }

        DE_LOAD(0, 0);
        int s = 0;
        const int NT = DD / 16;
        for (int kt = 0; kt < NT; ++kt) {
            if (kt + 1 < NT) { DE_LOAD(s ^ 1, (kt + 1) * 16); CP_WAIT(1); }
            else             { CP_WAIT(0); }
            __syncthreads();

            #pragma unroll
            for (int ks = 0; ks < 2; ++ks) {
                const int kb = ks * 8;
                uint32_t afr[2][4], bfr[4][2];
                #pragma unroll
                for (int i = 0; i < 2; ++i) {
                    int m0 = wm + i * 16;
                    afr[i][0] = f2tf(DAS(s, m0 + g,     kb + tg));
                    afr[i][1] = f2tf(DAS(s, m0 + g + 8, kb + tg));
                    afr[i][2] = f2tf(DAS(s, m0 + g,     kb + tg + 4));
                    afr[i][3] = f2tf(DAS(s, m0 + g + 8, kb + tg + 4));
                }
                #pragma unroll
                for (int j = 0; j < 4; ++j) {
                    int n0 = wn + j * 8;
                    bfr[j][0] = f2tf(DPS(s, n0 + g, kb + tg));
                    bfr[j][1] = f2tf(DPS(s, n0 + g, kb + tg + 4));
                }
                #pragma unroll
                for (int i = 0; i < 2; ++i)
                    #pragma unroll
                    for (int j = 0; j < 4; ++j)
                        mma_tf32(acc[i][j], afr[i], bfr[j]);
            }
            __syncthreads();
            s ^= 1;
        }

        #pragma unroll
        for (int i = 0; i < 2; ++i) {
            int r0 = bm0 + wm + i * 16 + g;
            #pragma unroll
            for (int j = 0; j < 4; ++j) {
                int col = bn0 + wn + j * 8 + 2 * tg;
                *(float2*)(g_dotep + (size_t)r0 * (CC * KK) + col)       = make_float2(acc[i][j][0], acc[i][j][1]);
                *(float2*)(g_dotep + (size_t)(r0 + 8) * (CC * KK) + col) = make_float2(acc[i][j][2], acc[i][j][3]);
            }
        }
        #undef DE_LOAD
        #undef DAS
        #undef DPS
    }
}

// ===========================================================================
// Kernel B (main, fused): per (64-batch-tile, class):
//   1. qW tile [64 x 256] = emb_tile @ W1top  (tf32 mma, acc in registers)
//   2. epilogue: tanh in f16x2, then scores via SECOND-STAGE fp16 mma:
//      C-frag(half2) of GEMM == A-frag of m16n8k16; B = w2 pairs broadcast
//      over n. Tensor core does the d-reduction; no shfl, fp32 accumulate.
//   3. softmax over K, dist via Gram trick, write out
// grid (16, 32), 256 threads (8 warps, n-sliced: warp tile 64x32), 2 CTAs/SM.
// ===========================================================================
__global__ __launch_bounds__(256, 2) void fused_main(
    const float* __restrict__ emb, const float* __restrict__ W1,
    const float* __restrict__ w2, const float* __restrict__ b2,
    const float* __restrict__ temperature, float* __restrict__ out)
{
    extern __shared__ float sh[];
    // phase-1 layout: As [2][64][20] = 2560 fl ; Bs [2][16][260] = 8320 fl
    float* Asb = sh;
    float* Bsb = sh + 2560;
    // phase-2 layout (aliases phase-1 region)
    uint32_t* sh_pt_h2 = (uint32_t*)sh;        // [16][128] half2 = 2048 words
    float* sh_scorew = sh + 2048;              // [8 warps][64 rows][20] = 10240
    float* sh_w2    = sh + 2048 + 10240;       // 256
    float* sh_G     = sh_w2 + 256;             // [16][17] = 272
    float* sh_inval = sh_G + 272;              // 16

    const int c  = blockIdx.y;
    const int b0 = blockIdx.x * 64;
    const float* A  = emb;
    const float* Bm = W1 + (size_t)c * TWO_D * DD;   // top half [256 k][256 n]

    const int tid  = threadIdx.x;
    const int warp = tid >> 5, lane = tid & 31;
    const int wn = warp * 32;            // warp n-slice (all 64 rows)
    const int g  = lane >> 2, tg = lane & 3;

    float acc[4][4][4];                  // [m16 tile][n8 tile][frag]
    #pragma unroll
    for (int i = 0; i < 4; ++i)
        #pragma unroll
        for (int j = 0; j < 4; ++j)
            #pragma unroll
            for (int t = 0; t < 4; ++t) acc[i][j][t] = 0.f;

    #define AS(s, m, k) Asb[(s) * 1280 + (m) * 20 + (k)]
    #define BS(s, k, n) Bsb[(s) * 4160 + (k) * 260 + (n)]
    #define FM_LOAD(s, kbase)                                                    \
        {                                                                         \
            { int m = tid >> 2, k4 = (tid & 3) << 2;                              \
              cp16(&AS(s, m, k4), A + (size_t)(b0 + m) * DD + (kbase) + k4); }    \
            _Pragma("unroll")                                                     \
            for (int i_ = 0; i_ < 4; ++i_) {                                      \
                int slot = tid + i_ * 256;                                        \
                int k = slot >> 6, n4 = (slot & 63) << 2;                         \
                cp16(&BS(s, k, n4), Bm + (size_t)((kbase) + k) * DD + n4);        \
            }                                                                     \
            CP_COMMIT();                                                          \
        }

    // ---------------- Phase 1: tf32 GEMM ----------------
    FM_LOAD(0, 0);
    int s = 0;
    const int NT = DD / 16;   // 16
    for (int kt = 0; kt < NT; ++kt) {
        if (kt + 1 < NT) { FM_LOAD(s ^ 1, (kt + 1) * 16); CP_WAIT(1); }
        else             { CP_WAIT(0); }
        __syncthreads();

        #pragma unroll
        for (int ks = 0; ks < 2; ++ks) {
            const int kb = ks * 8;
            uint32_t afr[4][4], bfr[4][2];
            #pragma unroll
            for (int i = 0; i < 4; ++i) {
                int m0 = i * 16;
                afr[i][0] = f2tf(AS(s, m0 + g,     kb + tg));
                afr[i][1] = f2tf(AS(s, m0 + g + 8, kb + tg));
                afr[i][2] = f2tf(AS(s, m0 + g,     kb + tg + 4));
                afr[i][3] = f2tf(AS(s, m0 + g + 8, kb + tg + 4));
            }
            #pragma unroll
            for (int j = 0; j < 4; ++j) {
                int n0 = wn + j * 8;
                bfr[j][0] = f2tf(BS(s, kb + tg,     n0 + g));
                bfr[j][1] = f2tf(BS(s, kb + tg + 4, n0 + g));
            }
            #pragma unroll
            for (int i = 0; i < 4; ++i)
                #pragma unroll
                for (int j = 0; j < 4; ++j)
                    mma_tf32(acc[i][j], afr[i], bfr[j]);
        }
        __syncthreads();
        s ^= 1;
    }
    // last iteration ended with __syncthreads() — safe to repurpose smem.

    // ---------------- Phase 2 tables ----------------
    {
        // pt as half2: [k][128 d-pairs]
        const float2* ptg2 = (const float2*)(g_proto_term + (size_t)c * KK * DD);
        #pragma unroll
        for (int i = 0; i < 8; ++i) {
            int idx = tid + i * 256;            // 0..2047
            float2 v = ptg2[idx];
            __half2 h = __floats2half2_rn(v.x, v.y);
            sh_pt_h2[idx] = *(uint32_t*)&h;
        }
        if (tid < DD) sh_w2[tid] = w2[c * DD + tid];
        if (tid < KK * KK) sh_G[(tid >> 4) * 17 + (tid & 15)] = g_G[c * 256 + tid];
        if (tid < KK) sh_inval[tid] = g_inval[c * KK + tid];
    }
    __syncthreads();

    // pack acc fragments to half2 once (rows g / g+8, cols {2tg,2tg+1} of tile j)
    __half2 acch[4][4][2];
    #pragma unroll
    for (int i = 0; i < 4; ++i)
        #pragma unroll
        for (int j = 0; j < 4; ++j) {
            acch[i][j][0] = __floats2half2_rn(acc[i][j][0], acc[i][j][1]);
            acch[i][j][1] = __floats2half2_rn(acc[i][j][2], acc[i][j][3]);
        }

    // per-thread w2 pairs for held columns (double as B-fragments of 2nd mma)
    uint32_t w2u[4];
    #pragma unroll
    for (int j = 0; j < 4; ++j) {
        float2 w = *(float2*)&sh_w2[wn + j * 8 + 2 * tg];
        w2u[j] = h2u(__floats2half2_rn(w.x, w.y));
    }

    float* my_slab = sh_scorew + warp * 1280;   // [64][20]
    const int ptbase = (wn >> 1) + tg;          // d-pair index base

    // ---------------- Phase 3: tanh + 2nd-stage mma scores ----------------
    #pragma unroll 1
    for (int k = 0; k < KK; ++k) {
        __half2 pth[4];
        #pragma unroll
        for (int j = 0; j < 4; ++j) {
            uint32_t w = sh_pt_h2[k * 128 + ptbase + j * 4];
            pth[j] = *reinterpret_cast<__half2*>(&w);
        }

        #pragma unroll
        for (int i = 0; i < 4; ++i) {
            // tanh outputs, already in A-fragment half2 layout
            uint32_t t00 = h2u(tanh_h2(__hadd2(acch[i][0][0], pth[0])));
            uint32_t t01 = h2u(tanh_h2(__hadd2(acch[i][0][1], pth[0])));
            uint32_t t10 = h2u(tanh_h2(__hadd2(acch[i][1][0], pth[1])));
            uint32_t t11 = h2u(tanh_h2(__hadd2(acch[i][1][1], pth[1])));
            uint32_t t20 = h2u(tanh_h2(__hadd2(acch[i][2][0], pth[2])));
            uint32_t t21 = h2u(tanh_h2(__hadd2(acch[i][2][1], pth[2])));
            uint32_t t30 = h2u(tanh_h2(__hadd2(acch[i][3][0], pth[3])));
            uint32_t t31 = h2u(tanh_h2(__hadd2(acch[i][3][1], pth[3])));

            float cfr[4] = {0.f, 0.f, 0.f, 0.f};
            // u=0: k16 group from n8-tiles 0,1 ; B = w2 pairs (broadcast over n)
            mma_f16(cfr, t00, t01, t10, t11, w2u[0], w2u[1]);
            // u=1: k16 group from n8-tiles 2,3
            mma_f16(cfr, t20, t21, t30, t31, w2u[2], w2u[3]);

            // every n-col holds the same score; c0 = row g, c2 = row g+8
            if (tg == 0) {
                my_slab[(i * 16 + g) * 20 + k]     = cfr[0];
                my_slab[(i * 16 + g + 8) * 20 + k] = cfr[2];
            }
        }
    }
    __syncthreads();

    // ---------------- Phase 4: gather slabs + softmax + Gram distance -------
    if (tid < 64) {
        const int b = b0 + tid;
        const float b2v  = b2[c];
        const float temp = temperature[0];

        float s16[KK];
        #pragma unroll
        for (int k = 0; k < KK; ++k) s16[k] = b2v + sh_inval[k];
        #pragma unroll
        for (int w = 0; w < 8; ++w) {
            const float* p = sh_scorew + w * 1280 + tid * 20;
            float4 v0 = *(const float4*)(p + 0);
            float4 v1 = *(const float4*)(p + 4);
            float4 v2 = *(const float4*)(p + 8);
            float4 v3 = *(const float4*)(p + 12);
            s16[0] += v0.x;  s16[1] += v0.y;  s16[2] += v0.z;  s16[3] += v0.w;
            s16[4] += v1.x;  s16[5] += v1.y;  s16[6] += v1.z;  s16[7] += v1.w;
            s16[8] += v2.x;  s16[9] += v2.y;  s16[10] += v2.z; s16[11] += v2.w;
            s16[12] += v3.x; s16[13] += v3.y; s16[14] += v3.z; s16[15] += v3.w;
        }

        float m = s16[0];
        #pragma unroll
        for (int k = 1; k < KK; ++k) m = fmaxf(m, s16[k]);
        float sum = 0.f;
        #pragma unroll
        for (int k = 0; k < KK; ++k) {
            float e = __expf(s16[k] - m);
            s16[k] = e;
            sum += e;
        }
        float inv = 1.f / sum;
        #pragma unroll
        for (int k = 0; k < KK; ++k) s16[k] *= inv;

        // dist^2 = e2 - 2*attn·dotep + attn^T G attn
        float depv[KK];
        const float4* dep = (const float4*)(g_dotep + (size_t)b * (CC * KK) + c * KK);
        #pragma unroll
        for (int q = 0; q < 4; ++q) {
            float4 v = dep[q];
            depv[4 * q + 0] = v.x; depv[4 * q + 1] = v.y;
            depv[4 * q + 2] = v.z; depv[4 * q + 3] = v.w;
        }
        float dist2 = g_e2[b];
        #pragma unroll
        for (int k = 0; k < KK; ++k)
            dist2 = fmaf(-2.0f * s16[k], depv[k], dist2);
        #pragma unroll
        for (int k = 0; k < KK; ++k) {
            float t = 0.f;
            #pragma unroll
            for (int k2 = 0; k2 < KK; ++k2)
                t = fmaf(sh_G[k * 17 + k2], s16[k2], t);
            dist2 = fmaf(s16[k], t, dist2);
        }
        out[(size_t)b * CC + c] = -sqrtf(fmaxf(dist2, 0.f)) * temp;
    }
    #undef AS
    #undef BS
    #undef FM_LOAD
}

// ---------------------------------------------------------------------------
extern "C" void kernel_launch(void* const* d_in, const int* in_sizes, int n_in,
                              void* d_out, int out_size)
{
    const float* emb    = (const float*)d_in[0];   // [B,D]
    const float* protos = (const float*)d_in[1];   // [C,K,D]
    const float* W1     = (const float*)d_in[2];   // [C,2D,D]
    const float* b1     = (const float*)d_in[3];   // [C,D]
    const float* w2     = (const float*)d_in[4];   // [C,D]
    const float* b2     = (const float*)d_in[5];   // [C]
    const float* temp   = (const float*)d_in[6];   // [1]
    const void*  valid  = (const void*)d_in[7];    // [C,K] bool (storage dtype unknown)
    float* out = (float*)d_out;                    // [B,C]

    // dyn smem = max(GEMM phase 43520 B, epilogue 12832 floats = 51328 B)
    const int dyn = 12832 * 4;
    cudaFuncSetAttribute(fused_main, cudaFuncAttributeMaxDynamicSharedMemorySize, dyn);

    prologue_kernel<<<257, 256>>>(emb, protos, W1, b1, valid);
    fused_main<<<dim3(16, CC), 256, dyn>>>(emb, W1, w2, b2, temp, out);
}

// round 10
// speedup vs baseline: 1.3159x; 1.0738x over previous
#include <cuda_runtime.h>
#include <math_constants.h>
#include <cuda_fp16.h>
#include <cstdint>

// Problem constants
#define BB 1024   // batch
#define CC 32     // classes
#define KK 16     // prototypes per class
#define DD 256    // embedding dim
#define TWO_D 512

// Scratch (static device arrays — no allocation allowed)
__device__ float g_proto_term[CC * KK * DD];          // 512 KB
__device__ float g_dotep[(size_t)BB * CC * KK];       // 2 MB: emb·proto
__device__ float g_G[CC * KK * KK];                   // 32 KB: Gram
__device__ float g_e2[BB];                            // |emb|^2
__device__ float g_inval[CC * KK];                    // 0 = valid, -inf = invalid
__device__ __half g_emb_h[(size_t)BB * DD];           // 512 KB: emb as half
__device__ __half g_W1h[(size_t)CC * DD * DD];        // 4 MB: W1top^T as half [c][n][k]

__device__ __forceinline__ uint32_t f2tf(float f) {
    uint32_t r;
    asm("cvt.rna.tf32.f32 %0, %1;" : "=r"(r) : "f"(f));
    return r;
}
__device__ __forceinline__ __half2 tanh_h2(__half2 x) {
    uint32_t xi = *reinterpret_cast<uint32_t*>(&x);
    uint32_t r;
    asm("tanh.approx.f16x2 %0, %1;" : "=r"(r) : "r"(xi));
    return *reinterpret_cast<__half2*>(&r);
}
__device__ __forceinline__ uint32_t h2u(__half2 h) {
    return *reinterpret_cast<uint32_t*>(&h);
}
__device__ __forceinline__ void cp16(void* smem, const void* g) {
    uint32_t sa = (uint32_t)__cvta_generic_to_shared(smem);
    asm volatile("cp.async.cg.shared.global [%0], [%1], 16;" :: "r"(sa), "l"(g));
}
#define CP_COMMIT() asm volatile("cp.async.commit_group;")
#define CP_WAIT(N)  asm volatile("cp.async.wait_group %0;" :: "n"(N))

__device__ __forceinline__ void mma_tf32(float c_[4], const uint32_t a[4], const uint32_t b[2]) {
    asm volatile(
        "mma.sync.aligned.m16n8k8.row.col.f32.tf32.tf32.f32 "
        "{%0,%1,%2,%3}, {%4,%5,%6,%7}, {%8,%9}, {%0,%1,%2,%3};"
        : "+f"(c_[0]), "+f"(c_[1]), "+f"(c_[2]), "+f"(c_[3])
        : "r"(a[0]), "r"(a[1]), "r"(a[2]), "r"(a[3]), "r"(b[0]), "r"(b[1]));
}
// fp16 inputs, fp32 accumulate
__device__ __forceinline__ void mma_f16(float c_[4],
    uint32_t a0, uint32_t a1, uint32_t a2, uint32_t a3,
    uint32_t b0, uint32_t b1) {
    asm volatile(
        "mma.sync.aligned.m16n8k16.row.col.f32.f16.f16.f32 "
        "{%0,%1,%2,%3}, {%4,%5,%6,%7}, {%8,%9}, {%0,%1,%2,%3};"
        : "+f"(c_[0]), "+f"(c_[1]), "+f"(c_[2]), "+f"(c_[3])
        : "r"(a0), "r"(a1), "r"(a2), "r"(a3), "r"(b0), "r"(b1));
}

// ===========================================================================
// Kernel A (prologue, fused): blockIdx dispatch, 256 threads everywhere
//   [0,128)   : proto_term  (c = blk>>2, d-slice = (blk&3)*64), MLP-8 prefetch
//   [128,160) : Gram        (c = blk-128)
//   [160,192) : e2 + emb->half
//   192       : decode prototype_valid mask
//   [193,257) : dotep tf32 GEMM (64x128 tiles)
//   [257,385) : W1top transpose->half: g_W1h[c][n][k]  (c = idx>>2, tj = idx&3)
// ===========================================================================
__global__ __launch_bounds__(256) void prologue_kernel(
    const float* __restrict__ emb,      // [B,D]
    const float* __restrict__ protos,   // [C,K,D]
    const float* __restrict__ W1,       // [C,2D,D]
    const float* __restrict__ b1,       // [C,D]
    const void*  __restrict__ valid)
{
    __shared__ __align__(16) float sh[8192];   // 32 KB, reused per role
    const int blk = blockIdx.x;
    const int tid = threadIdx.x;

    if (blk < 128) {
        // ----- proto_term[c][k][d0+dl] = b1 + sum_e protos[c][k][e]*W1[c][D+e][d0+dl]
        const int c  = blk >> 2;
        const int d0 = (blk & 3) * 64;
        const int dl = tid & 63;
        const int eg = tid >> 6;

        float* p_s  = sh;               // [16][256]
        float* sred = sh + KK * DD;     // [4][16][64]

        const float* pg = protos + (size_t)c * KK * DD;
        #pragma unroll
        for (int i = 0; i < 16; ++i) p_s[tid + i * 256] = pg[tid + i * 256];
        __syncthreads();

        float acc[KK];
        #pragma unroll
        for (int k = 0; k < KK; ++k) acc[k] = 0.f;

        const float* Wb = W1 + ((size_t)c * TWO_D + DD + eg * 64) * DD + d0 + dl;
        for (int e0 = 0; e0 < 64; e0 += 8) {
            float w[8];
            #pragma unroll
            for (int u = 0; u < 8; ++u) w[u] = Wb[(size_t)(e0 + u) * DD];
            #pragma unroll
            for (int u = 0; u < 8; ++u) {
                const float* pe = p_s + eg * 64 + e0 + u;
                #pragma unroll
                for (int k = 0; k < KK; ++k)
                    acc[k] = fmaf(pe[k * DD], w[u], acc[k]);
            }
        }

        #pragma unroll
        for (int k = 0; k < KK; ++k)
            sred[(eg * KK + k) * 64 + dl] = acc[k];
        __syncthreads();

        #pragma unroll
        for (int r = 0; r < 4; ++r) {
            int idx = tid + r * 256;
            int k = idx >> 6, d = idx & 63;
            float s = sred[(0 * KK + k) * 64 + d] + sred[(1 * KK + k) * 64 + d]
                    + sred[(2 * KK + k) * 64 + d] + sred[(3 * KK + k) * 64 + d];
            g_proto_term[((c * KK) + k) * DD + d0 + d] = s + b1[c * DD + d0 + d];
        }

    } else if (blk < 160) {
        // ----- Gram G[c][k][k2]
        const int c = blk - 128;
        float* p_s = sh;   // [16][257]
        for (int i = tid; i < KK * DD; i += 256) {
            int k = i / DD, d = i % DD;
            p_s[k * (DD + 1) + d] = protos[(size_t)c * KK * DD + i];
        }
        __syncthreads();
        const int k = tid >> 4, k2 = tid & 15;
        float s = 0.f;
        #pragma unroll 4
        for (int d = 0; d < DD; ++d)
            s = fmaf(p_s[k * (DD + 1) + d], p_s[k2 * (DD + 1) + d], s);
        g_G[c * 256 + tid] = s;

    } else if (blk < 192) {
        // ----- e2 + emb->half: warp-per-row, 4 rows per warp
        const int warp = tid >> 5, lane = tid & 31;
        const int base = (blk - 160) * 32 + warp * 4;
        #pragma unroll
        for (int t = 0; t < 4; ++t) {
            const int b = base + t;
            const float4* p = (const float4*)(emb + (size_t)b * DD);
            float4 v0 = p[lane], v1 = p[lane + 32];
            // emit half copies (coalesced uint2 stores)
            uint2* eh = (uint2*)(g_emb_h + (size_t)b * DD);
            uint2 w0, w1;
            w0.x = h2u(__floats2half2_rn(v0.x, v0.y));
            w0.y = h2u(__floats2half2_rn(v0.z, v0.w));
            w1.x = h2u(__floats2half2_rn(v1.x, v1.y));
            w1.y = h2u(__floats2half2_rn(v1.z, v1.w));
            eh[lane]      = w0;
            eh[lane + 32] = w1;
            float s = v0.x*v0.x + v0.y*v0.y + v0.z*v0.z + v0.w*v0.w
                    + v1.x*v1.x + v1.y*v1.y + v1.z*v1.z + v1.w*v1.w;
            #pragma unroll
            for (int off = 16; off > 0; off >>= 1)
                s += __shfl_xor_sync(0xFFFFFFFFu, s, off);
            if (lane == 0) g_e2[b] = s;
        }

    } else if (blk == 192) {
        // ----- decode prototype_valid (dtype-sniffing)
        __shared__ int s_hasF, s_hasHi, s_mode;
        if (tid == 0) { s_hasF = 0; s_hasHi = 0; }
        __syncthreads();
        if (tid < 128) {
            unsigned v = ((const unsigned*)valid)[tid];
            if (v == 0x3F800000u)                        atomicOr(&s_hasF, 1);
            else if (v != 0u && (v & 0xFFFFFF00u) != 0u) atomicOr(&s_hasHi, 1);
        }
        __syncthreads();
        if (tid == 0) s_mode = s_hasF ? 0 : (s_hasHi ? 2 : 1);
        __syncthreads();
        const int mode = s_mode;
        for (int i = tid; i < CC * KK; i += 256) {
            bool v;
            if (mode == 0)      v = ((const float*)valid)[i] != 0.0f;
            else if (mode == 1) v = ((const int*)valid)[i] != 0;
            else                v = ((const unsigned char*)valid)[i] != 0;
            g_inval[i] = v ? 0.0f : -CUDART_INF_F;
        }

    } else if (blk < 257) {
        // ----- dotep[b][ck] = emb[b,:]·proto[ck,:]  (tf32 mma)
        const int b    = blk - 193;              // 0..63
        const int bm0  = (b >> 2) * 64;
        const int bn0  = (b & 3) * 128;

        #define DAS(s, m, k) sh[(s) * 1280 + (m) * 20 + (k)]
        #define DPS(s, n, k) sh[2560 + (s) * 2560 + (n) * 20 + (k)]

        const int warp = tid >> 5, lane = tid & 31;
        const int wm = (warp >> 2) * 32;
        const int wn = (warp & 3) * 32;
        const int g  = lane >> 2, tg = lane & 3;

        float acc[2][4][4];
        #pragma unroll
        for (int i = 0; i < 2; ++i)
            #pragma unroll
            for (int j = 0; j < 4; ++j)
                #pragma unroll
                for (int t = 0; t < 4; ++t) acc[i][j][t] = 0.f;

        #define DE_LOAD(s, kbase)                                                         \
            {                                                                              \
                { int m = tid >> 2, k4 = (tid & 3) << 2;                                   \
                  cp16(&DAS(s, m, k4), emb + (size_t)(bm0 + m) * DD + (kbase) + k4); }     \
                _Pragma("unroll")                                                          \
                for (int i_ = 0; i_ < 2; ++i_) {                                           \
                    int slot = tid + i_ * 256;                                             \
                    int n = slot >> 2, k4 = (slot & 3) << 2;                               \
                    cp16(&DPS(s, n, k4), protos + (size_t)(bn0 + n) * DD + (kbase) + k4);  \
                }                                                                          \
                CP_COMMIT();                                                               \
            }

        DE_LOAD(0, 0);
        int s = 0;
        const int NT = DD / 16;
        for (int kt = 0; kt < NT; ++kt) {
            if (kt + 1 < NT) { DE_LOAD(s ^ 1, (kt + 1) * 16); CP_WAIT(1); }
            else             { CP_WAIT(0); }
            __syncthreads();

            #pragma unroll
            for (int ks = 0; ks < 2; ++ks) {
                const int kb = ks * 8;
                uint32_t afr[2][4], bfr[4][2];
                #pragma unroll
                for (int i = 0; i < 2; ++i) {
                    int m0 = wm + i * 16;
                    afr[i][0] = f2tf(DAS(s, m0 + g,     kb + tg));
                    afr[i][1] = f2tf(DAS(s, m0 + g + 8, kb + tg));
                    afr[i][2] = f2tf(DAS(s, m0 + g,     kb + tg + 4));
                    afr[i][3] = f2tf(DAS(s, m0 + g + 8, kb + tg + 4));
                }
                #pragma unroll
                for (int j = 0; j < 4; ++j) {
                    int n0 = wn + j * 8;
                    bfr[j][0] = f2tf(DPS(s, n0 + g, kb + tg));
                    bfr[j][1] = f2tf(DPS(s, n0 + g, kb + tg + 4));
                }
                #pragma unroll
                for (int i = 0; i < 2; ++i)
                    #pragma unroll
                    for (int j = 0; j < 4; ++j)
                        mma_tf32(acc[i][j], afr[i], bfr[j]);
            }
            __syncthreads();
            s ^= 1;
        }

        #pragma unroll
        for (int i = 0; i < 2; ++i) {
            int r0 = bm0 + wm + i * 16 + g;
            #pragma unroll
            for (int j = 0; j < 4; ++j) {
                int col = bn0 + wn + j * 8 + 2 * tg;
                *(float2*)(g_dotep + (size_t)r0 * (CC * KK) + col)       = make_float2(acc[i][j][0], acc[i][j][1]);
                *(float2*)(g_dotep + (size_t)(r0 + 8) * (CC * KK) + col) = make_float2(acc[i][j][2], acc[i][j][3]);
            }
        }
        #undef DE_LOAD
        #undef DAS
        #undef DPS

    } else {
        // ----- W1top -> g_W1h[c][n][k] (transpose + half convert)
        const int idx = blk - 257;           // 0..127
        const int c  = idx >> 2;
        const int tj = idx & 3;              // 64-wide n slice
        float* ts = sh;                      // [64][65]
        const float* Wt = W1 + (size_t)c * TWO_D * DD;   // top half [256 k][256 n]
        __half* outc = g_W1h + (size_t)c * DD * DD;

        for (int ti = 0; ti < 4; ++ti) {
            // load tile: rows k=ti*64+r, cols n=tj*64..+63
            {
                int r = tid >> 2, cg = (tid & 3) * 16;
                const float* src = Wt + (size_t)(ti * 64 + r) * DD + tj * 64 + cg;
                #pragma unroll
                for (int u = 0; u < 4; ++u) {
                    float4 v = *(const float4*)(src + u * 4);
                    ts[r * 65 + cg + u * 4 + 0] = v.x;
                    ts[r * 65 + cg + u * 4 + 1] = v.y;
                    ts[r * 65 + cg + u * 4 + 2] = v.z;
                    ts[r * 65 + cg + u * 4 + 3] = v.w;
                }
            }
            __syncthreads();
            // write transposed: out[n][k] = ts[k_local][n_local]
            {
                int nn = tid >> 2, kg = (tid & 3) * 16;
                uint32_t* dst = (uint32_t*)(outc + (size_t)(tj * 64 + nn) * DD + ti * 64 + kg);
                #pragma unroll
                for (int u = 0; u < 8; ++u) {
                    __half2 h = __floats2half2_rn(ts[(kg + 2 * u) * 65 + nn],
                                                  ts[(kg + 2 * u + 1) * 65 + nn]);
                    dst[u] = h2u(h);
                }
            }
            __syncthreads();
        }
    }
}

// ===========================================================================
// Kernel B (main, fused): per (64-batch-tile, class):
//   1. qW tile [64 x 256] = emb_h @ W1h   (f16 mma k16, fp32 accumulate,
//      operands preconverted — zero cvt in the hot loop)
//   2. epilogue: tanh f16x2 + 2nd-stage f16 mma scores (tensor-core reduction)
//   3. softmax over K, dist via Gram trick, write out
// grid (16, 32), 256 threads (8 warps, n-sliced: warp tile 64x32), 2 CTAs/SM.
// ===========================================================================
__global__ __launch_bounds__(256, 2) void fused_main(
    const float* __restrict__ w2, const float* __restrict__ b2,
    const float* __restrict__ temperature, float* __restrict__ out)
{
    extern __shared__ float sh[];
    uint32_t* shw = (uint32_t*)sh;
    // phase-1 (half, padded rows of 12 words = 24 halfs):
    //   AsW: [2][64][12]  words 0..1535
    //   BsW: [2][256][12] words 1536..7679
    // phase-2 layout (aliases phase-1 region)
    uint32_t* sh_pt_h2 = (uint32_t*)sh;        // [16][128] half2 = 2048 words
    float* sh_scorew = sh + 2048;              // [8 warps][64 rows][20] = 10240
    float* sh_w2    = sh + 2048 + 10240;       // 256
    float* sh_G     = sh_w2 + 256;             // [16][17] = 272
    float* sh_inval = sh_G + 272;              // 16

    const int c  = blockIdx.y;
    const int b0 = blockIdx.x * 64;
    const __half* Wh = g_W1h + (size_t)c * DD * DD;   // [n][k] half

    const int tid  = threadIdx.x;
    const int warp = tid >> 5, lane = tid & 31;
    const int wn = warp * 32;            // warp n-slice (all 64 rows)
    const int g  = lane >> 2, tg = lane & 3;

    float acc[4][4][4];                  // [m16 tile][n8 tile][frag]
    #pragma unroll
    for (int i = 0; i < 4; ++i)
        #pragma unroll
        for (int j = 0; j < 4; ++j)
            #pragma unroll
            for (int t = 0; t < 4; ++t) acc[i][j][t] = 0.f;

    #define ASW(s, idx) shw[(s) * 768 + (idx)]
    #define BSW(s, idx) shw[1536 + (s) * 3072 + (idx)]
    #define FM_LOAD(s, kbase)                                                        \
        {                                                                             \
            if (tid < 128) {                                                          \
                int m = tid >> 1, ch = tid & 1;                                       \
                cp16(&ASW(s, m * 12 + ch * 4),                                        \
                     g_emb_h + (size_t)(b0 + m) * DD + (kbase) + ch * 8);             \
            }                                                                         \
            _Pragma("unroll")                                                         \
            for (int i_ = 0; i_ < 2; ++i_) {                                          \
                int slot = tid + i_ * 256;                                            \
                int n = slot >> 1, ch = slot & 1;                                     \
                cp16(&BSW(s, n * 12 + ch * 4),                                        \
                     Wh + (size_t)n * DD + (kbase) + ch * 8);                         \
            }                                                                         \
            CP_COMMIT();                                                              \
        }

    // ---------------- Phase 1: f16 GEMM (k16 steps) ----------------
    FM_LOAD(0, 0);
    int s = 0;
    const int NT = DD / 16;   // 16
    for (int kt = 0; kt < NT; ++kt) {
        if (kt + 1 < NT) { FM_LOAD(s ^ 1, (kt + 1) * 16); CP_WAIT(1); }
        else             { CP_WAIT(0); }
        __syncthreads();

        uint32_t afr[4][4], bfr[4][2];
        #pragma unroll
        for (int i = 0; i < 4; ++i) {
            int m0 = i * 16;
            afr[i][0] = ASW(s, (m0 + g)     * 12 + tg);
            afr[i][1] = ASW(s, (m0 + g + 8) * 12 + tg);
            afr[i][2] = ASW(s, (m0 + g)     * 12 + tg + 4);
            afr[i][3] = ASW(s, (m0 + g + 8) * 12 + tg + 4);
        }
        #pragma unroll
        for (int j = 0; j < 4; ++j) {
            int n0 = wn + j * 8;
            bfr[j][0] = BSW(s, (n0 + g) * 12 + tg);
            bfr[j][1] = BSW(s, (n0 + g) * 12 + tg + 4);
        }
        #pragma unroll
        for (int i = 0; i < 4; ++i)
            #pragma unroll
            for (int j = 0; j < 4; ++j)
                mma_f16(acc[i][j], afr[i][0], afr[i][1], afr[i][2], afr[i][3],
                        bfr[j][0], bfr[j][1]);
        __syncthreads();
        s ^= 1;
    }
    // last iteration ended with __syncthreads() — safe to repurpose smem.

    // ---------------- Phase 2 tables ----------------
    {
        const float2* ptg2 = (const float2*)(g_proto_term + (size_t)c * KK * DD);
        #pragma unroll
        for (int i = 0; i < 8; ++i) {
            int idx = tid + i * 256;            // 0..2047
            float2 v = ptg2[idx];
            __half2 h = __floats2half2_rn(v.x, v.y);
            sh_pt_h2[idx] = h2u(h);
        }
        if (tid < DD) sh_w2[tid] = w2[c * DD + tid];
        if (tid < KK * KK) sh_G[(tid >> 4) * 17 + (tid & 15)] = g_G[c * 256 + tid];
        if (tid < KK) sh_inval[tid] = g_inval[c * KK + tid];
    }
    __syncthreads();

    // pack acc fragments to half2 once
    __half2 acch[4][4][2];
    #pragma unroll
    for (int i = 0; i < 4; ++i)
        #pragma unroll
        for (int j = 0; j < 4; ++j) {
            acch[i][j][0] = __floats2half2_rn(acc[i][j][0], acc[i][j][1]);
            acch[i][j][1] = __floats2half2_rn(acc[i][j][2], acc[i][j][3]);
        }

    // per-thread w2 pairs (B-fragments of 2nd-stage mma)
    uint32_t w2u[4];
    #pragma unroll
    for (int j = 0; j < 4; ++j) {
        float2 w = *(float2*)&sh_w2[wn + j * 8 + 2 * tg];
        w2u[j] = h2u(__floats2half2_rn(w.x, w.y));
    }

    float* my_slab = sh_scorew + warp * 1280;   // [64][20]
    const int ptbase = (wn >> 1) + tg;

    // ---------------- Phase 3: tanh + 2nd-stage mma scores ----------------
    #pragma unroll 1
    for (int k = 0; k < KK; ++k) {
        __half2 pth[4];
        #pragma unroll
        for (int j = 0; j < 4; ++j) {
            uint32_t w = sh_pt_h2[k * 128 + ptbase + j * 4];
            pth[j] = *reinterpret_cast<__half2*>(&w);
        }

        #pragma unroll
        for (int i = 0; i < 4; ++i) {
            uint32_t t00 = h2u(tanh_h2(__hadd2(acch[i][0][0], pth[0])));
            uint32_t t01 = h2u(tanh_h2(__hadd2(acch[i][0][1], pth[0])));
            uint32_t t10 = h2u(tanh_h2(__hadd2(acch[i][1][0], pth[1])));
            uint32_t t11 = h2u(tanh_h2(__hadd2(acch[i][1][1], pth[1])));
            uint32_t t20 = h2u(tanh_h2(__hadd2(acch[i][2][0], pth[2])));
            uint32_t t21 = h2u(tanh_h2(__hadd2(acch[i][2][1], pth[2])));
            uint32_t t30 = h2u(tanh_h2(__hadd2(acch[i][3][0], pth[3])));
            uint32_t t31 = h2u(tanh_h2(__hadd2(acch[i][3][1], pth[3])));

            float cfr[4] = {0.f, 0.f, 0.f, 0.f};
            mma_f16(cfr, t00, t01, t10, t11, w2u[0], w2u[1]);
            mma_f16(cfr, t20, t21, t30, t31, w2u[2], w2u[3]);

            if (tg == 0) {
                my_slab[(i * 16 + g) * 20 + k]     = cfr[0];
                my_slab[(i * 16 + g + 8) * 20 + k] = cfr[2];
            }
        }
    }
    __syncthreads();

    // ---------------- Phase 4: gather slabs + softmax + Gram distance -------
    if (tid < 64) {
        const int b = b0 + tid;
        const float b2v  = b2[c];
        const float temp = temperature[0];

        float s16[KK];
        #pragma unroll
        for (int k = 0; k < KK; ++k) s16[k] = b2v + sh_inval[k];
        #pragma unroll
        for (int w = 0; w < 8; ++w) {
            const float* p = sh_scorew + w * 1280 + tid * 20;
            float4 v0 = *(const float4*)(p + 0);
            float4 v1 = *(const float4*)(p + 4);
            float4 v2 = *(const float4*)(p + 8);
            float4 v3 = *(const float4*)(p + 12);
            s16[0] += v0.x;  s16[1] += v0.y;  s16[2] += v0.z;  s16[3] += v0.w;
            s16[4] += v1.x;  s16[5] += v1.y;  s16[6] += v1.z;  s16[7] += v1.w;
            s16[8] += v2.x;  s16[9] += v2.y;  s16[10] += v2.z; s16[11] += v2.w;
            s16[12] += v3.x; s16[13] += v3.y; s16[14] += v3.z; s16[15] += v3.w;
        }

        float m = s16[0];
        #pragma unroll
        for (int k = 1; k < KK; ++k) m = fmaxf(m, s16[k]);
        float sum = 0.f;
        #pragma unroll
        for (int k = 0; k < KK; ++k) {
            float e = __expf(s16[k] - m);
            s16[k] = e;
            sum += e;
        }
        float inv = 1.f / sum;
        #pragma unroll
        for (int k = 0; k < KK; ++k) s16[k] *= inv;

        // dist^2 = e2 - 2*attn·dotep + attn^T G attn
        float depv[KK];
        const float4* dep = (const float4*)(g_dotep + (size_t)b * (CC * KK) + c * KK);
        #pragma unroll
        for (int q = 0; q < 4; ++q) {
            float4 v = dep[q];
            depv[4 * q + 0] = v.x; depv[4 * q + 1] = v.y;
            depv[4 * q + 2] = v.z; depv[4 * q + 3] = v.w;
        }
        float dist2 = g_e2[b];
        #pragma unroll
        for (int k = 0; k < KK; ++k)
            dist2 = fmaf(-2.0f * s16[k], depv[k], dist2);
        #pragma unroll
        for (int k = 0; k < KK; ++k) {
            float t = 0.f;
            #pragma unroll
            for (int k2 = 0; k2 < KK; ++k2)
                t = fmaf(sh_G[k * 17 + k2], s16[k2], t);
            dist2 = fmaf(s16[k], t, dist2);
        }
        out[(size_t)b * CC + c] = -sqrtf(fmaxf(dist2, 0.f)) * temp;
    }
    #undef ASW
    #undef BSW
    #undef FM_LOAD
}

// ---------------------------------------------------------------------------
extern "C" void kernel_launch(void* const* d_in, const int* in_sizes, int n_in,
                              void* d_out, int out_size)
{
    const float* emb    = (const float*)d_in[0];   // [B,D]
    const float* protos = (const float*)d_in[1];   // [C,K,D]
    const float* W1     = (const float*)d_in[2];   // [C,2D,D]
    const float* b1     = (const float*)d_in[3];   // [C,D]
    const float* w2     = (const float*)d_in[4];   // [C,D]
    const float* b2     = (const float*)d_in[5];   // [C]
    const float* temp   = (const float*)d_in[6];   // [1]
    const void*  valid  = (const void*)d_in[7];    // [C,K] bool (storage dtype unknown)
    float* out = (float*)d_out;                    // [B,C]

    // dyn smem = max(GEMM phase 7680 words = 30720 B, epilogue 12832 fl = 51328 B)
    const int dyn = 12832 * 4;
    cudaFuncSetAttribute(fused_main, cudaFuncAttributeMaxDynamicSharedMemorySize, dyn);

    prologue_kernel<<<385, 256>>>(emb, protos, W1, b1, valid);
    fused_main<<<dim3(16, CC), 256, dyn>>>(w2, b2, temp, out);
}

// round 11
// speedup vs baseline: 1.3598x; 1.0334x over previous
#include <cuda_runtime.h>
#include <math_constants.h>
#include <cuda_fp16.h>
#include <cstdint>

// Problem constants
#define BB 1024   // batch
#define CC 32     // classes
#define KK 16     // prototypes per class
#define DD 256    // embedding dim
#define TWO_D 512

// Scratch (static device arrays — no allocation allowed)
__device__ float g_proto_term[CC * KK * DD];          // 512 KB
__device__ float g_dotep[(size_t)BB * CC * KK];       // 2 MB: emb·proto
__device__ float g_G[CC * KK * KK];                   // 32 KB: Gram
__device__ float g_e2[BB];                            // |emb|^2
__device__ float g_inval[CC * KK];                    // 0 = valid, -inf = invalid
__device__ __half g_emb_h[(size_t)BB * DD];           // 512 KB: emb as half
__device__ __half g_W1h[(size_t)CC * DD * DD];        // 4 MB: W1top^T as half [c][n][k]

__device__ __forceinline__ uint32_t f2tf(float f) {
    uint32_t r;
    asm("cvt.rna.tf32.f32 %0, %1;" : "=r"(r) : "f"(f));
    return r;
}
__device__ __forceinline__ __half2 tanh_h2(__half2 x) {
    uint32_t xi = *reinterpret_cast<uint32_t*>(&x);
    uint32_t r;
    asm("tanh.approx.f16x2 %0, %1;" : "=r"(r) : "r"(xi));
    return *reinterpret_cast<__half2*>(&r);
}
__device__ __forceinline__ uint32_t h2u(__half2 h) {
    return *reinterpret_cast<uint32_t*>(&h);
}
__device__ __forceinline__ void cp16(void* smem, const void* g) {
    uint32_t sa = (uint32_t)__cvta_generic_to_shared(smem);
    asm volatile("cp.async.cg.shared.global [%0], [%1], 16;" :: "r"(sa), "l"(g));
}
#define CP_COMMIT() asm volatile("cp.async.commit_group;")
#define CP_WAIT(N)  asm volatile("cp.async.wait_group %0;" :: "n"(N))

__device__ __forceinline__ void mma_tf32(float c_[4], const uint32_t a[4], const uint32_t b[2]) {
    asm volatile(
        "mma.sync.aligned.m16n8k8.row.col.f32.tf32.tf32.f32 "
        "{%0,%1,%2,%3}, {%4,%5,%6,%7}, {%8,%9}, {%0,%1,%2,%3};"
        : "+f"(c_[0]), "+f"(c_[1]), "+f"(c_[2]), "+f"(c_[3])
        : "r"(a[0]), "r"(a[1]), "r"(a[2]), "r"(a[3]), "r"(b[0]), "r"(b[1]));
}
// fp16 inputs, fp32 accumulate
__device__ __forceinline__ void mma_f16(float c_[4],
    uint32_t a0, uint32_t a1, uint32_t a2, uint32_t a3,
    uint32_t b0, uint32_t b1) {
    asm volatile(
        "mma.sync.aligned.m16n8k16.row.col.f32.f16.f16.f32 "
        "{%0,%1,%2,%3}, {%4,%5,%6,%7}, {%8,%9}, {%0,%1,%2,%3};"
        : "+f"(c_[0]), "+f"(c_[1]), "+f"(c_[2]), "+f"(c_[3])
        : "r"(a0), "r"(a1), "r"(a2), "r"(a3), "r"(b0), "r"(b1));
}

// ===========================================================================
// Kernel A (prologue, fused): blockIdx dispatch, 256 threads everywhere
//   [0,128)   : proto_term  (c = blk>>2, d-slice = (blk&3)*64), MLP-8 prefetch
//   [128,160) : Gram        (c = blk-128)
//   [160,192) : e2 + emb->half
//   192       : decode prototype_valid mask
//   [193,257) : dotep tf32 GEMM (64x128 tiles)
//   [257,385) : W1top transpose->half: g_W1h[c][n][k]
// ===========================================================================
__global__ __launch_bounds__(256) void prologue_kernel(
    const float* __restrict__ emb,      // [B,D]
    const float* __restrict__ protos,   // [C,K,D]
    const float* __restrict__ W1,       // [C,2D,D]
    const float* __restrict__ b1,       // [C,D]
    const void*  __restrict__ valid)
{
    __shared__ __align__(16) float sh[8192];   // 32 KB, reused per role
    const int blk = blockIdx.x;
    const int tid = threadIdx.x;

    if (blk < 128) {
        // ----- proto_term[c][k][d0+dl] = b1 + sum_e protos[c][k][e]*W1[c][D+e][d0+dl]
        const int c  = blk >> 2;
        const int d0 = (blk & 3) * 64;
        const int dl = tid & 63;
        const int eg = tid >> 6;

        float* p_s  = sh;               // [16][256]
        float* sred = sh + KK * DD;     // [4][16][64]

        const float* pg = protos + (size_t)c * KK * DD;
        #pragma unroll
        for (int i = 0; i < 16; ++i) p_s[tid + i * 256] = pg[tid + i * 256];
        __syncthreads();

        float acc[KK];
        #pragma unroll
        for (int k = 0; k < KK; ++k) acc[k] = 0.f;

        const float* Wb = W1 + ((size_t)c * TWO_D + DD + eg * 64) * DD + d0 + dl;
        for (int e0 = 0; e0 < 64; e0 += 8) {
            float w[8];
            #pragma unroll
            for (int u = 0; u < 8; ++u) w[u] = Wb[(size_t)(e0 + u) * DD];
            #pragma unroll
            for (int u = 0; u < 8; ++u) {
                const float* pe = p_s + eg * 64 + e0 + u;
                #pragma unroll
                for (int k = 0; k < KK; ++k)
                    acc[k] = fmaf(pe[k * DD], w[u], acc[k]);
            }
        }

        #pragma unroll
        for (int k = 0; k < KK; ++k)
            sred[(eg * KK + k) * 64 + dl] = acc[k];
        __syncthreads();

        #pragma unroll
        for (int r = 0; r < 4; ++r) {
            int idx = tid + r * 256;
            int k = idx >> 6, d = idx & 63;
            float s = sred[(0 * KK + k) * 64 + d] + sred[(1 * KK + k) * 64 + d]
                    + sred[(2 * KK + k) * 64 + d] + sred[(3 * KK + k) * 64 + d];
            g_proto_term[((c * KK) + k) * DD + d0 + d] = s + b1[c * DD + d0 + d];
        }

    } else if (blk < 160) {
        // ----- Gram G[c][k][k2]
        const int c = blk - 128;
        float* p_s = sh;   // [16][257]
        for (int i = tid; i < KK * DD; i += 256) {
            int k = i / DD, d = i % DD;
            p_s[k * (DD + 1) + d] = protos[(size_t)c * KK * DD + i];
        }
        __syncthreads();
        const int k = tid >> 4, k2 = tid & 15;
        float s = 0.f;
        #pragma unroll 4
        for (int d = 0; d < DD; ++d)
            s = fmaf(p_s[k * (DD + 1) + d], p_s[k2 * (DD + 1) + d], s);
        g_G[c * 256 + tid] = s;

    } else if (blk < 192) {
        // ----- e2 + emb->half: warp-per-row, 4 rows per warp
        const int warp = tid >> 5, lane = tid & 31;
        const int base = (blk - 160) * 32 + warp * 4;
        #pragma unroll
        for (int t = 0; t < 4; ++t) {
            const int b = base + t;
            const float4* p = (const float4*)(emb + (size_t)b * DD);
            float4 v0 = p[lane], v1 = p[lane + 32];
            uint2* eh = (uint2*)(g_emb_h + (size_t)b * DD);
            uint2 w0, w1;
            w0.x = h2u(__floats2half2_rn(v0.x, v0.y));
            w0.y = h2u(__floats2half2_rn(v0.z, v0.w));
            w1.x = h2u(__floats2half2_rn(v1.x, v1.y));
            w1.y = h2u(__floats2half2_rn(v1.z, v1.w));
            eh[lane]      = w0;
            eh[lane + 32] = w1;
            float s = v0.x*v0.x + v0.y*v0.y + v0.z*v0.z + v0.w*v0.w
                    + v1.x*v1.x + v1.y*v1.y + v1.z*v1.z + v1.w*v1.w;
            #pragma unroll
            for (int off = 16; off > 0; off >>= 1)
                s += __shfl_xor_sync(0xFFFFFFFFu, s, off);
            if (lane == 0) g_e2[b] = s;
        }

    } else if (blk == 192) {
        // ----- decode prototype_valid (dtype-sniffing)
        __shared__ int s_hasF, s_hasHi, s_mode;
        if (tid == 0) { s_hasF = 0; s_hasHi = 0; }
        __syncthreads();
        if (tid < 128) {
            unsigned v = ((const unsigned*)valid)[tid];
            if (v == 0x3F800000u)                        atomicOr(&s_hasF, 1);
            else if (v != 0u && (v & 0xFFFFFF00u) != 0u) atomicOr(&s_hasHi, 1);
        }
        __syncthreads();
        if (tid == 0) s_mode = s_hasF ? 0 : (s_hasHi ? 2 : 1);
        __syncthreads();
        const int mode = s_mode;
        for (int i = tid; i < CC * KK; i += 256) {
            bool v;
            if (mode == 0)      v = ((const float*)valid)[i] != 0.0f;
            else if (mode == 1) v = ((const int*)valid)[i] != 0;
            else                v = ((const unsigned char*)valid)[i] != 0;
            g_inval[i] = v ? 0.0f : -CUDART_INF_F;
        }

    } else if (blk < 257) {
        // ----- dotep[b][ck] = emb[b,:]·proto[ck,:]  (tf32 mma)
        const int b    = blk - 193;              // 0..63
        const int bm0  = (b >> 2) * 64;
        const int bn0  = (b & 3) * 128;

        #define DAS(s, m, k) sh[(s) * 1280 + (m) * 20 + (k)]
        #define DPS(s, n, k) sh[2560 + (s) * 2560 + (n) * 20 + (k)]

        const int warp = tid >> 5, lane = tid & 31;
        const int wm = (warp >> 2) * 32;
        const int wn = (warp & 3) * 32;
        const int g  = lane >> 2, tg = lane & 3;

        float acc[2][4][4];
        #pragma unroll
        for (int i = 0; i < 2; ++i)
            #pragma unroll
            for (int j = 0; j < 4; ++j)
                #pragma unroll
                for (int t = 0; t < 4; ++t) acc[i][j][t] = 0.f;

        #define DE_LOAD(s, kbase)                                                         \
            {                                                                              \
                { int m = tid >> 2, k4 = (tid & 3) << 2;                                   \
                  cp16(&DAS(s, m, k4), emb + (size_t)(bm0 + m) * DD + (kbase) + k4); }     \
                _Pragma("unroll")                                                          \
                for (int i_ = 0; i_ < 2; ++i_) {                                           \
                    int slot = tid + i_ * 256;                                             \
                    int n = slot >> 2, k4 = (slot & 3) << 2;                               \
                    cp16(&DPS(s, n, k4), protos + (size_t)(bn0 + n) * DD + (kbase) + k4);  \
                }                                                                          \
                CP_COMMIT();                                                               \
            }

        DE_LOAD(0, 0);
        int s = 0;
        const int NT = DD / 16;
        for (int kt = 0; kt < NT; ++kt) {
            if (kt + 1 < NT) { DE_LOAD(s ^ 1, (kt + 1) * 16); CP_WAIT(1); }
            else             { CP_WAIT(0); }
            __syncthreads();

            #pragma unroll
            for (int ks = 0; ks < 2; ++ks) {
                const int kb = ks * 8;
                uint32_t afr[2][4], bfr[4][2];
                #pragma unroll
                for (int i = 0; i < 2; ++i) {
                    int m0 = wm + i * 16;
                    afr[i][0] = f2tf(DAS(s, m0 + g,     kb + tg));
                    afr[i][1] = f2tf(DAS(s, m0 + g + 8, kb + tg));
                    afr[i][2] = f2tf(DAS(s, m0 + g,     kb + tg + 4));
                    afr[i][3] = f2tf(DAS(s, m0 + g + 8, kb + tg + 4));
                }
                #pragma unroll
                for (int j = 0; j < 4; ++j) {
                    int n0 = wn + j * 8;
                    bfr[j][0] = f2tf(DPS(s, n0 + g, kb + tg));
                    bfr[j][1] = f2tf(DPS(s, n0 + g, kb + tg + 4));
                }
                #pragma unroll
                for (int i = 0; i < 2; ++i)
                    #pragma unroll
                    for (int j = 0; j < 4; ++j)
                        mma_tf32(acc[i][j], afr[i], bfr[j]);
            }
            __syncthreads();
            s ^= 1;
        }

        #pragma unroll
        for (int i = 0; i < 2; ++i) {
            int r0 = bm0 + wm + i * 16 + g;
            #pragma unroll
            for (int j = 0; j < 4; ++j) {
                int col = bn0 + wn + j * 8 + 2 * tg;
                *(float2*)(g_dotep + (size_t)r0 * (CC * KK) + col)       = make_float2(acc[i][j][0], acc[i][j][1]);
                *(float2*)(g_dotep + (size_t)(r0 + 8) * (CC * KK) + col) = make_float2(acc[i][j][2], acc[i][j][3]);
            }
        }
        #undef DE_LOAD
        #undef DAS
        #undef DPS

    } else {
        // ----- W1top -> g_W1h[c][n][k] (transpose + half convert)
        const int idx = blk - 257;           // 0..127
        const int c  = idx >> 2;
        const int tj = idx & 3;              // 64-wide n slice
        float* ts = sh;                      // [64][65]
        const float* Wt = W1 + (size_t)c * TWO_D * DD;   // top half [256 k][256 n]
        __half* outc = g_W1h + (size_t)c * DD * DD;

        for (int ti = 0; ti < 4; ++ti) {
            {
                int r = tid >> 2, cg = (tid & 3) * 16;
                const float* src = Wt + (size_t)(ti * 64 + r) * DD + tj * 64 + cg;
                #pragma unroll
                for (int u = 0; u < 4; ++u) {
                    float4 v = *(const float4*)(src + u * 4);
                    ts[r * 65 + cg + u * 4 + 0] = v.x;
                    ts[r * 65 + cg + u * 4 + 1] = v.y;
                    ts[r * 65 + cg + u * 4 + 2] = v.z;
                    ts[r * 65 + cg + u * 4 + 3] = v.w;
                }
            }
            __syncthreads();
            {
                int nn = tid >> 2, kg = (tid & 3) * 16;
                uint32_t* dst = (uint32_t*)(outc + (size_t)(tj * 64 + nn) * DD + ti * 64 + kg);
                #pragma unroll
                for (int u = 0; u < 8; ++u) {
                    __half2 h = __floats2half2_rn(ts[(kg + 2 * u) * 65 + nn],
                                                  ts[(kg + 2 * u + 1) * 65 + nn]);
                    dst[u] = h2u(h);
                }
            }
            __syncthreads();
        }
    }
}

// ===========================================================================
// Kernel B (main, fused): per (64-batch-tile, class):
//   1. qW tile [64 x 256] = emb_h @ W1h  — f16 mma, BK=32, 3-stage cp.async,
//      ONE __syncthreads per iteration (8 total vs 32)
//   2. epilogue: tanh f16x2 + 2nd-stage f16 mma scores, pt prefetch pipeline
//   3. softmax over K, dist via Gram trick, write out
// grid (16, 32), 256 threads (8 warps, n-sliced: warp tile 64x32), 2 CTAs/SM.
// ===========================================================================
__global__ __launch_bounds__(256, 2) void fused_main(
    const float* __restrict__ w2, const float* __restrict__ b2,
    const float* __restrict__ temperature, float* __restrict__ out)
{
    extern __shared__ float sh[];
    uint32_t* shw = (uint32_t*)sh;
    // phase-1 (half, padded rows of 20 words = 40 halfs for BK=32):
    //   AsW: [3][64][20]  words 0..3839
    //   BsW: [3][256][20] words 3840..19199          (76.8 KB total)
    // phase-2 layout (aliases phase-1 region)
    uint32_t* sh_pt_h2 = (uint32_t*)sh;        // [16][128] half2 = 2048 words
    float* sh_scorew = sh + 2048;              // [8 warps][64 rows][20] = 10240
    float* sh_w2    = sh + 2048 + 10240;       // 256
    float* sh_G     = sh_w2 + 256;             // [16][17] = 272
    float* sh_inval = sh_G + 272;              // 16

    const int c  = blockIdx.y;
    const int b0 = blockIdx.x * 64;
    const __half* Wh = g_W1h + (size_t)c * DD * DD;   // [n][k] half

    const int tid  = threadIdx.x;
    const int warp = tid >> 5, lane = tid & 31;
    const int wn = warp * 32;            // warp n-slice (all 64 rows)
    const int g  = lane >> 2, tg = lane & 3;

    float acc[4][4][4];                  // [m16 tile][n8 tile][frag]
    #pragma unroll
    for (int i = 0; i < 4; ++i)
        #pragma unroll
        for (int j = 0; j < 4; ++j)
            #pragma unroll
            for (int t = 0; t < 4; ++t) acc[i][j][t] = 0.f;

    #define ASW(s, idx) shw[(s) * 1280 + (idx)]
    #define BSW(s, idx) shw[3840 + (s) * 5120 + (idx)]
    // BK=32 halfs = 64B = 4 x 16B chunks per row
    #define FM_LOAD(s, kbase)                                                  \
        {                                                                       \
            { int r = tid >> 2, ch = tid & 3;                                   \
              cp16(&ASW(s, r * 20 + ch * 4),                                    \
                   g_emb_h + (size_t)(b0 + r) * DD + (kbase) + ch * 8); }       \
            _Pragma("unroll")                                                   \
            for (int i_ = 0; i_ < 4; ++i_) {                                    \
                int slot = tid + i_ * 256;                                      \
                int r = slot >> 2, ch = slot & 3;                               \
                cp16(&BSW(s, r * 20 + ch * 4),                                  \
                     Wh + (size_t)r * DD + (kbase) + ch * 8);                   \
            }                                                                   \
            CP_COMMIT();                                                        \
        }

    // ---------------- Phase 1: f16 GEMM, 3-stage, 1 sync/iter ----------------
    FM_LOAD(0, 0);
    FM_LOAD(1, 32);
    const int NT = DD / 32;   // 8
    #pragma unroll 1
    for (int kt = 0; kt < NT; ++kt) {
        const int cs = kt % 3;
        if (kt < NT - 1) { CP_WAIT(1); } else { CP_WAIT(0); }
        __syncthreads();   // stage cs data visible to all; stage (kt+2)%3 free
        if (kt + 2 < NT) FM_LOAD((kt + 2) % 3, (kt + 2) * 32);

        #pragma unroll
        for (int ks = 0; ks < 2; ++ks) {
            const int kb = ks * 8;   // word offset within the 20-word row
            uint32_t afr[4][4], bfr[4][2];
            #pragma unroll
            for (int i = 0; i < 4; ++i) {
                int m0 = i * 16;
                afr[i][0] = ASW(cs, (m0 + g)     * 20 + kb + tg);
                afr[i][1] = ASW(cs, (m0 + g + 8) * 20 + kb + tg);
                afr[i][2] = ASW(cs, (m0 + g)     * 20 + kb + tg + 4);
                afr[i][3] = ASW(cs, (m0 + g + 8) * 20 + kb + tg + 4);
            }
            #pragma unroll
            for (int j = 0; j < 4; ++j) {
                int n0 = wn + j * 8;
                bfr[j][0] = BSW(cs, (n0 + g) * 20 + kb + tg);
                bfr[j][1] = BSW(cs, (n0 + g) * 20 + kb + tg + 4);
            }
            #pragma unroll
            for (int i = 0; i < 4; ++i)
                #pragma unroll
                for (int j = 0; j < 4; ++j)
                    mma_f16(acc[i][j], afr[i][0], afr[i][1], afr[i][2], afr[i][3],
                            bfr[j][0], bfr[j][1]);
        }
    }
    __syncthreads();   // all warps done with GEMM smem before repurposing

    // ---------------- Phase 2 tables ----------------
    {
        const float2* ptg2 = (const float2*)(g_proto_term + (size_t)c * KK * DD);
        #pragma unroll
        for (int i = 0; i < 8; ++i) {
            int idx = tid + i * 256;            // 0..2047
            float2 v = ptg2[idx];
            __half2 h = __floats2half2_rn(v.x, v.y);
            sh_pt_h2[idx] = h2u(h);
        }
        if (tid < DD) sh_w2[tid] = w2[c * DD + tid];
        if (tid < KK * KK) sh_G[(tid >> 4) * 17 + (tid & 15)] = g_G[c * 256 + tid];
        if (tid < KK) sh_inval[tid] = g_inval[c * KK + tid];
    }
    __syncthreads();

    // pack acc fragments to half2 once
    __half2 acch[4][4][2];
    #pragma unroll
    for (int i = 0; i < 4; ++i)
        #pragma unroll
        for (int j = 0; j < 4; ++j) {
            acch[i][j][0] = __floats2half2_rn(acc[i][j][0], acc[i][j][1]);
            acch[i][j][1] = __floats2half2_rn(acc[i][j][2], acc[i][j][3]);
        }

    // per-thread w2 pairs (B-fragments of 2nd-stage mma)
    uint32_t w2u[4];
    #pragma unroll
    for (int j = 0; j < 4; ++j) {
        float2 w = *(float2*)&sh_w2[wn + j * 8 + 2 * tg];
        w2u[j] = h2u(__floats2half2_rn(w.x, w.y));
    }

    float* my_slab = sh_scorew + warp * 1280;   // [64][20]
    const int ptbase = (wn >> 1) + tg;

    // ---------------- Phase 3: tanh + 2nd-stage mma (pt prefetch) ----------
    uint32_t pw_cur[4];
    #pragma unroll
    for (int j = 0; j < 4; ++j) pw_cur[j] = sh_pt_h2[ptbase + j * 4];

    #pragma unroll 1
    for (int k = 0; k < KK; ++k) {
        uint32_t pw_nxt[4];
        if (k + 1 < KK) {
            #pragma unroll
            for (int j = 0; j < 4; ++j)
                pw_nxt[j] = sh_pt_h2[(k + 1) * 128 + ptbase + j * 4];
        }
        __half2 pth[4];
        #pragma unroll
        for (int j = 0; j < 4; ++j) pth[j] = *reinterpret_cast<__half2*>(&pw_cur[j]);

        #pragma unroll
        for (int i = 0; i < 4; ++i) {
            uint32_t t00 = h2u(tanh_h2(__hadd2(acch[i][0][0], pth[0])));
            uint32_t t01 = h2u(tanh_h2(__hadd2(acch[i][0][1], pth[0])));
            uint32_t t10 = h2u(tanh_h2(__hadd2(acch[i][1][0], pth[1])));
            uint32_t t11 = h2u(tanh_h2(__hadd2(acch[i][1][1], pth[1])));
            uint32_t t20 = h2u(tanh_h2(__hadd2(acch[i][2][0], pth[2])));
            uint32_t t21 = h2u(tanh_h2(__hadd2(acch[i][2][1], pth[2])));
            uint32_t t30 = h2u(tanh_h2(__hadd2(acch[i][3][0], pth[3])));
            uint32_t t31 = h2u(tanh_h2(__hadd2(acch[i][3][1], pth[3])));

            float cfr[4] = {0.f, 0.f, 0.f, 0.f};
            mma_f16(cfr, t00, t01, t10, t11, w2u[0], w2u[1]);
            mma_f16(cfr, t20, t21, t30, t31, w2u[2], w2u[3]);

            if (tg == 0) {
                my_slab[(i * 16 + g) * 20 + k]     = cfr[0];
                my_slab[(i * 16 + g + 8) * 20 + k] = cfr[2];
            }
        }
        #pragma unroll
        for (int j = 0; j < 4; ++j) pw_cur[j] = pw_nxt[j];
    }
    __syncthreads();

    // ---------------- Phase 4: gather slabs + softmax + Gram distance -------
    if (tid < 64) {
        const int b = b0 + tid;
        const float b2v  = b2[c];
        const float temp = temperature[0];

        float s16[KK];
        #pragma unroll
        for (int k = 0; k < KK; ++k) s16[k] = b2v + sh_inval[k];
        #pragma unroll
        for (int w = 0; w < 8; ++w) {
            const float* p = sh_scorew + w * 1280 + tid * 20;
            float4 v0 = *(const float4*)(p + 0);
            float4 v1 = *(const float4*)(p + 4);
            float4 v2 = *(const float4*)(p + 8);
            float4 v3 = *(const float4*)(p + 12);
            s16[0] += v0.x;  s16[1] += v0.y;  s16[2] += v0.z;  s16[3] += v0.w;
            s16[4] += v1.x;  s16[5] += v1.y;  s16[6] += v1.z;  s16[7] += v1.w;
            s16[8] += v2.x;  s16[9] += v2.y;  s16[10] += v2.z; s16[11] += v2.w;
            s16[12] += v3.x; s16[13] += v3.y; s16[14] += v3.z; s16[15] += v3.w;
        }

        float m = s16[0];
        #pragma unroll
        for (int k = 1; k < KK; ++k) m = fmaxf(m, s16[k]);
        float sum = 0.f;
        #pragma unroll
        for (int k = 0; k < KK; ++k) {
            float e = __expf(s16[k] - m);
            s16[k] = e;
            sum += e;
        }
        float inv = 1.f / sum;
        #pragma unroll
        for (int k = 0; k < KK; ++k) s16[k] *= inv;

        // dist^2 = e2 - 2*attn·dotep + attn^T G attn
        float depv[KK];
        const float4* dep = (const float4*)(g_dotep + (size_t)b * (CC * KK) + c * KK);
        #pragma unroll
        for (int q = 0; q < 4; ++q) {
            float4 v = dep[q];
            depv[4 * q + 0] = v.x; depv[4 * q + 1] = v.y;
            depv[4 * q + 2] = v.z; depv[4 * q + 3] = v.w;
        }
        float dist2 = g_e2[b];
        #pragma unroll
        for (int k = 0; k < KK; ++k)
            dist2 = fmaf(-2.0f * s16[k], depv[k], dist2);
        #pragma unroll
        for (int k = 0; k < KK; ++k) {
            float t = 0.f;
            #pragma unroll
            for (int k2 = 0; k2 < KK; ++k2)
                t = fmaf(sh_G[k * 17 + k2], s16[k2], t);
            dist2 = fmaf(s16[k], t, dist2);
        }
        out[(size_t)b * CC + c] = -sqrtf(fmaxf(dist2, 0.f)) * temp;
    }
    #undef ASW
    #undef BSW
    #undef FM_LOAD
}

// ---------------------------------------------------------------------------
extern "C" void kernel_launch(void* const* d_in, const int* in_sizes, int n_in,
                              void* d_out, int out_size)
{
    const float* emb    = (const float*)d_in[0];   // [B,D]
    const float* protos = (const float*)d_in[1];   // [C,K,D]
    const float* W1     = (const float*)d_in[2];   // [C,2D,D]
    const float* b1     = (const float*)d_in[3];   // [C,D]
    const float* w2     = (const float*)d_in[4];   // [C,D]
    const float* b2     = (const float*)d_in[5];   // [C]
    const float* temp   = (const float*)d_in[6];   // [1]
    const void*  valid  = (const void*)d_in[7];    // [C,K] bool (storage dtype unknown)
    float* out = (float*)d_out;                    // [B,C]

    // dyn smem = GEMM phase 19200 words = 76800 B (epilogue fits inside: 51328 B)
    const int dyn = 19200 * 4;
    cudaFuncSetAttribute(fused_main, cudaFuncAttributeMaxDynamicSharedMemorySize, dyn);

    prologue_kernel<<<385, 256>>>(emb, protos, W1, b1, valid);
    fused_main<<<dim3(16, CC), 256, dyn>>>(w2, b2, temp, out);
}

// round 13
// speedup vs baseline: 1.3777x; 1.0132x over previous
#include <cuda_runtime.h>
#include <math_constants.h>
#include <cuda_fp16.h>
#include <cstdint>

// Problem constants
#define BB 1024   // batch
#define CC 32     // classes
#define KK 16     // prototypes per class
#define DD 256    // embedding dim
#define TWO_D 512

// Scratch (static device arrays — no allocation allowed)
__device__ float g_proto_term[CC * KK * DD];          // 512 KB
__device__ float g_dotep[(size_t)BB * CC * KK];       // 2 MB: emb·proto
__device__ float g_G[CC * KK * KK];                   // 32 KB: Gram
__device__ float g_e2[BB];                            // |emb|^2
__device__ float g_inval[CC * KK];                    // 0 = valid, -inf = invalid
__device__ __half g_emb_h[(size_t)BB * DD];           // 512 KB: emb as half
__device__ __half g_W1h[(size_t)CC * DD * DD];        // 4 MB: W1top^T as half [c][n][k]

__device__ __forceinline__ uint32_t f2tf(float f) {
    uint32_t r;
    asm("cvt.rna.tf32.f32 %0, %1;" : "=r"(r) : "f"(f));
    return r;
}
__device__ __forceinline__ __half2 tanh_h2(__half2 x) {
    uint32_t xi = *reinterpret_cast<uint32_t*>(&x);
    uint32_t r;
    asm("tanh.approx.f16x2 %0, %1;" : "=r"(r) : "r"(xi));
    return *reinterpret_cast<__half2*>(&r);
}
__device__ __forceinline__ uint32_t h2u(__half2 h) {
    return *reinterpret_cast<uint32_t*>(&h);
}
__device__ __forceinline__ void cp16(void* smem, const void* g) {
    uint32_t sa = (uint32_t)__cvta_generic_to_shared(smem);
    asm volatile("cp.async.cg.shared.global [%0], [%1], 16;" :: "r"(sa), "l"(g));
}
#define CP_COMMIT() asm volatile("cp.async.commit_group;")
#define CP_WAIT(N)  asm volatile("cp.async.wait_group %0;" :: "n"(N))

__device__ __forceinline__ void mma_tf32(float c_[4], const uint32_t a[4], const uint32_t b[2]) {
    asm volatile(
        "mma.sync.aligned.m16n8k8.row.col.f32.tf32.tf32.f32 "
        "{%0,%1,%2,%3}, {%4,%5,%6,%7}, {%8,%9}, {%0,%1,%2,%3};"
        : "+f"(c_[0]), "+f"(c_[1]), "+f"(c_[2]), "+f"(c_[3])
        : "r"(a[0]), "r"(a[1]), "r"(a[2]), "r"(a[3]), "r"(b[0]), "r"(b[1]));
}
// fp16 inputs, fp32 accumulate (used by 2nd-stage score mma)
__device__ __forceinline__ void mma_f16(float c_[4],
    uint32_t a0, uint32_t a1, uint32_t a2, uint32_t a3,
    uint32_t b0, uint32_t b1) {
    asm volatile(
        "mma.sync.aligned.m16n8k16.row.col.f32.f16.f16.f32 "
        "{%0,%1,%2,%3}, {%4,%5,%6,%7}, {%8,%9}, {%0,%1,%2,%3};"
        : "+f"(c_[0]), "+f"(c_[1]), "+f"(c_[2]), "+f"(c_[3])
        : "r"(a0), "r"(a1), "r"(a2), "r"(a3), "r"(b0), "r"(b1));
}
// fp16 inputs, fp16 accumulate (GEMM phase — C/D = 2 regs)
__device__ __forceinline__ void mma_f16_hacc(uint32_t c_[2],
    uint32_t a0, uint32_t a1, uint32_t a2, uint32_t a3,
    uint32_t b0, uint32_t b1) {
    asm volatile(
        "mma.sync.aligned.m16n8k16.row.col.f16.f16.f16.f16 "
        "{%0,%1}, {%2,%3,%4,%5}, {%6,%7}, {%0,%1};"
        : "+r"(c_[0]), "+r"(c_[1])
        : "r"(a0), "r"(a1), "r"(a2), "r"(a3), "r"(b0), "r"(b1));
}

// ===========================================================================
// Kernel A (prologue, fused): blockIdx dispatch, 256 threads everywhere
//   [0,128)   : proto_term  (c = blk>>2, d-slice = (blk&3)*64), MLP-8 prefetch
//   [128,160) : Gram        (c = blk-128)
//   [160,192) : e2 + emb->half
//   192       : decode prototype_valid mask
//   [193,257) : dotep tf32 GEMM (64x128 tiles)
//   [257,385) : W1top transpose->half: g_W1h[c][n][k]
// ===========================================================================
__global__ __launch_bounds__(256) void prologue_kernel(
    const float* __restrict__ emb,      // [B,D]
    const float* __restrict__ protos,   // [C,K,D]
    const float* __restrict__ W1,       // [C,2D,D]
    const float* __restrict__ b1,       // [C,D]
    const void*  __restrict__ valid)
{
    __shared__ __align__(16) float sh[8192];   // 32 KB, reused per role
    const int blk = blockIdx.x;
    const int tid = threadIdx.x;

    if (blk < 128) {
        // ----- proto_term[c][k][d0+dl] = b1 + sum_e protos[c][k][e]*W1[c][D+e][d0+dl]
        const int c  = blk >> 2;
        const int d0 = (blk & 3) * 64;
        const int dl = tid & 63;
        const int eg = tid >> 6;

        float* p_s  = sh;               // [16][256]
        float* sred = sh + KK * DD;     // [4][16][64]

        const float* pg = protos + (size_t)c * KK * DD;
        #pragma unroll
        for (int i = 0; i < 16; ++i) p_s[tid + i * 256] = pg[tid + i * 256];
        __syncthreads();

        float acc[KK];
        #pragma unroll
        for (int k = 0; k < KK; ++k) acc[k] = 0.f;

        const float* Wb = W1 + ((size_t)c * TWO_D + DD + eg * 64) * DD + d0 + dl;
        for (int e0 = 0; e0 < 64; e0 += 8) {
            float w[8];
            #pragma unroll
            for (int u = 0; u < 8; ++u) w[u] = Wb[(size_t)(e0 + u) * DD];
            #pragma unroll
            for (int u = 0; u < 8; ++u) {
                const float* pe = p_s + eg * 64 + e0 + u;
                #pragma unroll
                for (int k = 0; k < KK; ++k)
                    acc[k] = fmaf(pe[k * DD], w[u], acc[k]);
            }
        }

        #pragma unroll
        for (int k = 0; k < KK; ++k)
            sred[(eg * KK + k) * 64 + dl] = acc[k];
        __syncthreads();

        #pragma unroll
        for (int r = 0; r < 4; ++r) {
            int idx = tid + r * 256;
            int k = idx >> 6, d = idx & 63;
            float s = sred[(0 * KK + k) * 64 + d] + sred[(1 * KK + k) * 64 + d]
                    + sred[(2 * KK + k) * 64 + d] + sred[(3 * KK + k) * 64 + d];
            g_proto_term[((c * KK) + k) * DD + d0 + d] = s + b1[c * DD + d0 + d];
        }

    } else if (blk < 160) {
        // ----- Gram G[c][k][k2]
        const int c = blk - 128;
        float* p_s = sh;   // [16][257]
        for (int i = tid; i < KK * DD; i += 256) {
            int k = i / DD, d = i % DD;
            p_s[k * (DD + 1) + d] = protos[(size_t)c * KK * DD + i];
        }
        __syncthreads();
        const int k = tid >> 4, k2 = tid & 15;
        float s = 0.f;
        #pragma unroll 4
        for (int d = 0; d < DD; ++d)
            s = fmaf(p_s[k * (DD + 1) + d], p_s[k2 * (DD + 1) + d], s);
        g_G[c * 256 + tid] = s;

    } else if (blk < 192) {
        // ----- e2 + emb->half: warp-per-row, 4 rows per warp
        const int warp = tid >> 5, lane = tid & 31;
        const int base = (blk - 160) * 32 + warp * 4;
        #pragma unroll
        for (int t = 0; t < 4; ++t) {
            const int b = base + t;
            const float4* p = (const float4*)(emb + (size_t)b * DD);
            float4 v0 = p[lane], v1 = p[lane + 32];
            uint2* eh = (uint2*)(g_emb_h + (size_t)b * DD);
            uint2 w0, w1;
            w0.x = h2u(__floats2half2_rn(v0.x, v0.y));
            w0.y = h2u(__floats2half2_rn(v0.z, v0.w));
            w1.x = h2u(__floats2half2_rn(v1.x, v1.y));
            w1.y = h2u(__floats2half2_rn(v1.z, v1.w));
            eh[lane]      = w0;
            eh[lane + 32] = w1;
            float s = v0.x*v0.x + v0.y*v0.y + v0.z*v0.z + v0.w*v0.w
                    + v1.x*v1.x + v1.y*v1.y + v1.z*v1.z + v1.w*v1.w;
            #pragma unroll
            for (int off = 16; off > 0; off >>= 1)
                s += __shfl_xor_sync(0xFFFFFFFFu, s, off);
            if (lane == 0) g_e2[b] = s;
        }

    } else if (blk == 192) {
        // ----- decode prototype_valid (dtype-sniffing)
        __shared__ int s_hasF, s_hasHi, s_mode;
        if (tid == 0) { s_hasF = 0; s_hasHi = 0; }
        __syncthreads();
        if (tid < 128) {
            unsigned v = ((const unsigned*)valid)[tid];
            if (v == 0x3F800000u)                        atomicOr(&s_hasF, 1);
            else if (v != 0u && (v & 0xFFFFFF00u) != 0u) atomicOr(&s_hasHi, 1);
        }
        __syncthreads();
        if (tid == 0) s_mode = s_hasF ? 0 : (s_hasHi ? 2 : 1);
        __syncthreads();
        const int mode = s_mode;
        for (int i = tid; i < CC * KK; i += 256) {
            bool v;
            if (mode == 0)      v = ((const float*)valid)[i] != 0.0f;
            else if (mode == 1) v = ((const int*)valid)[i] != 0;
            else                v = ((const unsigned char*)valid)[i] != 0;
            g_inval[i] = v ? 0.0f : -CUDART_INF_F;
        }

    } else if (blk < 257) {
        // ----- dotep[b][ck] = emb[b,:]·proto[ck,:]  (tf32 mma)
        const int b    = blk - 193;              // 0..63
        const int bm0  = (b >> 2) * 64;
        const int bn0  = (b & 3) * 128;

        #define DAS(s, m, k) sh[(s) * 1280 + (m) * 20 + (k)]
        #define DPS(s, n, k) sh[2560 + (s) * 2560 + (n) * 20 + (k)]

        const int warp = tid >> 5, lane = tid & 31;
        const int wm = (warp >> 2) * 32;
        const int wn = (warp & 3) * 32;
        const int g  = lane >> 2, tg = lane & 3;

        float acc[2][4][4];
        #pragma unroll
        for (int i = 0; i < 2; ++i)
            #pragma unroll
            for (int j = 0; j < 4; ++j)
                #pragma unroll
                for (int t = 0; t < 4; ++t) acc[i][j][t] = 0.f;

        #define DE_LOAD(s, kbase)                                                         \
            {                                                                              \
                { int m = tid >> 2, k4 = (tid & 3) << 2;                                   \
                  cp16(&DAS(s, m, k4), emb + (size_t)(bm0 + m) * DD + (kbase) + k4); }     \
                _Pragma("unroll")                                                          \
                for (int i_ = 0; i_ < 2; ++i_) {                                           \
                    int slot = tid + i_ * 256;                                             \
                    int n = slot >> 2, k4 = (slot & 3) << 2;                               \
                    cp16(&DPS(s, n, k4), protos + (size_t)(bn0 + n) * DD + (kbase) + k4);  \
                }                                                                          \
                CP_COMMIT();                                                               \
            }

        DE_LOAD(0, 0);
        int s = 0;
        const int NT = DD / 16;
        for (int kt = 0; kt < NT; ++kt) {
            if (kt + 1 < NT) { DE_LOAD(s ^ 1, (kt + 1) * 16); CP_WAIT(1); }
            else             { CP_WAIT(0); }
            __syncthreads();

            #pragma unroll
            for (int ks = 0; ks < 2; ++ks) {
                const int kb = ks * 8;
                uint32_t afr[2][4], bfr[4][2];
                #pragma unroll
                for (int i = 0; i < 2; ++i) {
                    int m0 = wm + i * 16;
                    afr[i][0] = f2tf(DAS(s, m0 + g,     kb + tg));
                    afr[i][1] = f2tf(DAS(s, m0 + g + 8, kb + tg));
                    afr[i][2] = f2tf(DAS(s, m0 + g,     kb + tg + 4));
                    afr[i][3] = f2tf(DAS(s, m0 + g + 8, kb + tg + 4));
                }
                #pragma unroll
                for (int j = 0; j < 4; ++j) {
                    int n0 = wn + j * 8;
                    bfr[j][0] = f2tf(DPS(s, n0 + g, kb + tg));
                    bfr[j][1] = f2tf(DPS(s, n0 + g, kb + tg + 4));
                }
                #pragma unroll
                for (int i = 0; i < 2; ++i)
                    #pragma unroll
                    for (int j = 0; j < 4; ++j)
                        mma_tf32(acc[i][j], afr[i], bfr[j]);
            }
            __syncthreads();
            s ^= 1;
        }

        #pragma unroll
        for (int i = 0; i < 2; ++i) {
            int r0 = bm0 + wm + i * 16 + g;
            #pragma unroll
            for (int j = 0; j < 4; ++j) {
                int col = bn0 + wn + j * 8 + 2 * tg;
                *(float2*)(g_dotep + (size_t)r0 * (CC * KK) + col)       = make_float2(acc[i][j][0], acc[i][j][1]);
                *(float2*)(g_dotep + (size_t)(r0 + 8) * (CC * KK) + col) = make_float2(acc[i][j][2], acc[i][j][3]);
            }
        }
        #undef DE_LOAD
        #undef DAS
        #undef DPS

    } else {
        // ----- W1top -> g_W1h[c][n][k] (transpose + half convert)
        const int idx = blk - 257;           // 0..127
        const int c  = idx >> 2;
        const int tj = idx & 3;              // 64-wide n slice
        float* ts = sh;                      // [64][65]
        const float* Wt = W1 + (size_t)c * TWO_D * DD;   // top half [256 k][256 n]
        __half* outc = g_W1h + (size_t)c * DD * DD;

        for (int ti = 0; ti < 4; ++ti) {
            {
                int r = tid >> 2, cg = (tid & 3) * 16;
                const float* src = Wt + (size_t)(ti * 64 + r) * DD + tj * 64 + cg;
                #pragma unroll
                for (int u = 0; u < 4; ++u) {
                    float4 v = *(const float4*)(src + u * 4);
                    ts[r * 65 + cg + u * 4 + 0] = v.x;
                    ts[r * 65 + cg + u * 4 + 1] = v.y;
                    ts[r * 65 + cg + u * 4 + 2] = v.z;
                    ts[r * 65 + cg + u * 4 + 3] = v.w;
                }
            }
            __syncthreads();
            {
                int nn = tid >> 2, kg = (tid & 3) * 16;
                uint32_t* dst = (uint32_t*)(outc + (size_t)(tj * 64 + nn) * DD + ti * 64 + kg);
                #pragma unroll
                for (int u = 0; u < 8; ++u) {
                    __half2 h = __floats2half2_rn(ts[(kg + 2 * u) * 65 + nn],
                                                  ts[(kg + 2 * u + 1) * 65 + nn]);
                    dst[u] = h2u(h);
                }
            }
            __syncthreads();
        }
    }
}

// ===========================================================================
// Kernel B (main, fused): per (64-batch-tile, class):
//   1. qW tile [64 x 256] = emb_h @ W1h  — f16 mma with F16 ACCUMULATE
//      (acc = 32 half2 regs), BK=32, 3-stage cp.async, 1 sync/iter
//   2. epilogue: tanh f16x2 + 2nd-stage f16 mma scores (fp32 acc)
//   3. softmax over K, dist via Gram trick, write out
// grid (16, 32), 256 threads (8 warps, n-sliced: warp tile 64x32), 3 CTAs/SM.
// smem/CTA: As [3][64][20] + Bs [3][256][20] = 19200 words = 76800 B.
// Row pitch 20 words = 80 B: 16B-aligned for cp.async AND conflict-free.
// ===========================================================================
__global__ __launch_bounds__(256, 3) void fused_main(
    const float* __restrict__ w2, const float* __restrict__ b2,
    const float* __restrict__ temperature, float* __restrict__ out)
{
    extern __shared__ float sh[];
    uint32_t* shw = (uint32_t*)sh;
    // phase-1: AsW [3][64][20] words 0..3839 ; BsW [3][256][20] words 3840..19199
    // phase-2 layout (aliases phase-1 region)
    uint32_t* sh_pt_h2 = (uint32_t*)sh;        // [16][128] half2 = 2048 words
    float* sh_scorew = sh + 2048;              // [8 warps][64 rows][20] = 10240
    float* sh_w2    = sh + 2048 + 10240;       // 256
    float* sh_G     = sh_w2 + 256;             // [16][17] = 272
    float* sh_inval = sh_G + 272;              // 16

    const int c  = blockIdx.y;
    const int b0 = blockIdx.x * 64;
    const __half* Wh = g_W1h + (size_t)c * DD * DD;   // [n][k] half

    const int tid  = threadIdx.x;
    const int warp = tid >> 5, lane = tid & 31;
    const int wn = warp * 32;            // warp n-slice (all 64 rows)
    const int g  = lane >> 2, tg = lane & 3;

    uint32_t acc[4][4][2];               // f16x2 accumulators [m16][n8][row g/g+8]
    #pragma unroll
    for (int i = 0; i < 4; ++i)
        #pragma unroll
        for (int j = 0; j < 4; ++j) { acc[i][j][0] = 0u; acc[i][j][1] = 0u; }

    #define ASW(s, idx) shw[(s) * 1280 + (idx)]
    #define BSW(s, idx) shw[3840 + (s) * 5120 + (idx)]
    // BK=32 halfs = 16 data words/row; rows padded to 20 words (80 B)
    #define FM_LOAD(s, kbase)                                                  \
        {                                                                       \
            { int r = tid >> 2, ch = tid & 3;                                   \
              cp16(&ASW(s, r * 20 + ch * 4),                                    \
                   g_emb_h + (size_t)(b0 + r) * DD + (kbase) + ch * 8); }       \
            _Pragma("unroll")                                                   \
            for (int i_ = 0; i_ < 4; ++i_) {                                    \
                int slot = tid + i_ * 256;                                      \
                int r = slot >> 2, ch = slot & 3;                               \
                cp16(&BSW(s, r * 20 + ch * 4),                                  \
                     Wh + (size_t)r * DD + (kbase) + ch * 8);                   \
            }                                                                   \
            CP_COMMIT();                                                        \
        }

    // ---------------- Phase 1: f16 GEMM (f16 acc), 3-stage, 1 sync/iter ------
    FM_LOAD(0, 0);
    FM_LOAD(1, 32);
    const int NT = DD / 32;   // 8
    #pragma unroll 1
    for (int kt = 0; kt < NT; ++kt) {
        const int cs = kt % 3;
        if (kt < NT - 1) { CP_WAIT(1); } else { CP_WAIT(0); }
        __syncthreads();
        if (kt + 2 < NT) FM_LOAD((kt + 2) % 3, (kt + 2) * 32);

        #pragma unroll
        for (int ks = 0; ks < 2; ++ks) {
            const int kb = ks * 8;
            uint32_t afr[4][4], bfr[4][2];
            #pragma unroll
            for (int i = 0; i < 4; ++i) {
                int m0 = i * 16;
                afr[i][0] = ASW(cs, (m0 + g)     * 20 + kb + tg);
                afr[i][1] = ASW(cs, (m0 + g + 8) * 20 + kb + tg);
                afr[i][2] = ASW(cs, (m0 + g)     * 20 + kb + tg + 4);
                afr[i][3] = ASW(cs, (m0 + g + 8) * 20 + kb + tg + 4);
            }
            #pragma unroll
            for (int j = 0; j < 4; ++j) {
                int n0 = wn + j * 8;
                bfr[j][0] = BSW(cs, (n0 + g) * 20 + kb + tg);
                bfr[j][1] = BSW(cs, (n0 + g) * 20 + kb + tg + 4);
            }
            #pragma unroll
            for (int i = 0; i < 4; ++i)
                #pragma unroll
                for (int j = 0; j < 4; ++j)
                    mma_f16_hacc(acc[i][j], afr[i][0], afr[i][1], afr[i][2], afr[i][3],
                                 bfr[j][0], bfr[j][1]);
        }
    }
    __syncthreads();   // all warps done with GEMM smem before repurposing

    // ---------------- Phase 2 tables ----------------
    {
        const float2* ptg2 = (const float2*)(g_proto_term + (size_t)c * KK * DD);
        #pragma unroll
        for (int i = 0; i < 8; ++i) {
            int idx = tid + i * 256;            // 0..2047
            float2 v = ptg2[idx];
            __half2 h = __floats2half2_rn(v.x, v.y);
            sh_pt_h2[idx] = h2u(h);
        }
        if (tid < DD) sh_w2[tid] = w2[c * DD + tid];
        if (tid < KK * KK) sh_G[(tid >> 4) * 17 + (tid & 15)] = g_G[c * 256 + tid];
        if (tid < KK) sh_inval[tid] = g_inval[c * KK + tid];
    }
    __syncthreads();

    // per-thread w2 pairs (B-fragments of 2nd-stage mma)
    uint32_t w2u[4];
    #pragma unroll
    for (int j = 0; j < 4; ++j) {
        float2 w = *(float2*)&sh_w2[wn + j * 8 + 2 * tg];
        w2u[j] = h2u(__floats2half2_rn(w.x, w.y));
    }

    float* my_slab = sh_scorew + warp * 1280;   // [64][20]
    const int ptbase = (wn >> 1) + tg;

    // ---------------- Phase 3: tanh + 2nd-stage mma (pt prefetch) ----------
    uint32_t pw_cur[4];
    #pragma unroll
    for (int j = 0; j < 4; ++j) pw_cur[j] = sh_pt_h2[ptbase + j * 4];

    #pragma unroll 1
    for (int k = 0; k < KK; ++k) {
        uint32_t pw_nxt[4];
        if (k + 1 < KK) {
            #pragma unroll
            for (int j = 0; j < 4; ++j)
                pw_nxt[j] = sh_pt_h2[(k + 1) * 128 + ptbase + j * 4];
        }
        __half2 pth[4];
        #pragma unroll
        for (int j = 0; j < 4; ++j) pth[j] = *reinterpret_cast<__half2*>(&pw_cur[j]);

        #pragma unroll
        for (int i = 0; i < 4; ++i) {
            #define ACCH(jj, uu) (*reinterpret_cast<__half2*>(&acc[i][jj][uu]))
            uint32_t t00 = h2u(tanh_h2(__hadd2(ACCH(0, 0), pth[0])));
            uint32_t t01 = h2u(tanh_h2(__hadd2(ACCH(0, 1), pth[0])));
            uint32_t t10 = h2u(tanh_h2(__hadd2(ACCH(1, 0), pth[1])));
            uint32_t t11 = h2u(tanh_h2(__hadd2(ACCH(1, 1), pth[1])));
            uint32_t t20 = h2u(tanh_h2(__hadd2(ACCH(2, 0), pth[2])));
            uint32_t t21 = h2u(tanh_h2(__hadd2(ACCH(2, 1), pth[2])));
            uint32_t t30 = h2u(tanh_h2(__hadd2(ACCH(3, 0), pth[3])));
            uint32_t t31 = h2u(tanh_h2(__hadd2(ACCH(3, 1), pth[3])));
            #undef ACCH

            float cfr[4] = {0.f, 0.f, 0.f, 0.f};
            mma_f16(cfr, t00, t01, t10, t11, w2u[0], w2u[1]);
            mma_f16(cfr, t20, t21, t30, t31, w2u[2], w2u[3]);

            if (tg == 0) {
                my_slab[(i * 16 + g) * 20 + k]     = cfr[0];
                my_slab[(i * 16 + g + 8) * 20 + k] = cfr[2];
            }
        }
        #pragma unroll
        for (int j = 0; j < 4; ++j) pw_cur[j] = pw_nxt[j];
    }
    __syncthreads();

    // ---------------- Phase 4: gather slabs + softmax + Gram distance -------
    if (tid < 64) {
        const int b = b0 + tid;
        const float b2v  = b2[c];
        const float temp = temperature[0];

        float s16[KK];
        #pragma unroll
        for (int k = 0; k < KK; ++k) s16[k] = b2v + sh_inval[k];
        #pragma unroll
        for (int w = 0; w < 8; ++w) {
            const float* p = sh_scorew + w * 1280 + tid * 20;
            float4 v0 = *(const float4*)(p + 0);
            float4 v1 = *(const float4*)(p + 4);
            float4 v2 = *(const float4*)(p + 8);
            float4 v3 = *(const float4*)(p + 12);
            s16[0] += v0.x;  s16[1] += v0.y;  s16[2] += v0.z;  s16[3] += v0.w;
            s16[4] += v1.x;  s16[5] += v1.y;  s16[6] += v1.z;  s16[7] += v1.w;
            s16[8] += v2.x;  s16[9] += v2.y;  s16[10] += v2.z; s16[11] += v2.w;
            s16[12] += v3.x; s16[13] += v3.y; s16[14] += v3.z; s16[15] += v3.w;
        }

        float m = s16[0];
        #pragma unroll
        for (int k = 1; k < KK; ++k) m = fmaxf(m, s16[k]);
        float sum = 0.f;
        #pragma unroll
        for (int k = 0; k < KK; ++k) {
            float e = __expf(s16[k] - m);
            s16[k] = e;
            sum += e;
        }
        float inv = 1.f / sum;
        #pragma unroll
        for (int k = 0; k < KK; ++k) s16[k] *= inv;

        // dist^2 = e2 - 2*attn·dotep + attn^T G attn
        float depv[KK];
        const float4* dep = (const float4*)(g_dotep + (size_t)b * (CC * KK) + c * KK);
        #pragma unroll
        for (int q = 0; q < 4; ++q) {
            float4 v = dep[q];
            depv[4 * q + 0] = v.x; depv[4 * q + 1] = v.y;
            depv[4 * q + 2] = v.z; depv[4 * q + 3] = v.w;
        }
        float dist2 = g_e2[b];
        #pragma unroll
        for (int k = 0; k < KK; ++k)
            dist2 = fmaf(-2.0f * s16[k], depv[k], dist2);
        #pragma unroll
        for (int k = 0; k < KK; ++k) {
            float t = 0.f;
            #pragma unroll
            for (int k2 = 0; k2 < KK; ++k2)
                t = fmaf(sh_G[k * 17 + k2], s16[k2], t);
            dist2 = fmaf(s16[k], t, dist2);
        }
        out[(size_t)b * CC + c] = -sqrtf(fmaxf(dist2, 0.f)) * temp;
    }
    #undef ASW
    #undef BSW
    #undef FM_LOAD
}

// ---------------------------------------------------------------------------
extern "C" void kernel_launch(void* const* d_in, const int* in_sizes, int n_in,
                              void* d_out, int out_size)
{
    const float* emb    = (const float*)d_in[0];   // [B,D]
    const float* protos = (const float*)d_in[1];   // [C,K,D]
    const float* W1     = (const float*)d_in[2];   // [C,2D,D]
    const float* b1     = (const float*)d_in[3];   // [C,D]
    const float* w2     = (const float*)d_in[4];   // [C,D]
    const float* b2     = (const float*)d_in[5];   // [C]
    const float* temp   = (const float*)d_in[6];   // [1]
    const void*  valid  = (const void*)d_in[7];    // [C,K] bool (storage dtype unknown)
    float* out = (float*)d_out;                    // [B,C]

    // dyn smem = 19200 words = 76800 B (epilogue 12832 words fits inside)
    const int dyn = 19200 * 4;
    cudaFuncSetAttribute(fused_main, cudaFuncAttributeMaxDynamicSharedMemorySize, dyn);

    prologue_kernel<<<385, 256>>>(emb, protos, W1, b1, valid);
    fused_main<<<dim3(16, CC), 256, dyn>>>(w2, b2, temp, out);
}

// round 14
// speedup vs baseline: 1.5310x; 1.1113x over previous
#include <cuda_runtime.h>
#include <math_constants.h>
#include <cuda_fp16.h>
#include <cstdint>

// Problem constants
#define BB 1024   // batch
#define CC 32     // classes
#define KK 16     // prototypes per class
#define DD 256    // embedding dim
#define TWO_D 512

// Scratch (static device arrays — no allocation allowed)
__device__ float g_proto_term[CC * KK * DD];          // 512 KB
__device__ float g_dotep[(size_t)BB * CC * KK];       // 2 MB: emb·proto
__device__ float g_G[CC * KK * KK];                   // 32 KB: Gram
__device__ float g_e2[BB];                            // |emb|^2
__device__ float g_inval[CC * KK];                    // 0 = valid, -inf = invalid
__device__ __half g_emb_h[(size_t)BB * DD];           // 512 KB: emb as half
__device__ __half g_W1h[(size_t)CC * DD * DD];        // 4 MB: W1top^T as half [c][n][k]

__device__ __forceinline__ uint32_t f2tf(float f) {
    uint32_t r;
    asm("cvt.rna.tf32.f32 %0, %1;" : "=r"(r) : "f"(f));
    return r;
}
__device__ __forceinline__ __half2 tanh_h2(__half2 x) {
    uint32_t xi = *reinterpret_cast<uint32_t*>(&x);
    uint32_t r;
    asm("tanh.approx.f16x2 %0, %1;" : "=r"(r) : "r"(xi));
    return *reinterpret_cast<__half2*>(&r);
}
__device__ __forceinline__ uint32_t h2u(__half2 h) {
    return *reinterpret_cast<uint32_t*>(&h);
}
__device__ __forceinline__ void cp16(void* smem, const void* g) {
    uint32_t sa = (uint32_t)__cvta_generic_to_shared(smem);
    asm volatile("cp.async.cg.shared.global [%0], [%1], 16;" :: "r"(sa), "l"(g));
}
#define CP_COMMIT() asm volatile("cp.async.commit_group;")
#define CP_WAIT(N)  asm volatile("cp.async.wait_group %0;" :: "n"(N))

__device__ __forceinline__ void mma_tf32(float c_[4], const uint32_t a[4], const uint32_t b[2]) {
    asm volatile(
        "mma.sync.aligned.m16n8k8.row.col.f32.tf32.tf32.f32 "
        "{%0,%1,%2,%3}, {%4,%5,%6,%7}, {%8,%9}, {%0,%1,%2,%3};"
        : "+f"(c_[0]), "+f"(c_[1]), "+f"(c_[2]), "+f"(c_[3])
        : "r"(a[0]), "r"(a[1]), "r"(a[2]), "r"(a[3]), "r"(b[0]), "r"(b[1]));
}
// fp16 inputs, fp32 accumulate (used by 2nd-stage score mma)
__device__ __forceinline__ void mma_f16(float c_[4],
    uint32_t a0, uint32_t a1, uint32_t a2, uint32_t a3,
    uint32_t b0, uint32_t b1) {
    asm volatile(
        "mma.sync.aligned.m16n8k16.row.col.f32.f16.f16.f32 "
        "{%0,%1,%2,%3}, {%4,%5,%6,%7}, {%8,%9}, {%0,%1,%2,%3};"
        : "+f"(c_[0]), "+f"(c_[1]), "+f"(c_[2]), "+f"(c_[3])
        : "r"(a0), "r"(a1), "r"(a2), "r"(a3), "r"(b0), "r"(b1));
}
// fp16 inputs, fp16 accumulate (GEMM phase — C/D = 2 regs)
__device__ __forceinline__ void mma_f16_hacc(uint32_t c_[2],
    uint32_t a0, uint32_t a1, uint32_t a2, uint32_t a3,
    uint32_t b0, uint32_t b1) {
    asm volatile(
        "mma.sync.aligned.m16n8k16.row.col.f16.f16.f16.f16 "
        "{%0,%1}, {%2,%3,%4,%5}, {%6,%7}, {%0,%1};"
        : "+r"(c_[0]), "+r"(c_[1])
        : "r"(a0), "r"(a1), "r"(a2), "r"(a3), "r"(b0), "r"(b1));
}

// ===========================================================================
// Kernel A (prologue, fused): blockIdx dispatch, 256 threads everywhere
//   [0,128)   : proto_term  (c = blk>>2, d-slice = (blk&3)*64), MLP-8 prefetch
//   [128,160) : Gram        (c = blk-128)
//   [160,192) : e2 + emb->half
//   192       : decode prototype_valid mask
//   [193,257) : dotep tf32 GEMM (64x128 tiles)
//   [257,385) : W1top transpose->half: g_W1h[c][n][k]
// ===========================================================================
__global__ __launch_bounds__(256) void prologue_kernel(
    const float* __restrict__ emb,      // [B,D]
    const float* __restrict__ protos,   // [C,K,D]
    const float* __restrict__ W1,       // [C,2D,D]
    const float* __restrict__ b1,       // [C,D]
    const void*  __restrict__ valid)
{
    __shared__ __align__(16) float sh[8192];   // 32 KB, reused per role
    const int blk = blockIdx.x;
    const int tid = threadIdx.x;

    if (blk < 128) {
        // ----- proto_term[c][k][d0+dl] = b1 + sum_e protos[c][k][e]*W1[c][D+e][d0+dl]
        const int c  = blk >> 2;
        const int d0 = (blk & 3) * 64;
        const int dl = tid & 63;
        const int eg = tid >> 6;

        float* p_s  = sh;               // [16][256]
        float* sred = sh + KK * DD;     // [4][16][64]

        const float* pg = protos + (size_t)c * KK * DD;
        #pragma unroll
        for (int i = 0; i < 16; ++i) p_s[tid + i * 256] = pg[tid + i * 256];
        __syncthreads();

        float acc[KK];
        #pragma unroll
        for (int k = 0; k < KK; ++k) acc[k] = 0.f;

        const float* Wb = W1 + ((size_t)c * TWO_D + DD + eg * 64) * DD + d0 + dl;
        for (int e0 = 0; e0 < 64; e0 += 8) {
            float w[8];
            #pragma unroll
            for (int u = 0; u < 8; ++u) w[u] = Wb[(size_t)(e0 + u) * DD];
            #pragma unroll
            for (int u = 0; u < 8; ++u) {
                const float* pe = p_s + eg * 64 + e0 + u;
                #pragma unroll
                for (int k = 0; k < KK; ++k)
                    acc[k] = fmaf(pe[k * DD], w[u], acc[k]);
            }
        }

        #pragma unroll
        for (int k = 0; k < KK; ++k)
            sred[(eg * KK + k) * 64 + dl] = acc[k];
        __syncthreads();

        #pragma unroll
        for (int r = 0; r < 4; ++r) {
            int idx = tid + r * 256;
            int k = idx >> 6, d = idx & 63;
            float s = sred[(0 * KK + k) * 64 + d] + sred[(1 * KK + k) * 64 + d]
                    + sred[(2 * KK + k) * 64 + d] + sred[(3 * KK + k) * 64 + d];
            g_proto_term[((c * KK) + k) * DD + d0 + d] = s + b1[c * DD + d0 + d];
        }

    } else if (blk < 160) {
        // ----- Gram G[c][k][k2]
        const int c = blk - 128;
        float* p_s = sh;   // [16][257]
        for (int i = tid; i < KK * DD; i += 256) {
            int k = i / DD, d = i % DD;
            p_s[k * (DD + 1) + d] = protos[(size_t)c * KK * DD + i];
        }
        __syncthreads();
        const int k = tid >> 4, k2 = tid & 15;
        float s = 0.f;
        #pragma unroll 4
        for (int d = 0; d < DD; ++d)
            s = fmaf(p_s[k * (DD + 1) + d], p_s[k2 * (DD + 1) + d], s);
        g_G[c * 256 + tid] = s;

    } else if (blk < 192) {
        // ----- e2 + emb->half: warp-per-row, 4 rows per warp
        const int warp = tid >> 5, lane = tid & 31;
        const int base = (blk - 160) * 32 + warp * 4;
        #pragma unroll
        for (int t = 0; t < 4; ++t) {
            const int b = base + t;
            const float4* p = (const float4*)(emb + (size_t)b * DD);
            float4 v0 = p[lane], v1 = p[lane + 32];
            uint2* eh = (uint2*)(g_emb_h + (size_t)b * DD);
            uint2 w0, w1;
            w0.x = h2u(__floats2half2_rn(v0.x, v0.y));
            w0.y = h2u(__floats2half2_rn(v0.z, v0.w));
            w1.x = h2u(__floats2half2_rn(v1.x, v1.y));
            w1.y = h2u(__floats2half2_rn(v1.z, v1.w));
            eh[lane]      = w0;
            eh[lane + 32] = w1;
            float s = v0.x*v0.x + v0.y*v0.y + v0.z*v0.z + v0.w*v0.w
                    + v1.x*v1.x + v1.y*v1.y + v1.z*v1.z + v1.w*v1.w;
            #pragma unroll
            for (int off = 16; off > 0; off >>= 1)
                s += __shfl_xor_sync(0xFFFFFFFFu, s, off);
            if (lane == 0) g_e2[b] = s;
        }

    } else if (blk == 192) {
        // ----- decode prototype_valid (dtype-sniffing)
        __shared__ int s_hasF, s_hasHi, s_mode;
        if (tid == 0) { s_hasF = 0; s_hasHi = 0; }
        __syncthreads();
        if (tid < 128) {
            unsigned v = ((const unsigned*)valid)[tid];
            if (v == 0x3F800000u)                        atomicOr(&s_hasF, 1);
            else if (v != 0u && (v & 0xFFFFFF00u) != 0u) atomicOr(&s_hasHi, 1);
        }
        __syncthreads();
        if (tid == 0) s_mode = s_hasF ? 0 : (s_hasHi ? 2 : 1);
        __syncthreads();
        const int mode = s_mode;
        for (int i = tid; i < CC * KK; i += 256) {
            bool v;
            if (mode == 0)      v = ((const float*)valid)[i] != 0.0f;
            else if (mode == 1) v = ((const int*)valid)[i] != 0;
            else                v = ((const unsigned char*)valid)[i] != 0;
            g_inval[i] = v ? 0.0f : -CUDART_INF_F;
        }

    } else if (blk < 257) {
        // ----- dotep[b][ck] = emb[b,:]·proto[ck,:]  (tf32 mma)
        const int b    = blk - 193;              // 0..63
        const int bm0  = (b >> 2) * 64;
        const int bn0  = (b & 3) * 128;

        #define DAS(s, m, k) sh[(s) * 1280 + (m) * 20 + (k)]
        #define DPS(s, n, k) sh[2560 + (s) * 2560 + (n) * 20 + (k)]

        const int warp = tid >> 5, lane = tid & 31;
        const int wm = (warp >> 2) * 32;
        const int wn = (warp & 3) * 32;
        const int g  = lane >> 2, tg = lane & 3;

        float acc[2][4][4];
        #pragma unroll
        for (int i = 0; i < 2; ++i)
            #pragma unroll
            for (int j = 0; j < 4; ++j)
                #pragma unroll
                for (int t = 0; t < 4; ++t) acc[i][j][t] = 0.f;

        #define DE_LOAD(s, kbase)                                                         \
            {                                                                              \
                { int m = tid >> 2, k4 = (tid & 3) << 2;                                   \
                  cp16(&DAS(s, m, k4), emb + (size_t)(bm0 + m) * DD + (kbase) + k4); }     \
                _Pragma("unroll")                                                          \
                for (int i_ = 0; i_ < 2; ++i_) {                                           \
                    int slot = tid + i_ * 256;                                             \
                    int n = slot >> 2, k4 = (slot & 3) << 2;                               \
                    cp16(&DPS(s, n, k4), protos + (size_t)(bn0 + n) * DD + (kbase) + k4);  \
                }                                                                          \
                CP_COMMIT();                                                               \
            }

        DE_LOAD(0, 0);
        int s = 0;
        const int NT = DD / 16;
        for (int kt = 0; kt < NT; ++kt) {
            if (kt + 1 < NT) { DE_LOAD(s ^ 1, (kt + 1) * 16); CP_WAIT(1); }
            else             { CP_WAIT(0); }
            __syncthreads();

            #pragma unroll
            for (int ks = 0; ks < 2; ++ks) {
                const int kb = ks * 8;
                uint32_t afr[2][4], bfr[4][2];
                #pragma unroll
                for (int i = 0; i < 2; ++i) {
                    int m0 = wm + i * 16;
                    afr[i][0] = f2tf(DAS(s, m0 + g,     kb + tg));
                    afr[i][1] = f2tf(DAS(s, m0 + g + 8, kb + tg));
                    afr[i][2] = f2tf(DAS(s, m0 + g,     kb + tg + 4));
                    afr[i][3] = f2tf(DAS(s, m0 + g + 8, kb + tg + 4));
                }
                #pragma unroll
                for (int j = 0; j < 4; ++j) {
                    int n0 = wn + j * 8;
                    bfr[j][0] = f2tf(DPS(s, n0 + g, kb + tg));
                    bfr[j][1] = f2tf(DPS(s, n0 + g, kb + tg + 4));
                }
                #pragma unroll
                for (int i = 0; i < 2; ++i)
                    #pragma unroll
                    for (int j = 0; j < 4; ++j)
                        mma_tf32(acc[i][j], afr[i], bfr[j]);
            }
            __syncthreads();
            s ^= 1;
        }

        #pragma unroll
        for (int i = 0; i < 2; ++i) {
            int r0 = bm0 + wm + i * 16 + g;
            #pragma unroll
            for (int j = 0; j < 4; ++j) {
                int col = bn0 + wn + j * 8 + 2 * tg;
                *(float2*)(g_dotep + (size_t)r0 * (CC * KK) + col)       = make_float2(acc[i][j][0], acc[i][j][1]);
                *(float2*)(g_dotep + (size_t)(r0 + 8) * (CC * KK) + col) = make_float2(acc[i][j][2], acc[i][j][3]);
            }
        }
        #undef DE_LOAD
        #undef DAS
        #undef DPS

    } else {
        // ----- W1top -> g_W1h[c][n][k] (transpose + half convert)
        const int idx = blk - 257;           // 0..127
        const int c  = idx >> 2;
        const int tj = idx & 3;              // 64-wide n slice
        float* ts = sh;                      // [64][65]
        const float* Wt = W1 + (size_t)c * TWO_D * DD;   // top half [256 k][256 n]
        __half* outc = g_W1h + (size_t)c * DD * DD;

        for (int ti = 0; ti < 4; ++ti) {
            {
                int r = tid >> 2, cg = (tid & 3) * 16;
                const float* src = Wt + (size_t)(ti * 64 + r) * DD + tj * 64 + cg;
                #pragma unroll
                for (int u = 0; u < 4; ++u) {
                    float4 v = *(const float4*)(src + u * 4);
                    ts[r * 65 + cg + u * 4 + 0] = v.x;
                    ts[r * 65 + cg + u * 4 + 1] = v.y;
                    ts[r * 65 + cg + u * 4 + 2] = v.z;
                    ts[r * 65 + cg + u * 4 + 3] = v.w;
                }
            }
            __syncthreads();
            {
                int nn = tid >> 2, kg = (tid & 3) * 16;
                uint32_t* dst = (uint32_t*)(outc + (size_t)(tj * 64 + nn) * DD + ti * 64 + kg);
                #pragma unroll
                for (int u = 0; u < 8; ++u) {
                    __half2 h = __floats2half2_rn(ts[(kg + 2 * u) * 65 + nn],
                                                  ts[(kg + 2 * u + 1) * 65 + nn]);
                    dst[u] = h2u(h);
                }
            }
            __syncthreads();
        }
    }
}

// ===========================================================================
// Kernel B (main, fused): per (32-batch-tile, class):
//   1. qW tile [32 x 256] = emb_h @ W1h  — f16 mma, f16 acc (16 regs),
//      BK=32, 3-stage cp.async, 1 sync/iter, XOR-swizzled 16-word row pitch
//   2. epilogue: tanh f16x2 + 2nd-stage f16 mma scores (fp32 acc)
//   3. softmax over K, dist via Gram trick, write out
// grid (32, 32) = 1024 blocks, 256 threads (8 warps, warp tile 32x32),
// 4 CTAs/SM (592 slots for 1024 units -> 86% slot utilization).
// smem/CTA: As [3][32][16] + Bs [3][256][16] = 13824 words = 55296 B.
// Swizzle: chunk c (4 words) of row r stored at word r*16 + ((c^((r>>1)&3))<<2)
//   -> conflict-free for cp.async stores AND both mma fragment read patterns.
// ===========================================================================
__global__ __launch_bounds__(256, 4) void fused_main(
    const float* __restrict__ w2, const float* __restrict__ b2,
    const float* __restrict__ temperature, float* __restrict__ out)
{
    extern __shared__ float sh[];
    uint32_t* shw = (uint32_t*)sh;
    // phase-1: AsW [3][32][16] words 0..1535 ; BsW [3][256][16] words 1536..13823
    // phase-2 layout (aliases phase-1 region)
    uint32_t* sh_pt_h2 = (uint32_t*)sh;        // [16][128] half2 = 2048 words
    float* sh_scorew = sh + 2048;              // [8 warps][32 rows][18] = 4608
    float* sh_w2    = sh + 2048 + 4608;        // 256
    float* sh_G     = sh_w2 + 256;             // [16][17] = 272
    float* sh_inval = sh_G + 272;              // 16      (total 7200 words)

    const int c  = blockIdx.y;
    const int b0 = blockIdx.x * 32;
    const __half* Wh = g_W1h + (size_t)c * DD * DD;   // [n][k] half

    const int tid  = threadIdx.x;
    const int warp = tid >> 5, lane = tid & 31;
    const int wn = warp * 32;            // warp n-slice (all 32 rows)
    const int g  = lane >> 2, tg = lane & 3;

    uint32_t acc[2][4][2];               // f16x2 accumulators [m16][n8][row g/g+8]
    #pragma unroll
    for (int i = 0; i < 2; ++i)
        #pragma unroll
        for (int j = 0; j < 4; ++j) { acc[i][j][0] = 0u; acc[i][j][1] = 0u; }

    // swizzled word index within a stage: row r, chunk ch (0..3), word j (0..3)
    #define SWIZ(r, ch, j) ((r) * 16 + ((((ch) ^ (((r) >> 1) & 3))) << 2) + (j))
    #define ASW(s, r, ch, j) shw[(s) * 512 + SWIZ(r, ch, j)]
    #define BSW(s, r, ch, j) shw[1536 + (s) * 4096 + SWIZ(r, ch, j)]
    #define FM_LOAD(s, kbase)                                                  \
        {                                                                       \
            if (tid < 128) {                                                    \
                int r = tid >> 2, ch = tid & 3;                                 \
                cp16(&ASW(s, r, ch, 0),                                         \
                     g_emb_h + (size_t)(b0 + r) * DD + (kbase) + ch * 8);       \
            }                                                                   \
            _Pragma("unroll")                                                   \
            for (int i_ = 0; i_ < 4; ++i_) {                                    \
                int slot = tid + i_ * 256;                                      \
                int r = slot >> 2, ch = slot & 3;                               \
                cp16(&BSW(s, r, ch, 0),                                         \
                     Wh + (size_t)r * DD + (kbase) + ch * 8);                   \
            }                                                                   \
            CP_COMMIT();                                                        \
        }

    // ---------------- Phase 1: f16 GEMM (f16 acc), 3-stage, 1 sync/iter ------
    FM_LOAD(0, 0);
    FM_LOAD(1, 32);
    const int NT = DD / 32;   // 8
    #pragma unroll 1
    for (int kt = 0; kt < NT; ++kt) {
        const int cs = kt % 3;
        if (kt < NT - 1) { CP_WAIT(1); } else { CP_WAIT(0); }
        __syncthreads();
        if (kt + 2 < NT) FM_LOAD((kt + 2) % 3, (kt + 2) * 32);

        #pragma unroll
        for (int ks = 0; ks < 2; ++ks) {
            const int c0 = ks * 2;   // chunk pair for this k8-step
            uint32_t afr[2][4], bfr[4][2];
            #pragma unroll
            for (int i = 0; i < 2; ++i) {
                int m0 = i * 16;
                afr[i][0] = ASW(cs, m0 + g,     c0,     tg);
                afr[i][1] = ASW(cs, m0 + g + 8, c0,     tg);
                afr[i][2] = ASW(cs, m0 + g,     c0 + 1, tg);
                afr[i][3] = ASW(cs, m0 + g + 8, c0 + 1, tg);
            }
            #pragma unroll
            for (int j = 0; j < 4; ++j) {
                int n0 = wn + j * 8;
                bfr[j][0] = BSW(cs, n0 + g, c0,     tg);
                bfr[j][1] = BSW(cs, n0 + g, c0 + 1, tg);
            }
            #pragma unroll
            for (int i = 0; i < 2; ++i)
                #pragma unroll
                for (int j = 0; j < 4; ++j)
                    mma_f16_hacc(acc[i][j], afr[i][0], afr[i][1], afr[i][2], afr[i][3],
                                 bfr[j][0], bfr[j][1]);
        }
    }
    __syncthreads();   // all warps done with GEMM smem before repurposing

    // ---------------- Phase 2 tables ----------------
    {
        const float2* ptg2 = (const float2*)(g_proto_term + (size_t)c * KK * DD);
        #pragma unroll
        for (int i = 0; i < 8; ++i) {
            int idx = tid + i * 256;            // 0..2047
            float2 v = ptg2[idx];
            __half2 h = __floats2half2_rn(v.x, v.y);
            sh_pt_h2[idx] = h2u(h);
        }
        if (tid < DD) sh_w2[tid] = w2[c * DD + tid];
        if (tid < KK * KK) sh_G[(tid >> 4) * 17 + (tid & 15)] = g_G[c * 256 + tid];
        if (tid < KK) sh_inval[tid] = g_inval[c * KK + tid];
    }
    __syncthreads();

    // per-thread w2 pairs (B-fragments of 2nd-stage mma)
    uint32_t w2u[4];
    #pragma unroll
    for (int j = 0; j < 4; ++j) {
        float2 w = *(float2*)&sh_w2[wn + j * 8 + 2 * tg];
        w2u[j] = h2u(__floats2half2_rn(w.x, w.y));
    }

    float* my_slab = sh_scorew + warp * 576;   // [32][18]
    const int ptbase = (wn >> 1) + tg;

    // ---------------- Phase 3: tanh + 2nd-stage mma (pt prefetch) ----------
    uint32_t pw_cur[4];
    #pragma unroll
    for (int j = 0; j < 4; ++j) pw_cur[j] = sh_pt_h2[ptbase + j * 4];

    #pragma unroll 1
    for (int k = 0; k < KK; ++k) {
        uint32_t pw_nxt[4];
        if (k + 1 < KK) {
            #pragma unroll
            for (int j = 0; j < 4; ++j)
                pw_nxt[j] = sh_pt_h2[(k + 1) * 128 + ptbase + j * 4];
        }
        __half2 pth[4];
        #pragma unroll
        for (int j = 0; j < 4; ++j) pth[j] = *reinterpret_cast<__half2*>(&pw_cur[j]);

        #pragma unroll
        for (int i = 0; i < 2; ++i) {
            #define ACCH(jj, uu) (*reinterpret_cast<__half2*>(&acc[i][jj][uu]))
            uint32_t t00 = h2u(tanh_h2(__hadd2(ACCH(0, 0), pth[0])));
            uint32_t t01 = h2u(tanh_h2(__hadd2(ACCH(0, 1), pth[0])));
            uint32_t t10 = h2u(tanh_h2(__hadd2(ACCH(1, 0), pth[1])));
            uint32_t t11 = h2u(tanh_h2(__hadd2(ACCH(1, 1), pth[1])));
            uint32_t t20 = h2u(tanh_h2(__hadd2(ACCH(2, 0), pth[2])));
            uint32_t t21 = h2u(tanh_h2(__hadd2(ACCH(2, 1), pth[2])));
            uint32_t t30 = h2u(tanh_h2(__hadd2(ACCH(3, 0), pth[3])));
            uint32_t t31 = h2u(tanh_h2(__hadd2(ACCH(3, 1), pth[3])));
            #undef ACCH

            float cfr[4] = {0.f, 0.f, 0.f, 0.f};
            mma_f16(cfr, t00, t01, t10, t11, w2u[0], w2u[1]);
            mma_f16(cfr, t20, t21, t30, t31, w2u[2], w2u[3]);

            if (tg == 0) {
                my_slab[(i * 16 + g) * 18 + k]     = cfr[0];
                my_slab[(i * 16 + g + 8) * 18 + k] = cfr[2];
            }
        }
        #pragma unroll
        for (int j = 0; j < 4; ++j) pw_cur[j] = pw_nxt[j];
    }
    __syncthreads();

    // ---------------- Phase 4: gather slabs + softmax + Gram distance -------
    if (tid < 32) {
        const int b = b0 + tid;
        const float b2v  = b2[c];
        const float temp = temperature[0];

        float s16[KK];
        #pragma unroll
        for (int k = 0; k < KK; ++k) s16[k] = b2v + sh_inval[k];
        #pragma unroll
        for (int w = 0; w < 8; ++w) {
            const float* p = sh_scorew + w * 576 + tid * 18;
            #pragma unroll
            for (int q = 0; q < 8; ++q) {
                float2 v = *(const float2*)(p + 2 * q);
                s16[2 * q]     += v.x;
                s16[2 * q + 1] += v.y;
            }
        }

        float m = s16[0];
        #pragma unroll
        for (int k = 1; k < KK; ++k) m = fmaxf(m, s16[k]);
        float sum = 0.f;
        #pragma unroll
        for (int k = 0; k < KK; ++k) {
            float e = __expf(s16[k] - m);
            s16[k] = e;
            sum += e;
        }
        float inv = 1.f / sum;
        #pragma unroll
        for (int k = 0; k < KK; ++k) s16[k] *= inv;

        // dist^2 = e2 - 2*attn·dotep + attn^T G attn
        float depv[KK];
        const float4* dep = (const float4*)(g_dotep + (size_t)b * (CC * KK) + c * KK);
        #pragma unroll
        for (int q = 0; q < 4; ++q) {
            float4 v = dep[q];
            depv[4 * q + 0] = v.x; depv[4 * q + 1] = v.y;
            depv[4 * q + 2] = v.z; depv[4 * q + 3] = v.w;
        }
        float dist2 = g_e2[b];
        #pragma unroll
        for (int k = 0; k < KK; ++k)
            dist2 = fmaf(-2.0f * s16[k], depv[k], dist2);
        #pragma unroll
        for (int k = 0; k < KK; ++k) {
            float t = 0.f;
            #pragma unroll
            for (int k2 = 0; k2 < KK; ++k2)
                t = fmaf(sh_G[k * 17 + k2], s16[k2], t);
            dist2 = fmaf(s16[k], t, dist2);
        }
        out[(size_t)b * CC + c] = -sqrtf(fmaxf(dist2, 0.f)) * temp;
    }
    #undef SWIZ
    #undef ASW
    #undef BSW
    #undef FM_LOAD
}

// ---------------------------------------------------------------------------
extern "C" void kernel_launch(void* const* d_in, const int* in_sizes, int n_in,
                              void* d_out, int out_size)
{
    const float* emb    = (const float*)d_in[0];   // [B,D]
    const float* protos = (const float*)d_in[1];   // [C,K,D]
    const float* W1     = (const float*)d_in[2];   // [C,2D,D]
    const float* b1     = (const float*)d_in[3];   // [C,D]
    const float* w2     = (const float*)d_in[4];   // [C,D]
    const float* b2     = (const float*)d_in[5];   // [C]
    const float* temp   = (const float*)d_in[6];   // [1]
    const void*  valid  = (const void*)d_in[7];    // [C,K] bool (storage dtype unknown)
    float* out = (float*)d_out;                    // [B,C]

    // dyn smem = 13824 words = 55296 B (epilogue 7200 words fits inside)
    const int dyn = 13824 * 4;
    cudaFuncSetAttribute(fused_main, cudaFuncAttributeMaxDynamicSharedMemorySize, dyn);

    prologue_kernel<<<385, 256>>>(emb, protos, W1, b1, valid);
    fused_main<<<dim3(32, CC), 256, dyn>>>(w2, b2, temp, out);
}

// round 15
// speedup vs baseline: 1.5317x; 1.0005x over previous
#include <cuda_runtime.h>
#include <math_constants.h>
#include <cuda_fp16.h>
#include <cstdint>

// Problem constants
#define BB 1024   // batch
#define CC 32     // classes
#define KK 16     // prototypes per class
#define DD 256    // embedding dim
#define TWO_D 512

// Scratch (static device arrays — no allocation allowed)
__device__ float g_proto_term[CC * KK * DD];          // 512 KB
__device__ float g_dotep[(size_t)BB * CC * KK];       // 2 MB: emb·proto
__device__ float g_G[CC * KK * KK];                   // 32 KB: Gram
__device__ float g_e2[BB];                            // |emb|^2
__device__ float g_inval[CC * KK];                    // 0 = valid, -inf = invalid
__device__ __half g_emb_h[(size_t)BB * DD];           // 512 KB: emb as half
__device__ __half g_W1h[(size_t)CC * DD * DD];        // 4 MB: W1top^T as half [c][n][k]

__device__ __forceinline__ uint32_t f2tf(float f) {
    uint32_t r;
    asm("cvt.rna.tf32.f32 %0, %1;" : "=r"(r) : "f"(f));
    return r;
}
__device__ __forceinline__ __half2 tanh_h2(__half2 x) {
    uint32_t xi = *reinterpret_cast<uint32_t*>(&x);
    uint32_t r;
    asm("tanh.approx.f16x2 %0, %1;" : "=r"(r) : "r"(xi));
    return *reinterpret_cast<__half2*>(&r);
}
__device__ __forceinline__ uint32_t h2u(__half2 h) {
    return *reinterpret_cast<uint32_t*>(&h);
}
__device__ __forceinline__ void cp16(void* smem, const void* g) {
    uint32_t sa = (uint32_t)__cvta_generic_to_shared(smem);
    asm volatile("cp.async.cg.shared.global [%0], [%1], 16;" :: "r"(sa), "l"(g));
}
#define CP_COMMIT() asm volatile("cp.async.commit_group;")
#define CP_WAIT(N)  asm volatile("cp.async.wait_group %0;" :: "n"(N))

__device__ __forceinline__ void mma_tf32(float c_[4], const uint32_t a[4], const uint32_t b[2]) {
    asm volatile(
        "mma.sync.aligned.m16n8k8.row.col.f32.tf32.tf32.f32 "
        "{%0,%1,%2,%3}, {%4,%5,%6,%7}, {%8,%9}, {%0,%1,%2,%3};"
        : "+f"(c_[0]), "+f"(c_[1]), "+f"(c_[2]), "+f"(c_[3])
        : "r"(a[0]), "r"(a[1]), "r"(a[2]), "r"(a[3]), "r"(b[0]), "r"(b[1]));
}
// fp16 inputs, fp32 accumulate (used by 2nd-stage score mma)
__device__ __forceinline__ void mma_f16(float c_[4],
    uint32_t a0, uint32_t a1, uint32_t a2, uint32_t a3,
    uint32_t b0, uint32_t b1) {
    asm volatile(
        "mma.sync.aligned.m16n8k16.row.col.f32.f16.f16.f32 "
        "{%0,%1,%2,%3}, {%4,%5,%6,%7}, {%8,%9}, {%0,%1,%2,%3};"
        : "+f"(c_[0]), "+f"(c_[1]), "+f"(c_[2]), "+f"(c_[3])
        : "r"(a0), "r"(a1), "r"(a2), "r"(a3), "r"(b0), "r"(b1));
}
// fp16 inputs, fp16 accumulate (GEMM phase — C/D = 2 regs)
__device__ __forceinline__ void mma_f16_hacc(uint32_t c_[2],
    uint32_t a0, uint32_t a1, uint32_t a2, uint32_t a3,
    uint32_t b0, uint32_t b1) {
    asm volatile(
        "mma.sync.aligned.m16n8k16.row.col.f16.f16.f16.f16 "
        "{%0,%1}, {%2,%3,%4,%5}, {%6,%7}, {%0,%1};"
        : "+r"(c_[0]), "+r"(c_[1])
        : "r"(a0), "r"(a1), "r"(a2), "r"(a3), "r"(b0), "r"(b1));
}

// ===========================================================================
// Kernel A (prologue, fused): blockIdx dispatch, 256 threads everywhere
//   [0,32)    : proto_term via tf32 mma (c = blk): PT = protos @ W1bot + b1
//   [32,64)   : Gram        (c = blk-32)
//   [64,96)   : e2 + emb->half
//   96        : decode prototype_valid mask
//   [97,161)  : dotep tf32 GEMM (64x128 tiles)
//   [161,417) : W1top transpose->half (c = idx>>3, tj = (idx>>1)&3, th = idx&1)
// ===========================================================================
__global__ __launch_bounds__(256) void prologue_kernel(
    const float* __restrict__ emb,      // [B,D]
    const float* __restrict__ protos,   // [C,K,D]
    const float* __restrict__ W1,       // [C,2D,D]
    const float* __restrict__ b1,       // [C,D]
    const void*  __restrict__ valid)
{
    __shared__ __align__(16) float sh[8448];   // 33 KB, reused per role
    const int blk = blockIdx.x;
    const int tid = threadIdx.x;

    if (blk < 32) {
        // ----- proto_term[c] = protos[c] @ W1bot[c] + b1[c]  (tf32 mma)
        // M=16 (protos), N=256 (d), K=256, BK=8 double-buffered.
        const int c = blk;
        float* As = sh;             // [16][260] fp32 protos (4160 words)
        float* Bs = sh + 4160;      // [2][8][264] (4224 words)

        const int warp = tid >> 5, lane = tid & 31;
        const int wn = warp * 32;
        const int g  = lane >> 2, tg = lane & 3;

        const float* pg = protos + (size_t)c * KK * DD;
        #pragma unroll
        for (int i = 0; i < 16; ++i) {
            int idx = tid + i * 256;
            As[(idx >> 8) * 260 + (idx & 255)] = pg[idx];
        }

        const float* Wb = W1 + ((size_t)c * TWO_D + DD) * DD;   // [256 k][256 n]
        #define PT_LOAD(s, kbase)                                               \
            {                                                                    \
                _Pragma("unroll")                                                \
                for (int i_ = 0; i_ < 2; ++i_) {                                 \
                    int slot = tid + i_ * 256;                                   \
                    int k = slot >> 6, n4 = (slot & 63) << 2;                    \
                    cp16(&Bs[(s) * 2112 + k * 264 + n4],                         \
                         Wb + (size_t)((kbase) + k) * DD + n4);                  \
                }                                                                \
                CP_COMMIT();                                                     \
            }

        PT_LOAD(0, 0);
        float accp[4][4];
        #pragma unroll
        for (int j = 0; j < 4; ++j)
            #pragma unroll
            for (int t = 0; t < 4; ++t) accp[j][t] = 0.f;

        int s = 0;
        for (int kt = 0; kt < 32; ++kt) {
            if (kt + 1 < 32) { PT_LOAD(s ^ 1, (kt + 1) * 8); CP_WAIT(1); }
            else             { CP_WAIT(0); }
            __syncthreads();

            const int kb = kt * 8;
            uint32_t afr[4], bfr[4][2];
            afr[0] = f2tf(As[g * 260 + kb + tg]);
            afr[1] = f2tf(As[(g + 8) * 260 + kb + tg]);
            afr[2] = f2tf(As[g * 260 + kb + tg + 4]);
            afr[3] = f2tf(As[(g + 8) * 260 + kb + tg + 4]);
            #pragma unroll
            for (int j = 0; j < 4; ++j) {
                int n0 = wn + j * 8;
                bfr[j][0] = f2tf(Bs[s * 2112 + tg * 264 + n0 + g]);
                bfr[j][1] = f2tf(Bs[s * 2112 + (tg + 4) * 264 + n0 + g]);
            }
            #pragma unroll
            for (int j = 0; j < 4; ++j)
                mma_tf32(accp[j], afr, bfr[j]);
            __syncthreads();
            s ^= 1;
        }

        // epilogue: rows g/g+8 = proto index, cols wn+j*8+2tg(+1) = d
        #pragma unroll
        for (int j = 0; j < 4; ++j) {
            int col = wn + j * 8 + 2 * tg;
            float2 b1v = *(const float2*)&b1[c * DD + col];
            *(float2*)&g_proto_term[((c * KK) + g) * DD + col] =
                make_float2(accp[j][0] + b1v.x, accp[j][1] + b1v.y);
            *(float2*)&g_proto_term[((c * KK) + g + 8) * DD + col] =
                make_float2(accp[j][2] + b1v.x, accp[j][3] + b1v.y);
        }
        #undef PT_LOAD

    } else if (blk < 64) {
        // ----- Gram G[c][k][k2]
        const int c = blk - 32;
        float* p_s = sh;   // [16][257]
        for (int i = tid; i < KK * DD; i += 256) {
            int k = i / DD, d = i % DD;
            p_s[k * (DD + 1) + d] = protos[(size_t)c * KK * DD + i];
        }
        __syncthreads();
        const int k = tid >> 4, k2 = tid & 15;
        float s = 0.f;
        #pragma unroll 4
        for (int d = 0; d < DD; ++d)
            s = fmaf(p_s[k * (DD + 1) + d], p_s[k2 * (DD + 1) + d], s);
        g_G[c * 256 + tid] = s;

    } else if (blk < 96) {
        // ----- e2 + emb->half: warp-per-row, 4 rows per warp
        const int warp = tid >> 5, lane = tid & 31;
        const int base = (blk - 64) * 32 + warp * 4;
        #pragma unroll
        for (int t = 0; t < 4; ++t) {
            const int b = base + t;
            const float4* p = (const float4*)(emb + (size_t)b * DD);
            float4 v0 = p[lane], v1 = p[lane + 32];
            uint2* eh = (uint2*)(g_emb_h + (size_t)b * DD);
            uint2 w0, w1;
            w0.x = h2u(__floats2half2_rn(v0.x, v0.y));
            w0.y = h2u(__floats2half2_rn(v0.z, v0.w));
            w1.x = h2u(__floats2half2_rn(v1.x, v1.y));
            w1.y = h2u(__floats2half2_rn(v1.z, v1.w));
            eh[lane]      = w0;
            eh[lane + 32] = w1;
            float s = v0.x*v0.x + v0.y*v0.y + v0.z*v0.z + v0.w*v0.w
                    + v1.x*v1.x + v1.y*v1.y + v1.z*v1.z + v1.w*v1.w;
            #pragma unroll
            for (int off = 16; off > 0; off >>= 1)
                s += __shfl_xor_sync(0xFFFFFFFFu, s, off);
            if (lane == 0) g_e2[b] = s;
        }

    } else if (blk == 96) {
        // ----- decode prototype_valid (dtype-sniffing)
        __shared__ int s_hasF, s_hasHi, s_mode;
        if (tid == 0) { s_hasF = 0; s_hasHi = 0; }
        __syncthreads();
        if (tid < 128) {
            unsigned v = ((const unsigned*)valid)[tid];
            if (v == 0x3F800000u)                        atomicOr(&s_hasF, 1);
            else if (v != 0u && (v & 0xFFFFFF00u) != 0u) atomicOr(&s_hasHi, 1);
        }
        __syncthreads();
        if (tid == 0) s_mode = s_hasF ? 0 : (s_hasHi ? 2 : 1);
        __syncthreads();
        const int mode = s_mode;
        for (int i = tid; i < CC * KK; i += 256) {
            bool v;
            if (mode == 0)      v = ((const float*)valid)[i] != 0.0f;
            else if (mode == 1) v = ((const int*)valid)[i] != 0;
            else                v = ((const unsigned char*)valid)[i] != 0;
            g_inval[i] = v ? 0.0f : -CUDART_INF_F;
        }

    } else if (blk < 161) {
        // ----- dotep[b][ck] = emb[b,:]·proto[ck,:]  (tf32 mma)
        const int b    = blk - 97;               // 0..63
        const int bm0  = (b >> 2) * 64;
        const int bn0  = (b & 3) * 128;

        #define DAS(s, m, k) sh[(s) * 1280 + (m) * 20 + (k)]
        #define DPS(s, n, k) sh[2560 + (s) * 2560 + (n) * 20 + (k)]

        const int warp = tid >> 5, lane = tid & 31;
        const int wm = (warp >> 2) * 32;
        const int wn = (warp & 3) * 32;
        const int g  = lane >> 2, tg = lane & 3;

        float acc[2][4][4];
        #pragma unroll
        for (int i = 0; i < 2; ++i)
            #pragma unroll
            for (int j = 0; j < 4; ++j)
                #pragma unroll
                for (int t = 0; t < 4; ++t) acc[i][j][t] = 0.f;

        #define DE_LOAD(s, kbase)                                                         \
            {                                                                              \
                { int m = tid >> 2, k4 = (tid & 3) << 2;                                   \
                  cp16(&DAS(s, m, k4), emb + (size_t)(bm0 + m) * DD + (kbase) + k4); }     \
                _Pragma("unroll")                                                          \
                for (int i_ = 0; i_ < 2; ++i_) {                                           \
                    int slot = tid + i_ * 256;                                             \
                    int n = slot >> 2, k4 = (slot & 3) << 2;                               \
                    cp16(&DPS(s, n, k4), protos + (size_t)(bn0 + n) * DD + (kbase) + k4);  \
                }                                                                          \
                CP_COMMIT();                                                               \
            }

        DE_LOAD(0, 0);
        int s = 0;
        const int NT = DD / 16;
        for (int kt = 0; kt < NT; ++kt) {
            if (kt + 1 < NT) { DE_LOAD(s ^ 1, (kt + 1) * 16); CP_WAIT(1); }
            else             { CP_WAIT(0); }
            __syncthreads();

            #pragma unroll
            for (int ks = 0; ks < 2; ++ks) {
                const int kb = ks * 8;
                uint32_t afr[2][4], bfr[4][2];
                #pragma unroll
                for (int i = 0; i < 2; ++i) {
                    int m0 = wm + i * 16;
                    afr[i][0] = f2tf(DAS(s, m0 + g,     kb + tg));
                    afr[i][1] = f2tf(DAS(s, m0 + g + 8, kb + tg));
                    afr[i][2] = f2tf(DAS(s, m0 + g,     kb + tg + 4));
                    afr[i][3] = f2tf(DAS(s, m0 + g + 8, kb + tg + 4));
                }
                #pragma unroll
                for (int j = 0; j < 4; ++j) {
                    int n0 = wn + j * 8;
                    bfr[j][0] = f2tf(DPS(s, n0 + g, kb + tg));
                    bfr[j][1] = f2tf(DPS(s, n0 + g, kb + tg + 4));
                }
                #pragma unroll
                for (int i = 0; i < 2; ++i)
                    #pragma unroll
                    for (int j = 0; j < 4; ++j)
                        mma_tf32(acc[i][j], afr[i], bfr[j]);
            }
            __syncthreads();
            s ^= 1;
        }

        #pragma unroll
        for (int i = 0; i < 2; ++i) {
            int r0 = bm0 + wm + i * 16 + g;
            #pragma unroll
            for (int j = 0; j < 4; ++j) {
                int col = bn0 + wn + j * 8 + 2 * tg;
                *(float2*)(g_dotep + (size_t)r0 * (CC * KK) + col)       = make_float2(acc[i][j][0], acc[i][j][1]);
                *(float2*)(g_dotep + (size_t)(r0 + 8) * (CC * KK) + col) = make_float2(acc[i][j][2], acc[i][j][3]);
            }
        }
        #undef DE_LOAD
        #undef DAS
        #undef DPS

    } else {
        // ----- W1top -> g_W1h[c][n][k] (transpose + half convert), 8 blocks/class
        const int idx = blk - 161;           // 0..255
        const int c  = idx >> 3;
        const int tj = (idx >> 1) & 3;       // 64-wide n slice
        const int th = idx & 1;              // handles ti = 2*th, 2*th+1
        float* ts = sh;                      // [64][65]
        const float* Wt = W1 + (size_t)c * TWO_D * DD;   // top half [256 k][256 n]
        __half* outc = g_W1h + (size_t)c * DD * DD;

        for (int tq = 0; tq < 2; ++tq) {
            const int ti = 2 * th + tq;
            {
                int r = tid >> 2, cg = (tid & 3) * 16;
                const float* src = Wt + (size_t)(ti * 64 + r) * DD + tj * 64 + cg;
                #pragma unroll
                for (int u = 0; u < 4; ++u) {
                    float4 v = *(const float4*)(src + u * 4);
                    ts[r * 65 + cg + u * 4 + 0] = v.x;
                    ts[r * 65 + cg + u * 4 + 1] = v.y;
                    ts[r * 65 + cg + u * 4 + 2] = v.z;
                    ts[r * 65 + cg + u * 4 + 3] = v.w;
                }
            }
            __syncthreads();
            {
                int nn = tid >> 2, kg = (tid & 3) * 16;
                uint32_t* dst = (uint32_t*)(outc + (size_t)(tj * 64 + nn) * DD + ti * 64 + kg);
                #pragma unroll
                for (int u = 0; u < 8; ++u) {
                    __half2 h = __floats2half2_rn(ts[(kg + 2 * u) * 65 + nn],
                                                  ts[(kg + 2 * u + 1) * 65 + nn]);
                    dst[u] = h2u(h);
                }
            }
            __syncthreads();
        }
    }
}

// ===========================================================================
// Kernel B (main, fused): per (32-batch-tile, class):
//   1. qW tile [32 x 256] = emb_h @ W1h  — f16 mma, f16 acc (16 regs),
//      BK=32, 3-stage cp.async, 1 sync/iter, XOR-swizzled 16-word row pitch
//   2. epilogue: tanh f16x2 + 2nd-stage f16 mma scores (fp32 acc)
//   3. softmax over K, dist via Gram trick, write out
// grid (32, 32) = 1024 blocks, 256 threads (8 warps, warp tile 32x32),
// 4 CTAs/SM. smem/CTA: 13824 words = 55296 B.
// ===========================================================================
__global__ __launch_bounds__(256, 4) void fused_main(
    const float* __restrict__ w2, const float* __restrict__ b2,
    const float* __restrict__ temperature, float* __restrict__ out)
{
    extern __shared__ float sh[];
    uint32_t* shw = (uint32_t*)sh;
    // phase-1: AsW [3][32][16] words 0..1535 ; BsW [3][256][16] words 1536..13823
    // phase-2 layout (aliases phase-1 region)
    uint32_t* sh_pt_h2 = (uint32_t*)sh;        // [16][128] half2 = 2048 words
    float* sh_scorew = sh + 2048;              // [8 warps][32 rows][18] = 4608
    float* sh_w2    = sh + 2048 + 4608;        // 256
    float* sh_G     = sh_w2 + 256;             // [16][17] = 272
    float* sh_inval = sh_G + 272;              // 16      (total 7200 words)

    const int c  = blockIdx.y;
    const int b0 = blockIdx.x * 32;
    const __half* Wh = g_W1h + (size_t)c * DD * DD;   // [n][k] half

    const int tid  = threadIdx.x;
    const int warp = tid >> 5, lane = tid & 31;
    const int wn = warp * 32;            // warp n-slice (all 32 rows)
    const int g  = lane >> 2, tg = lane & 3;

    uint32_t acc[2][4][2];               // f16x2 accumulators [m16][n8][row g/g+8]
    #pragma unroll
    for (int i = 0; i < 2; ++i)
        #pragma unroll
        for (int j = 0; j < 4; ++j) { acc[i][j][0] = 0u; acc[i][j][1] = 0u; }

    // swizzled word index within a stage: row r, chunk ch (0..3), word j (0..3)
    #define SWIZ(r, ch, j) ((r) * 16 + ((((ch) ^ (((r) >> 1) & 3))) << 2) + (j))
    #define ASW(s, r, ch, j) shw[(s) * 512 + SWIZ(r, ch, j)]
    #define BSW(s, r, ch, j) shw[1536 + (s) * 4096 + SWIZ(r, ch, j)]
    #define FM_LOAD(s, kbase)                                                  \
        {                                                                       \
            if (tid < 128) {                                                    \
                int r = tid >> 2, ch = tid & 3;                                 \
                cp16(&ASW(s, r, ch, 0),                                         \
                     g_emb_h + (size_t)(b0 + r) * DD + (kbase) + ch * 8);       \
            }                                                                   \
            _Pragma("unroll")                                                   \
            for (int i_ = 0; i_ < 4; ++i_) {                                    \
                int slot = tid + i_ * 256;                                      \
                int r = slot >> 2, ch = slot & 3;                               \
                cp16(&BSW(s, r, ch, 0),                                         \
                     Wh + (size_t)r * DD + (kbase) + ch * 8);                   \
            }                                                                   \
            CP_COMMIT();                                                        \
        }

    // ---------------- Phase 1: f16 GEMM (f16 acc), 3-stage, 1 sync/iter ------
    FM_LOAD(0, 0);
    FM_LOAD(1, 32);
    const int NT = DD / 32;   // 8
    #pragma unroll 1
    for (int kt = 0; kt < NT; ++kt) {
        const int cs = kt % 3;
        if (kt < NT - 1) { CP_WAIT(1); } else { CP_WAIT(0); }
        __syncthreads();
        if (kt + 2 < NT) FM_LOAD((kt + 2) % 3, (kt + 2) * 32);

        #pragma unroll
        for (int ks = 0; ks < 2; ++ks) {
            const int c0 = ks * 2;   // chunk pair for this k8-step
            uint32_t afr[2][4], bfr[4][2];
            #pragma unroll
            for (int i = 0; i < 2; ++i) {
                int m0 = i * 16;
                afr[i][0] = ASW(cs, m0 + g,     c0,     tg);
                afr[i][1] = ASW(cs, m0 + g + 8, c0,     tg);
                afr[i][2] = ASW(cs, m0 + g,     c0 + 1, tg);
                afr[i][3] = ASW(cs, m0 + g + 8, c0 + 1, tg);
            }
            #pragma unroll
            for (int j = 0; j < 4; ++j) {
                int n0 = wn + j * 8;
                bfr[j][0] = BSW(cs, n0 + g, c0,     tg);
                bfr[j][1] = BSW(cs, n0 + g, c0 + 1, tg);
            }
            #pragma unroll
            for (int i = 0; i < 2; ++i)
                #pragma unroll
                for (int j = 0; j < 4; ++j)
                    mma_f16_hacc(acc[i][j], afr[i][0], afr[i][1], afr[i][2], afr[i][3],
                                 bfr[j][0], bfr[j][1]);
        }
    }
    __syncthreads();   // all warps done with GEMM smem before repurposing

    // ---------------- Phase 2 tables ----------------
    {
        const float2* ptg2 = (const float2*)(g_proto_term + (size_t)c * KK * DD);
        #pragma unroll
        for (int i = 0; i < 8; ++i) {
            int idx = tid + i * 256;            // 0..2047
            float2 v = ptg2[idx];
            __half2 h = __floats2half2_rn(v.x, v.y);
            sh_pt_h2[idx] = h2u(h);
        }
        if (tid < DD) sh_w2[tid] = w2[c * DD + tid];
        if (tid < KK * KK) sh_G[(tid >> 4) * 17 + (tid & 15)] = g_G[c * 256 + tid];
        if (tid < KK) sh_inval[tid] = g_inval[c * KK + tid];
    }
    __syncthreads();

    // per-thread w2 pairs (B-fragments of 2nd-stage mma)
    uint32_t w2u[4];
    #pragma unroll
    for (int j = 0; j < 4; ++j) {
        float2 w = *(float2*)&sh_w2[wn + j * 8 + 2 * tg];
        w2u[j] = h2u(__floats2half2_rn(w.x, w.y));
    }

    float* my_slab = sh_scorew + warp * 576;   // [32][18]
    const int ptbase = (wn >> 1) + tg;

    // ---------------- Phase 3: tanh + 2nd-stage mma (pt prefetch) ----------
    uint32_t pw_cur[4];
    #pragma unroll
    for (int j = 0; j < 4; ++j) pw_cur[j] = sh_pt_h2[ptbase + j * 4];

    #pragma unroll 1
    for (int k = 0; k < KK; ++k) {
        uint32_t pw_nxt[4];
        if (k + 1 < KK) {
            #pragma unroll
            for (int j = 0; j < 4; ++j)
                pw_nxt[j] = sh_pt_h2[(k + 1) * 128 + ptbase + j * 4];
        }
        __half2 pth[4];
        #pragma unroll
        for (int j = 0; j < 4; ++j) pth[j] = *reinterpret_cast<__half2*>(&pw_cur[j]);

        #pragma unroll
        for (int i = 0; i < 2; ++i) {
            #define ACCH(jj, uu) (*reinterpret_cast<__half2*>(&acc[i][jj][uu]))
            uint32_t t00 = h2u(tanh_h2(__hadd2(ACCH(0, 0), pth[0])));
            uint32_t t01 = h2u(tanh_h2(__hadd2(ACCH(0, 1), pth[0])));
            uint32_t t10 = h2u(tanh_h2(__hadd2(ACCH(1, 0), pth[1])));
            uint32_t t11 = h2u(tanh_h2(__hadd2(ACCH(1, 1), pth[1])));
            uint32_t t20 = h2u(tanh_h2(__hadd2(ACCH(2, 0), pth[2])));
            uint32_t t21 = h2u(tanh_h2(__hadd2(ACCH(2, 1), pth[2])));
            uint32_t t30 = h2u(tanh_h2(__hadd2(ACCH(3, 0), pth[3])));
            uint32_t t31 = h2u(tanh_h2(__hadd2(ACCH(3, 1), pth[3])));
            #undef ACCH

            float cfr[4] = {0.f, 0.f, 0.f, 0.f};
            mma_f16(cfr, t00, t01, t10, t11, w2u[0], w2u[1]);
            mma_f16(cfr, t20, t21, t30, t31, w2u[2], w2u[3]);

            if (tg == 0) {
                my_slab[(i * 16 + g) * 18 + k]     = cfr[0];
                my_slab[(i * 16 + g + 8) * 18 + k] = cfr[2];
            }
        }
        #pragma unroll
        for (int j = 0; j < 4; ++j) pw_cur[j] = pw_nxt[j];
    }
    __syncthreads();

    // ---------------- Phase 4: gather slabs + softmax + Gram distance -------
    if (tid < 32) {
        const int b = b0 + tid;
        const float b2v  = b2[c];
        const float temp = temperature[0];

        float s16[KK];
        #pragma unroll
        for (int k = 0; k < KK; ++k) s16[k] = b2v + sh_inval[k];
        #pragma unroll
        for (int w = 0; w < 8; ++w) {
            const float* p = sh_scorew + w * 576 + tid * 18;
            #pragma unroll
            for (int q = 0; q < 8; ++q) {
                float2 v = *(const float2*)(p + 2 * q);
                s16[2 * q]     += v.x;
                s16[2 * q + 1] += v.y;
            }
        }

        float m = s16[0];
        #pragma unroll
        for (int k = 1; k < KK; ++k) m = fmaxf(m, s16[k]);
        float sum = 0.f;
        #pragma unroll
        for (int k = 0; k < KK; ++k) {
            float e = __expf(s16[k] - m);
            s16[k] = e;
            sum += e;
        }
        float inv = 1.f / sum;
        #pragma unroll
        for (int k = 0; k < KK; ++k) s16[k] *= inv;

        // dist^2 = e2 - 2*attn·dotep + attn^T G attn
        float depv[KK];
        const float4* dep = (const float4*)(g_dotep + (size_t)b * (CC * KK) + c * KK);
        #pragma unroll
        for (int q = 0; q < 4; ++q) {
            float4 v = dep[q];
            depv[4 * q + 0] = v.x; depv[4 * q + 1] = v.y;
            depv[4 * q + 2] = v.z; depv[4 * q + 3] = v.w;
        }
        float dist2 = g_e2[b];
        #pragma unroll
        for (int k = 0; k < KK; ++k)
            dist2 = fmaf(-2.0f * s16[k], depv[k], dist2);
        #pragma unroll
        for (int k = 0; k < KK; ++k) {
            float t = 0.f;
            #pragma unroll
            for (int k2 = 0; k2 < KK; ++k2)
                t = fmaf(sh_G[k * 17 + k2], s16[k2], t);
            dist2 = fmaf(s16[k], t, dist2);
        }
        out[(size_t)b * CC + c] = -sqrtf(fmaxf(dist2, 0.f)) * temp;
    }
    #undef SWIZ
    #undef ASW
    #undef BSW
    #undef FM_LOAD
}

// ---------------------------------------------------------------------------
extern "C" void kernel_launch(void* const* d_in, const int* in_sizes, int n_in,
                              void* d_out, int out_size)
{
    const float* emb    = (const float*)d_in[0];   // [B,D]
    const float* protos = (const float*)d_in[1];   // [C,K,D]
    const float* W1     = (const float*)d_in[2];   // [C,2D,D]
    const float* b1     = (const float*)d_in[3];   // [C,D]
    const float* w2     = (const float*)d_in[4];   // [C,D]
    const float* b2     = (const float*)d_in[5];   // [C]
    const float* temp   = (const float*)d_in[6];   // [1]
    const void*  valid  = (const void*)d_in[7];    // [C,K] bool (storage dtype unknown)
    float* out = (float*)d_out;                    // [B,C]

    // dyn smem = 13824 words = 55296 B (epilogue 7200 words fits inside)
    const int dyn = 13824 * 4;
    cudaFuncSetAttribute(fused_main, cudaFuncAttributeMaxDynamicSharedMemorySize, dyn);

    prologue_kernel<<<417, 256>>>(emb, protos, W1, b1, valid);
    fused_main<<<dim3(32, CC), 256, dyn>>>(w2, b2, temp, out);
}